// round 3
// baseline (speedup 1.0000x reference)
#include <cuda_runtime.h>
#include <cstdint>

#define BATCH 32
#define KPTS 2048
#define CFEAT 256
#define NPROP 256
#define NSAMP 16
#define NTOT (BATCH * NPROP * NSAMP)   // 131072
#define NP2  (BATCH * NPROP)           // 8192
#define OUTD 119

// ---------------- scratch (static device memory; no allocation) ------------
__device__ float g_X0[259 * NTOT];     // SA input (3 xyz rows + 256 feat rows); reused as layer-3 output
__device__ float g_X1[256 * NTOT];
__device__ float g_X2[256 * NTOT];
__device__ float g_Y [256 * NP2];
__device__ float g_Y1[256 * NP2];
__device__ float g_Y2[256 * NP2];
__device__ float g_net[OUTD * NP2];
__device__ float g_newxyz[NP2 * 3];
__device__ int   g_ball[NP2 * NSAMP];

// ---------------- output offsets (floats) ----------------------------------
#define OFF_OBJ   0
#define OFF_CEN   16384
#define OFF_SS    40960
#define OFF_SRES  188416
#define OFF_PSZ   630784
#define OFF_SEM   655360
#define OFF_CORN  802816
#define OFF_SLOG  999424
#define OFF_OPROB 1155072
#define OFF_SPROB 1163264

// ============================================================================
// FPS: one block per batch, 256 threads, 8 points each, distances in registers
// ============================================================================
__global__ void fps_kernel(const float* __restrict__ xyz, float* __restrict__ newxyz) {
    int b = blockIdx.x;
    int t = threadIdx.x;
    __shared__ float sx[KPTS], sy[KPTS], sz[KPTS];
    __shared__ float wv[8];
    __shared__ int   wi[8];
    __shared__ int   far_s;

    const float* p = xyz + (size_t)b * KPTS * 3;
    float px[8], py[8], pz[8], dist[8];
#pragma unroll
    for (int i = 0; i < 8; i++) {
        int j = i * 256 + t;
        px[i] = p[j * 3 + 0];
        py[i] = p[j * 3 + 1];
        pz[i] = p[j * 3 + 2];
        sx[j] = px[i]; sy[j] = py[i]; sz[j] = pz[i];
        dist[i] = 1e10f;
    }
    if (t == 0) far_s = 0;
    __syncthreads();

    for (int it = 0; it < NPROP; it++) {
        int far = far_s;
        if (t == 0) {
            float* o = newxyz + (size_t)(b * NPROP + it) * 3;
            o[0] = sx[far]; o[1] = sy[far]; o[2] = sz[far];
        }
        float cx = sx[far], cy = sy[far], cz = sz[far];
        float bv = -1.0f;
        int   bj = 0x7fffffff;
#pragma unroll
        for (int i = 0; i < 8; i++) {
            float dx = px[i] - cx, dy = py[i] - cy, dz = pz[i] - cz;
            float d = dx * dx + dy * dy + dz * dz;
            dist[i] = fminf(dist[i], d);
            int j = i * 256 + t;
            if (dist[i] > bv || (dist[i] == bv && j < bj)) { bv = dist[i]; bj = j; }
        }
        // warp reduce (lexicographic: larger v, tie -> smaller index)
#pragma unroll
        for (int off = 16; off; off >>= 1) {
            float ov = __shfl_down_sync(0xffffffffu, bv, off);
            int   oj = __shfl_down_sync(0xffffffffu, bj, off);
            if (ov > bv || (ov == bv && oj < bj)) { bv = ov; bj = oj; }
        }
        if ((t & 31) == 0) { wv[t >> 5] = bv; wi[t >> 5] = bj; }
        __syncthreads();
        if (t == 0) {
            float fv = wv[0]; int fj = wi[0];
#pragma unroll
            for (int w = 1; w < 8; w++) {
                if (wv[w] > fv || (wv[w] == fv && wi[w] < fj)) { fv = wv[w]; fj = wi[w]; }
            }
            far_s = fj;
        }
        __syncthreads();
    }
}

// ============================================================================
// Ball query: one warp per proposal; first 16 in-range indices ascending,
// pad with the first one found.
// ============================================================================
__global__ void ball_query_kernel(const float* __restrict__ xyz,
                                  const float* __restrict__ newxyz,
                                  int* __restrict__ ball) {
    int gwarp = (blockIdx.x * blockDim.x + threadIdx.x) >> 5;
    if (gwarp >= NP2) return;
    int lane = threadIdx.x & 31;
    int wl = threadIdx.x >> 5;
    int b = gwarp >> 8;

    __shared__ int slots[8][16];
    if (lane == 0) slots[wl][0] = 0;

    float cx = newxyz[gwarp * 3 + 0];
    float cy = newxyz[gwarp * 3 + 1];
    float cz = newxyz[gwarp * 3 + 2];
    const float* p = xyz + (size_t)b * KPTS * 3;

    int cnt = 0;
    for (int r = 0; r < KPTS / 32 && cnt < NSAMP; r++) {
        int j = r * 32 + lane;
        float dx = cx - p[j * 3 + 0];
        float dy = cy - p[j * 3 + 1];
        float dz = cz - p[j * 3 + 2];
        float d2 = dx * dx + dy * dy + dz * dz;
        bool pred = d2 < 0.09f;
        unsigned m = __ballot_sync(0xffffffffu, pred);
        int pos = cnt + __popc(m & ((1u << lane) - 1u));
        if (pred && pos < NSAMP) slots[wl][pos] = j;
        cnt += __popc(m);
    }
    __syncwarp();
    if (lane < NSAMP) {
        int first = slots[wl][0];
        int v = (lane < cnt) ? slots[wl][lane] : first;
        ball[gwarp * NSAMP + lane] = v;
    }
}

// ============================================================================
// Gather: build X0 rows (3 normalized-xyz rows + 256 feature rows)
// ============================================================================
__global__ void gather_xyz_kernel(const float* __restrict__ xyz,
                                  const float* __restrict__ newxyz,
                                  const int* __restrict__ ball,
                                  float* __restrict__ X0) {
    int n = blockIdx.x * blockDim.x + threadIdx.x;
    if (n >= NTOT) return;
    int bp = n >> 4;
    int b = bp >> 8;
    int j = ball[n];
    const float* pj = xyz + ((size_t)b * KPTS + j) * 3;
    const float* cen = newxyz + (size_t)bp * 3;
    X0[0 * (size_t)NTOT + n] = (pj[0] - cen[0]) / 0.3f;
    X0[1 * (size_t)NTOT + n] = (pj[1] - cen[1]) / 0.3f;
    X0[2 * (size_t)NTOT + n] = (pj[2] - cen[2]) / 0.3f;
}

__global__ void gather_feat_kernel(const float* __restrict__ feat,
                                   const int* __restrict__ ball,
                                   float* __restrict__ X0) {
    int bc = blockIdx.x;          // b * 256 + c
    int b = bc >> 8;
    int c = bc & 255;
    const float* f = feat + ((size_t)b * CFEAT + c) * KPTS;
    const int* bl = ball + (size_t)b * NPROP * NSAMP;
    float* dst = X0 + (size_t)(3 + c) * NTOT + (size_t)b * NPROP * NSAMP;
    for (int t = threadIdx.x; t < NPROP * NSAMP; t += blockDim.x)
        dst[t] = f[bl[t]];
}

// ============================================================================
// SGEMM 128x128x16, 256 threads, 8x8 per thread.  MODE 0: BN+ReLU, 1: +bias
// C[M][N] = W[M][Kc] * X[Kc][N]
// ============================================================================
#define BM 128
#define BN 128
#define BK 16

template <int MODE>
__global__ void __launch_bounds__(256, 2)
gemm_kernel(const float* __restrict__ W, const float* __restrict__ X,
            float* __restrict__ Cout, int M, int Kc, int N,
            const float* __restrict__ gamma, const float* __restrict__ beta,
            const float* __restrict__ mean, const float* __restrict__ var,
            const float* __restrict__ bias) {
    __shared__ float As[BK][BM + 4];
    __shared__ float Bs[BK][BN];
    int tid = threadIdx.x;
    int m0 = blockIdx.y * BM;
    int n0 = blockIdx.x * BN;
    int tx = tid & 15;
    int ty = tid >> 4;

    float acc[8][8];
#pragma unroll
    for (int i = 0; i < 8; i++)
#pragma unroll
        for (int j = 0; j < 8; j++) acc[i][j] = 0.f;

    for (int k0 = 0; k0 < Kc; k0 += BK) {
        // A tile: W[m0+m][k0+kk..], transpose into As[k][m]
        {
            int m = tid >> 1;
            int kk = (tid & 1) * 8;
#pragma unroll
            for (int j = 0; j < 8; j++) {
                int kg = k0 + kk + j;
                float v = 0.f;
                if (m0 + m < M && kg < Kc) v = W[(size_t)(m0 + m) * Kc + kg];
                As[kk + j][m] = v;
            }
        }
        // B tile: X[k0+k][n0 .. n0+127]
        {
            int kk = tid >> 4;
            int nn = (tid & 15) * 8;
            int kg = k0 + kk;
            float4 v0 = {0, 0, 0, 0}, v1 = {0, 0, 0, 0};
            if (kg < Kc) {
                const float* src = X + (size_t)kg * N + n0 + nn;
                v0 = *(const float4*)(src);
                v1 = *(const float4*)(src + 4);
            }
            *(float4*)&Bs[kk][nn] = v0;
            *(float4*)&Bs[kk][nn + 4] = v1;
        }
        __syncthreads();
#pragma unroll
        for (int kk = 0; kk < BK; kk++) {
            float a[8], bb[8];
#pragma unroll
            for (int i = 0; i < 8; i++) a[i] = As[kk][ty * 8 + i];
#pragma unroll
            for (int j = 0; j < 8; j++) bb[j] = Bs[kk][tx * 8 + j];
#pragma unroll
            for (int i = 0; i < 8; i++)
#pragma unroll
                for (int j = 0; j < 8; j++) acc[i][j] += a[i] * bb[j];
        }
        __syncthreads();
    }

#pragma unroll
    for (int i = 0; i < 8; i++) {
        int m = m0 + ty * 8 + i;
        if (m >= M) continue;
        float sc = 1.f, sh = 0.f;
        if (MODE == 0) {
            float s = gamma[m] * rsqrtf(var[m] + 1e-5f);
            sc = s;
            sh = beta[m] - mean[m] * s;
        } else {
            sh = bias[m];
        }
        float* dst = Cout + (size_t)m * N + n0 + tx * 8;
#pragma unroll
        for (int j = 0; j < 8; j++) {
            float v;
            if (MODE == 0) v = fmaxf(acc[i][j] * sc + sh, 0.f);
            else           v = acc[i][j] + sh;
            dst[j] = v;
        }
    }
}

// ============================================================================
// Max over the 16 samples per proposal
// ============================================================================
__global__ void maxpool_kernel(const float* __restrict__ X, float* __restrict__ Y) {
    int i = blockIdx.x * blockDim.x + threadIdx.x;  // ch * NP2 + bp
    if (i >= 256 * NP2) return;
    const float* src = X + (size_t)(i >> 13) * NTOT + (size_t)(i & (NP2 - 1)) * NSAMP;
    float m = src[0];
#pragma unroll
    for (int s = 1; s < NSAMP; s++) m = fmaxf(m, src[s]);
    Y[i] = m;
}

// ============================================================================
// Finalize: heads, argmax size class, corners, softmaxes -> d_out
// ============================================================================
__global__ void finalize_kernel(const float* __restrict__ net,
                                const float* __restrict__ newxyz,
                                const float* __restrict__ msz,
                                float* __restrict__ out) {
    int n = blockIdx.x * blockDim.x + threadIdx.x;  // proposal id 0..8191
    if (n >= NP2) return;
#define NET(o) net[(size_t)(o) * NP2 + n]

    float obj0 = NET(0), obj1 = NET(1);
    out[OFF_OBJ + n * 2 + 0] = obj0;
    out[OFF_OBJ + n * 2 + 1] = obj1;

    float cx = newxyz[n * 3 + 0] + NET(2);
    float cy = newxyz[n * 3 + 1] + NET(3);
    float cz = newxyz[n * 3 + 2] + NET(4);
    out[OFF_CEN + n * 3 + 0] = cx;
    out[OFF_CEN + n * 3 + 1] = cy;
    out[OFF_CEN + n * 3 + 2] = cz;

    // size scores + argmax (first occurrence)
    int best = 0;
    float bv = NET(29);
    out[OFF_SS + n * 18 + 0] = bv;
#pragma unroll
    for (int sc = 1; sc < 18; sc++) {
        float v = NET(29 + sc);
        out[OFF_SS + n * 18 + sc] = v;
        if (v > bv) { bv = v; best = sc; }
    }

    // size residuals
#pragma unroll
    for (int sc = 0; sc < 18; sc++) {
#pragma unroll
        for (int d = 0; d < 3; d++) {
            float sres = NET(47 + sc * 3 + d) * msz[sc * 3 + d];
            out[OFF_SRES + ((size_t)n * 18 + sc) * 3 + d] = sres;
        }
    }

    float ps[3];
#pragma unroll
    for (int d = 0; d < 3; d++) {
        float m = msz[best * 3 + d];
        ps[d] = net[(size_t)(47 + best * 3 + d) * NP2 + n] * m + m;
        out[OFF_PSZ + n * 3 + d] = ps[d];
    }

    // sem
    float sem[18];
#pragma unroll
    for (int s = 0; s < 18; s++) {
        sem[s] = NET(101 + s);
        out[OFF_SEM + n * 18 + s] = sem[s];
    }

    // corners (angle = 0 -> identity rotation)
    const float sxA[8] = {1, 1, -1, -1, 1, 1, -1, -1};
    const float syA[8] = {1, 1, 1, 1, -1, -1, -1, -1};
    const float szA[8] = {1, -1, -1, 1, 1, -1, -1, 1};
    float c0 = cx, c1 = cz, c2 = -cy;
#pragma unroll
    for (int k = 0; k < 8; k++) {
        out[OFF_CORN + ((size_t)n * 8 + k) * 3 + 0] = ps[0] * sxA[k] * 0.5f + c0;
        out[OFF_CORN + ((size_t)n * 8 + k) * 3 + 1] = ps[2] * syA[k] * 0.5f + c1;
        out[OFF_CORN + ((size_t)n * 8 + k) * 3 + 2] = ps[1] * szA[k] * 0.5f + c2;
    }

    // sem_logits: sem then argmin(obj)*1e10 (first-min tie break)
#pragma unroll
    for (int s = 0; s < 18; s++) out[OFF_SLOG + n * 19 + s] = sem[s];
    out[OFF_SLOG + n * 19 + 18] = (obj0 <= obj1) ? 0.0f : 1e10f;

    // obj_prob = softmax(obj)[1]
    {
        float m = fmaxf(obj0, obj1);
        float e0 = expf(obj0 - m), e1 = expf(obj1 - m);
        out[OFF_OPROB + n] = e1 / (e0 + e1);
    }

    // sem_prob = softmax(sem)
    {
        float m = sem[0];
#pragma unroll
        for (int s = 1; s < 18; s++) m = fmaxf(m, sem[s]);
        float sum = 0.f;
        float e[18];
#pragma unroll
        for (int s = 0; s < 18; s++) { e[s] = expf(sem[s] - m); sum += e[s]; }
        float inv = 1.0f / sum;
#pragma unroll
        for (int s = 0; s < 18; s++) out[OFF_SPROB + n * 18 + s] = e[s] * inv;
    }
#undef NET
}

// ============================================================================
// launch
// ============================================================================
extern "C" void kernel_launch(void* const* d_in, const int* in_sizes, int n_in,
                              void* d_out, int out_size) {
    const float* xyz      = (const float*)d_in[0];
    const float* features = (const float*)d_in[1];
    const float* sa_w1    = (const float*)d_in[2];
    const float* sa_w2    = (const float*)d_in[3];
    const float* sa_w3    = (const float*)d_in[4];
    const float* sa_gamma = (const float*)d_in[5];
    const float* sa_beta  = (const float*)d_in[6];
    const float* sa_mean  = (const float*)d_in[7];
    const float* sa_var   = (const float*)d_in[8];
    const float* p_w1     = (const float*)d_in[9];
    const float* p_w2     = (const float*)d_in[10];
    const float* p_w3     = (const float*)d_in[11];
    const float* p_b3     = (const float*)d_in[12];
    const float* p_gamma  = (const float*)d_in[13];
    const float* p_beta   = (const float*)d_in[14];
    const float* p_mean   = (const float*)d_in[15];
    const float* p_var    = (const float*)d_in[16];
    const float* msz      = (const float*)d_in[17];
    float* out = (float*)d_out;

    float* X0; float* X1; float* X2; float* Y; float* Y1; float* Y2; float* net;
    float* newxyz; int* ball;
    cudaGetSymbolAddress((void**)&X0, g_X0);
    cudaGetSymbolAddress((void**)&X1, g_X1);
    cudaGetSymbolAddress((void**)&X2, g_X2);
    cudaGetSymbolAddress((void**)&Y,  g_Y);
    cudaGetSymbolAddress((void**)&Y1, g_Y1);
    cudaGetSymbolAddress((void**)&Y2, g_Y2);
    cudaGetSymbolAddress((void**)&net, g_net);
    cudaGetSymbolAddress((void**)&newxyz, g_newxyz);
    cudaGetSymbolAddress((void**)&ball, g_ball);

    fps_kernel<<<BATCH, 256>>>(xyz, newxyz);
    ball_query_kernel<<<NP2 * 32 / 256, 256>>>(xyz, newxyz, ball);
    gather_xyz_kernel<<<NTOT / 256, 256>>>(xyz, newxyz, ball, X0);
    gather_feat_kernel<<<BATCH * CFEAT, 256>>>(features, ball, X0);

    dim3 gSA(NTOT / BN, 2);
    gemm_kernel<0><<<gSA, 256>>>(sa_w1, X0, X1, 256, 259, NTOT,
                                 sa_gamma + 0,   sa_beta + 0,   sa_mean + 0,   sa_var + 0,   nullptr);
    gemm_kernel<0><<<gSA, 256>>>(sa_w2, X1, X2, 256, 256, NTOT,
                                 sa_gamma + 256, sa_beta + 256, sa_mean + 256, sa_var + 256, nullptr);
    gemm_kernel<0><<<gSA, 256>>>(sa_w3, X2, X0, 256, 256, NTOT,
                                 sa_gamma + 512, sa_beta + 512, sa_mean + 512, sa_var + 512, nullptr);

    maxpool_kernel<<<(256 * NP2) / 256, 256>>>(X0, Y);

    dim3 gP(NP2 / BN, 2);
    gemm_kernel<0><<<gP, 256>>>(p_w1, Y,  Y1, 256, 256, NP2,
                                p_gamma + 0,   p_beta + 0,   p_mean + 0,   p_var + 0,   nullptr);
    gemm_kernel<0><<<gP, 256>>>(p_w2, Y1, Y2, 256, 256, NP2,
                                p_gamma + 256, p_beta + 256, p_mean + 256, p_var + 256, nullptr);
    dim3 gP3(NP2 / BN, 1);
    gemm_kernel<1><<<gP3, 256>>>(p_w3, Y2, net, OUTD, 256, NP2,
                                 nullptr, nullptr, nullptr, nullptr, p_b3);

    finalize_kernel<<<NP2 / 256, 256>>>(net, newxyz, msz, out);
}

// round 4
// speedup vs baseline: 1.0010x; 1.0010x over previous
#include <cuda_runtime.h>
#include <cstdint>

#define BATCH 32
#define KPTS 2048
#define CFEAT 256
#define NPROP 256
#define NSAMP 16
#define NTOT (BATCH * NPROP * NSAMP)   // 131072
#define NP2  (BATCH * NPROP)           // 8192
#define OUTD 119

// ---------------- scratch (static device memory; no allocation) ------------
__device__ float g_X0[259 * NTOT];     // SA input (3 xyz rows + 256 feat rows); reused as layer-3 output
__device__ float g_X1[256 * NTOT];
__device__ float g_X2[256 * NTOT];
__device__ float g_Y [256 * NP2];
__device__ float g_Y1[256 * NP2];
__device__ float g_Y2[256 * NP2];
__device__ float g_net[OUTD * NP2];
__device__ float g_newxyz[NP2 * 3];
__device__ int   g_ball[NP2 * NSAMP];

// ---------------- output offsets (floats) ----------------------------------
#define OFF_OBJ   0
#define OFF_CEN   16384
#define OFF_SS    40960
#define OFF_SRES  188416
#define OFF_PSZ   630784
#define OFF_SEM   655360
#define OFF_CORN  802816
#define OFF_SLOG  999424
#define OFF_OPROB 1155072
#define OFF_SPROB 1163264

// ============================================================================
// FPS: one block per batch, 256 threads, 8 points each, distances in registers
// ============================================================================
__global__ void fps_kernel(const float* __restrict__ xyz, float* __restrict__ newxyz) {
    int b = blockIdx.x;
    int t = threadIdx.x;
    __shared__ float sx[KPTS], sy[KPTS], sz[KPTS];
    __shared__ float wv[8];
    __shared__ int   wi[8];
    __shared__ int   far_s;

    const float* p = xyz + (size_t)b * KPTS * 3;
    float px[8], py[8], pz[8], dist[8];
#pragma unroll
    for (int i = 0; i < 8; i++) {
        int j = i * 256 + t;
        px[i] = p[j * 3 + 0];
        py[i] = p[j * 3 + 1];
        pz[i] = p[j * 3 + 2];
        sx[j] = px[i]; sy[j] = py[i]; sz[j] = pz[i];
        dist[i] = 1e10f;
    }
    if (t == 0) far_s = 0;
    __syncthreads();

    for (int it = 0; it < NPROP; it++) {
        int far = far_s;
        if (t == 0) {
            float* o = newxyz + (size_t)(b * NPROP + it) * 3;
            o[0] = sx[far]; o[1] = sy[far]; o[2] = sz[far];
        }
        float cx = sx[far], cy = sy[far], cz = sz[far];
        float bv = -1.0f;
        int   bj = 0x7fffffff;
#pragma unroll
        for (int i = 0; i < 8; i++) {
            float dx = px[i] - cx, dy = py[i] - cy, dz = pz[i] - cz;
            float d = dx * dx + dy * dy + dz * dz;
            dist[i] = fminf(dist[i], d);
            int j = i * 256 + t;
            if (dist[i] > bv || (dist[i] == bv && j < bj)) { bv = dist[i]; bj = j; }
        }
        // warp reduce (lexicographic: larger v, tie -> smaller index)
#pragma unroll
        for (int off = 16; off; off >>= 1) {
            float ov = __shfl_down_sync(0xffffffffu, bv, off);
            int   oj = __shfl_down_sync(0xffffffffu, bj, off);
            if (ov > bv || (ov == bv && oj < bj)) { bv = ov; bj = oj; }
        }
        if ((t & 31) == 0) { wv[t >> 5] = bv; wi[t >> 5] = bj; }
        __syncthreads();
        if (t == 0) {
            float fv = wv[0]; int fj = wi[0];
#pragma unroll
            for (int w = 1; w < 8; w++) {
                if (wv[w] > fv || (wv[w] == fv && wi[w] < fj)) { fv = wv[w]; fj = wi[w]; }
            }
            far_s = fj;
        }
        __syncthreads();
    }
}

// ============================================================================
// Ball query: one warp per proposal; first 16 in-range indices ascending,
// pad with the first one found.
// ============================================================================
__global__ void ball_query_kernel(const float* __restrict__ xyz,
                                  const float* __restrict__ newxyz,
                                  int* __restrict__ ball) {
    int gwarp = (blockIdx.x * blockDim.x + threadIdx.x) >> 5;
    if (gwarp >= NP2) return;
    int lane = threadIdx.x & 31;
    int wl = threadIdx.x >> 5;
    int b = gwarp >> 8;

    __shared__ int slots[8][16];
    if (lane == 0) slots[wl][0] = 0;

    float cx = newxyz[gwarp * 3 + 0];
    float cy = newxyz[gwarp * 3 + 1];
    float cz = newxyz[gwarp * 3 + 2];
    const float* p = xyz + (size_t)b * KPTS * 3;

    int cnt = 0;
    for (int r = 0; r < KPTS / 32 && cnt < NSAMP; r++) {
        int j = r * 32 + lane;
        float dx = cx - p[j * 3 + 0];
        float dy = cy - p[j * 3 + 1];
        float dz = cz - p[j * 3 + 2];
        float d2 = dx * dx + dy * dy + dz * dz;
        bool pred = d2 < 0.09f;
        unsigned m = __ballot_sync(0xffffffffu, pred);
        int pos = cnt + __popc(m & ((1u << lane) - 1u));
        if (pred && pos < NSAMP) slots[wl][pos] = j;
        cnt += __popc(m);
    }
    __syncwarp();
    if (lane < NSAMP) {
        int first = slots[wl][0];
        int v = (lane < cnt) ? slots[wl][lane] : first;
        ball[gwarp * NSAMP + lane] = v;
    }
}

// ============================================================================
// Gather: build X0 rows (3 normalized-xyz rows + 256 feature rows)
// ============================================================================
__global__ void gather_xyz_kernel(const float* __restrict__ xyz,
                                  const float* __restrict__ newxyz,
                                  const int* __restrict__ ball,
                                  float* __restrict__ X0) {
    int n = blockIdx.x * blockDim.x + threadIdx.x;
    if (n >= NTOT) return;
    int bp = n >> 4;
    int b = bp >> 8;
    int j = ball[n];
    const float* pj = xyz + ((size_t)b * KPTS + j) * 3;
    const float* cen = newxyz + (size_t)bp * 3;
    X0[0 * (size_t)NTOT + n] = (pj[0] - cen[0]) / 0.3f;
    X0[1 * (size_t)NTOT + n] = (pj[1] - cen[1]) / 0.3f;
    X0[2 * (size_t)NTOT + n] = (pj[2] - cen[2]) / 0.3f;
}

__global__ void gather_feat_kernel(const float* __restrict__ feat,
                                   const int* __restrict__ ball,
                                   float* __restrict__ X0) {
    int bc = blockIdx.x;          // b * 256 + c
    int b = bc >> 8;
    int c = bc & 255;
    const float* f = feat + ((size_t)b * CFEAT + c) * KPTS;
    const int* bl = ball + (size_t)b * NPROP * NSAMP;
    float* dst = X0 + (size_t)(3 + c) * NTOT + (size_t)b * NPROP * NSAMP;
    for (int t = threadIdx.x; t < NPROP * NSAMP; t += blockDim.x)
        dst[t] = f[bl[t]];
}

// ============================================================================
// SGEMM 128x128x16, 256 threads, 8x8 per thread.  MODE 0: BN+ReLU, 1: +bias
// C[M][N] = W[M][Kc] * X[Kc][N]
// ============================================================================
#define BM 128
#define BN 128
#define BK 16

template <int MODE>
__global__ void __launch_bounds__(256, 2)
gemm_kernel(const float* __restrict__ W, const float* __restrict__ X,
            float* __restrict__ Cout, int M, int Kc, int N,
            const float* __restrict__ gamma, const float* __restrict__ beta,
            const float* __restrict__ mean, const float* __restrict__ var,
            const float* __restrict__ bias) {
    __shared__ float As[BK][BM + 4];
    __shared__ float Bs[BK][BN];
    int tid = threadIdx.x;
    int m0 = blockIdx.y * BM;
    int n0 = blockIdx.x * BN;
    int tx = tid & 15;
    int ty = tid >> 4;

    float acc[8][8];
#pragma unroll
    for (int i = 0; i < 8; i++)
#pragma unroll
        for (int j = 0; j < 8; j++) acc[i][j] = 0.f;

    for (int k0 = 0; k0 < Kc; k0 += BK) {
        // A tile: W[m0+m][k0+kk..], transpose into As[k][m]
        {
            int m = tid >> 1;
            int kk = (tid & 1) * 8;
#pragma unroll
            for (int j = 0; j < 8; j++) {
                int kg = k0 + kk + j;
                float v = 0.f;
                if (m0 + m < M && kg < Kc) v = W[(size_t)(m0 + m) * Kc + kg];
                As[kk + j][m] = v;
            }
        }
        // B tile: X[k0+k][n0 .. n0+127]
        {
            int kk = tid >> 4;
            int nn = (tid & 15) * 8;
            int kg = k0 + kk;
            float4 v0 = {0, 0, 0, 0}, v1 = {0, 0, 0, 0};
            if (kg < Kc) {
                const float* src = X + (size_t)kg * N + n0 + nn;
                v0 = *(const float4*)(src);
                v1 = *(const float4*)(src + 4);
            }
            *(float4*)&Bs[kk][nn] = v0;
            *(float4*)&Bs[kk][nn + 4] = v1;
        }
        __syncthreads();
#pragma unroll
        for (int kk = 0; kk < BK; kk++) {
            float a[8], bb[8];
#pragma unroll
            for (int i = 0; i < 8; i++) a[i] = As[kk][ty * 8 + i];
#pragma unroll
            for (int j = 0; j < 8; j++) bb[j] = Bs[kk][tx * 8 + j];
#pragma unroll
            for (int i = 0; i < 8; i++)
#pragma unroll
                for (int j = 0; j < 8; j++) acc[i][j] += a[i] * bb[j];
        }
        __syncthreads();
    }

#pragma unroll
    for (int i = 0; i < 8; i++) {
        int m = m0 + ty * 8 + i;
        if (m >= M) continue;
        float sc = 1.f, sh = 0.f;
        if (MODE == 0) {
            float s = gamma[m] * rsqrtf(var[m] + 1e-5f);
            sc = s;
            sh = beta[m] - mean[m] * s;
        } else {
            sh = bias[m];
        }
        float* dst = Cout + (size_t)m * N + n0 + tx * 8;
#pragma unroll
        for (int j = 0; j < 8; j++) {
            float v;
            if (MODE == 0) v = fmaxf(acc[i][j] * sc + sh, 0.f);
            else           v = acc[i][j] + sh;
            dst[j] = v;
        }
    }
}

// ============================================================================
// Max over the 16 samples per proposal
// ============================================================================
__global__ void maxpool_kernel(const float* __restrict__ X, float* __restrict__ Y) {
    int i = blockIdx.x * blockDim.x + threadIdx.x;  // ch * NP2 + bp
    if (i >= 256 * NP2) return;
    const float* src = X + (size_t)(i >> 13) * NTOT + (size_t)(i & (NP2 - 1)) * NSAMP;
    float m = src[0];
#pragma unroll
    for (int s = 1; s < NSAMP; s++) m = fmaxf(m, src[s]);
    Y[i] = m;
}

// ============================================================================
// Finalize: heads, argmax size class, corners, softmaxes -> d_out
// ============================================================================
__global__ void finalize_kernel(const float* __restrict__ net,
                                const float* __restrict__ newxyz,
                                const float* __restrict__ msz,
                                float* __restrict__ out) {
    int n = blockIdx.x * blockDim.x + threadIdx.x;  // proposal id 0..8191
    if (n >= NP2) return;
#define NET(o) net[(size_t)(o) * NP2 + n]

    float obj0 = NET(0), obj1 = NET(1);
    out[OFF_OBJ + n * 2 + 0] = obj0;
    out[OFF_OBJ + n * 2 + 1] = obj1;

    float cx = newxyz[n * 3 + 0] + NET(2);
    float cy = newxyz[n * 3 + 1] + NET(3);
    float cz = newxyz[n * 3 + 2] + NET(4);
    out[OFF_CEN + n * 3 + 0] = cx;
    out[OFF_CEN + n * 3 + 1] = cy;
    out[OFF_CEN + n * 3 + 2] = cz;

    // size scores + argmax (first occurrence)
    int best = 0;
    float bv = NET(29);
    out[OFF_SS + n * 18 + 0] = bv;
#pragma unroll
    for (int sc = 1; sc < 18; sc++) {
        float v = NET(29 + sc);
        out[OFF_SS + n * 18 + sc] = v;
        if (v > bv) { bv = v; best = sc; }
    }

    // size residuals
#pragma unroll
    for (int sc = 0; sc < 18; sc++) {
#pragma unroll
        for (int d = 0; d < 3; d++) {
            float sres = NET(47 + sc * 3 + d) * msz[sc * 3 + d];
            out[OFF_SRES + ((size_t)n * 18 + sc) * 3 + d] = sres;
        }
    }

    float ps[3];
#pragma unroll
    for (int d = 0; d < 3; d++) {
        float m = msz[best * 3 + d];
        ps[d] = net[(size_t)(47 + best * 3 + d) * NP2 + n] * m + m;
        out[OFF_PSZ + n * 3 + d] = ps[d];
    }

    // sem
    float sem[18];
#pragma unroll
    for (int s = 0; s < 18; s++) {
        sem[s] = NET(101 + s);
        out[OFF_SEM + n * 18 + s] = sem[s];
    }

    // corners (angle = 0 -> identity rotation)
    const float sxA[8] = {1, 1, -1, -1, 1, 1, -1, -1};
    const float syA[8] = {1, 1, 1, 1, -1, -1, -1, -1};
    const float szA[8] = {1, -1, -1, 1, 1, -1, -1, 1};
    float c0 = cx, c1 = cz, c2 = -cy;
#pragma unroll
    for (int k = 0; k < 8; k++) {
        out[OFF_CORN + ((size_t)n * 8 + k) * 3 + 0] = ps[0] * sxA[k] * 0.5f + c0;
        out[OFF_CORN + ((size_t)n * 8 + k) * 3 + 1] = ps[2] * syA[k] * 0.5f + c1;
        out[OFF_CORN + ((size_t)n * 8 + k) * 3 + 2] = ps[1] * szA[k] * 0.5f + c2;
    }

    // sem_logits: sem then argmin(obj)*1e10 (first-min tie break)
#pragma unroll
    for (int s = 0; s < 18; s++) out[OFF_SLOG + n * 19 + s] = sem[s];
    out[OFF_SLOG + n * 19 + 18] = (obj0 <= obj1) ? 0.0f : 1e10f;

    // obj_prob = softmax(obj)[1]
    {
        float m = fmaxf(obj0, obj1);
        float e0 = expf(obj0 - m), e1 = expf(obj1 - m);
        out[OFF_OPROB + n] = e1 / (e0 + e1);
    }

    // sem_prob = softmax(sem)
    {
        float m = sem[0];
#pragma unroll
        for (int s = 1; s < 18; s++) m = fmaxf(m, sem[s]);
        float sum = 0.f;
        float e[18];
#pragma unroll
        for (int s = 0; s < 18; s++) { e[s] = expf(sem[s] - m); sum += e[s]; }
        float inv = 1.0f / sum;
#pragma unroll
        for (int s = 0; s < 18; s++) out[OFF_SPROB + n * 18 + s] = e[s] * inv;
    }
#undef NET
}

// ============================================================================
// launch
// ============================================================================
extern "C" void kernel_launch(void* const* d_in, const int* in_sizes, int n_in,
                              void* d_out, int out_size) {
    const float* xyz      = (const float*)d_in[0];
    const float* features = (const float*)d_in[1];
    const float* sa_w1    = (const float*)d_in[2];
    const float* sa_w2    = (const float*)d_in[3];
    const float* sa_w3    = (const float*)d_in[4];
    const float* sa_gamma = (const float*)d_in[5];
    const float* sa_beta  = (const float*)d_in[6];
    const float* sa_mean  = (const float*)d_in[7];
    const float* sa_var   = (const float*)d_in[8];
    const float* p_w1     = (const float*)d_in[9];
    const float* p_w2     = (const float*)d_in[10];
    const float* p_w3     = (const float*)d_in[11];
    const float* p_b3     = (const float*)d_in[12];
    const float* p_gamma  = (const float*)d_in[13];
    const float* p_beta   = (const float*)d_in[14];
    const float* p_mean   = (const float*)d_in[15];
    const float* p_var    = (const float*)d_in[16];
    const float* msz      = (const float*)d_in[17];
    float* out = (float*)d_out;

    float* X0; float* X1; float* X2; float* Y; float* Y1; float* Y2; float* net;
    float* newxyz; int* ball;
    cudaGetSymbolAddress((void**)&X0, g_X0);
    cudaGetSymbolAddress((void**)&X1, g_X1);
    cudaGetSymbolAddress((void**)&X2, g_X2);
    cudaGetSymbolAddress((void**)&Y,  g_Y);
    cudaGetSymbolAddress((void**)&Y1, g_Y1);
    cudaGetSymbolAddress((void**)&Y2, g_Y2);
    cudaGetSymbolAddress((void**)&net, g_net);
    cudaGetSymbolAddress((void**)&newxyz, g_newxyz);
    cudaGetSymbolAddress((void**)&ball, g_ball);

    fps_kernel<<<BATCH, 256>>>(xyz, newxyz);
    ball_query_kernel<<<NP2 * 32 / 256, 256>>>(xyz, newxyz, ball);
    gather_xyz_kernel<<<NTOT / 256, 256>>>(xyz, newxyz, ball, X0);
    gather_feat_kernel<<<BATCH * CFEAT, 256>>>(features, ball, X0);

    dim3 gSA(NTOT / BN, 2);
    gemm_kernel<0><<<gSA, 256>>>(sa_w1, X0, X1, 256, 259, NTOT,
                                 sa_gamma + 0,   sa_beta + 0,   sa_mean + 0,   sa_var + 0,   nullptr);
    gemm_kernel<0><<<gSA, 256>>>(sa_w2, X1, X2, 256, 256, NTOT,
                                 sa_gamma + 256, sa_beta + 256, sa_mean + 256, sa_var + 256, nullptr);
    gemm_kernel<0><<<gSA, 256>>>(sa_w3, X2, X0, 256, 256, NTOT,
                                 sa_gamma + 512, sa_beta + 512, sa_mean + 512, sa_var + 512, nullptr);

    maxpool_kernel<<<(256 * NP2) / 256, 256>>>(X0, Y);

    dim3 gP(NP2 / BN, 2);
    gemm_kernel<0><<<gP, 256>>>(p_w1, Y,  Y1, 256, 256, NP2,
                                p_gamma + 0,   p_beta + 0,   p_mean + 0,   p_var + 0,   nullptr);
    gemm_kernel<0><<<gP, 256>>>(p_w2, Y1, Y2, 256, 256, NP2,
                                p_gamma + 256, p_beta + 256, p_mean + 256, p_var + 256, nullptr);
    dim3 gP3(NP2 / BN, 1);
    gemm_kernel<1><<<gP3, 256>>>(p_w3, Y2, net, OUTD, 256, NP2,
                                 nullptr, nullptr, nullptr, nullptr, p_b3);

    finalize_kernel<<<NP2 / 256, 256>>>(net, newxyz, msz, out);
}

// round 8
// speedup vs baseline: 1.7732x; 1.7714x over previous
#include <cuda_runtime.h>
#include <cuda_fp16.h>
#include <cstdint>

#define BATCH 32
#define KPTS 2048
#define CFEAT 256
#define NPROP 256
#define NSAMP 16
#define NTOT (BATCH * NPROP * NSAMP)   // 131072
#define NP2  (BATCH * NPROP)           // 8192
#define OUTD 119

// ---------------- scratch (static device memory) ----------------------------
__device__ float  g_G  [259 * NTOT];                       // channel-major gather staging
__device__ __align__(128) __half g_X0h[(size_t)NTOT * 288];
__device__ __align__(128) __half g_X0l[(size_t)NTOT * 288];
__device__ __align__(128) __half g_X1h[(size_t)NTOT * 256];
__device__ __align__(128) __half g_X1l[(size_t)NTOT * 256];
__device__ __align__(128) __half g_X2h[(size_t)NTOT * 256];
__device__ __align__(128) __half g_X2l[(size_t)NTOT * 256];
__device__ __align__(128) __half g_X3h[(size_t)NTOT * 256];
__device__ __align__(128) __half g_X3l[(size_t)NTOT * 256];
__device__ __align__(128) __half g_Yh [NP2 * 256];
__device__ __align__(128) __half g_Yl [NP2 * 256];
__device__ __align__(128) __half g_Y1h[NP2 * 256];
__device__ __align__(128) __half g_Y1l[NP2 * 256];
__device__ __align__(128) __half g_Y2h[NP2 * 256];
__device__ __align__(128) __half g_Y2l[NP2 * 256];
__device__ float  g_net[NP2 * 128];
__device__ __align__(128) __half g_W1h[256 * 288];
__device__ __align__(128) __half g_W1l[256 * 288];
__device__ __align__(128) __half g_W2h[256 * 256];
__device__ __align__(128) __half g_W2l[256 * 256];
__device__ __align__(128) __half g_W3h[256 * 256];
__device__ __align__(128) __half g_W3l[256 * 256];
__device__ __align__(128) __half g_P1h[256 * 256];
__device__ __align__(128) __half g_P1l[256 * 256];
__device__ __align__(128) __half g_P2h[256 * 256];
__device__ __align__(128) __half g_P2l[256 * 256];
__device__ __align__(128) __half g_P3h[128 * 256];
__device__ __align__(128) __half g_P3l[128 * 256];
__device__ float  g_newxyz[NP2 * 3];
__device__ int    g_ball[NP2 * NSAMP];

// ---------------- output offsets (floats) -----------------------------------
#define OFF_OBJ   0
#define OFF_CEN   16384
#define OFF_SS    40960
#define OFF_SRES  188416
#define OFF_PSZ   630784
#define OFF_SEM   655360
#define OFF_CORN  802816
#define OFF_SLOG  999424
#define OFF_OPROB 1155072
#define OFF_SPROB 1163264

// ---------------- helpers ----------------------------------------------------
__device__ __forceinline__ uint32_t s2u(const void* p) {
    uint32_t a;
    asm("{ .reg .u64 t; cvta.to.shared.u64 t, %1; cvt.u32.u64 %0, t; }" : "=r"(a) : "l"(p));
    return a;
}
__device__ __forceinline__ void ldsm4(uint32_t* r, uint32_t a) {
    asm volatile("ldmatrix.sync.aligned.m8n8.x4.shared.b16 {%0,%1,%2,%3}, [%4];"
                 : "=r"(r[0]), "=r"(r[1]), "=r"(r[2]), "=r"(r[3]) : "r"(a));
}
__device__ __forceinline__ void mma16816(float* c, const uint32_t* a, const uint32_t* b) {
    asm volatile(
        "mma.sync.aligned.m16n8k16.row.col.f32.f16.f16.f32 "
        "{%0,%1,%2,%3}, {%4,%5,%6,%7}, {%8,%9}, {%0,%1,%2,%3};"
        : "+f"(c[0]), "+f"(c[1]), "+f"(c[2]), "+f"(c[3])
        : "r"(a[0]), "r"(a[1]), "r"(a[2]), "r"(a[3]), "r"(b[0]), "r"(b[1]));
}
__device__ __forceinline__ void cpasync16(uint32_t sa, const void* g) {
    asm volatile("cp.async.cg.shared.global [%0], [%1], 16;" :: "r"(sa), "l"(g));
}
__device__ __forceinline__ void hsplit(float v, __half& h, __half& l) {
    h = __float2half_rn(v);
    l = __float2half_rn(v - __half2float(h));
}

// ============================================================================
// FPS: one block per batch
// ============================================================================
__global__ void fps_kernel(const float* __restrict__ xyz, float* __restrict__ newxyz) {
    int b = blockIdx.x;
    int t = threadIdx.x;
    __shared__ float sx[KPTS], sy[KPTS], sz[KPTS];
    __shared__ float wv[8];
    __shared__ int   wi[8];
    __shared__ int   far_s;

    const float* p = xyz + (size_t)b * KPTS * 3;
    float px[8], py[8], pz[8], dist[8];
#pragma unroll
    for (int i = 0; i < 8; i++) {
        int j = i * 256 + t;
        px[i] = p[j * 3 + 0];
        py[i] = p[j * 3 + 1];
        pz[i] = p[j * 3 + 2];
        sx[j] = px[i]; sy[j] = py[i]; sz[j] = pz[i];
        dist[i] = 1e10f;
    }
    if (t == 0) far_s = 0;
    __syncthreads();

    for (int it = 0; it < NPROP; it++) {
        int far = far_s;
        if (t == 0) {
            float* o = newxyz + (size_t)(b * NPROP + it) * 3;
            o[0] = sx[far]; o[1] = sy[far]; o[2] = sz[far];
        }
        float cx = sx[far], cy = sy[far], cz = sz[far];
        float bv = -1.0f;
        int   bj = 0x7fffffff;
#pragma unroll
        for (int i = 0; i < 8; i++) {
            float dx = px[i] - cx, dy = py[i] - cy, dz = pz[i] - cz;
            float d = dx * dx + dy * dy + dz * dz;
            dist[i] = fminf(dist[i], d);
            int j = i * 256 + t;
            if (dist[i] > bv || (dist[i] == bv && j < bj)) { bv = dist[i]; bj = j; }
        }
#pragma unroll
        for (int off = 16; off; off >>= 1) {
            float ov = __shfl_down_sync(0xffffffffu, bv, off);
            int   oj = __shfl_down_sync(0xffffffffu, bj, off);
            if (ov > bv || (ov == bv && oj < bj)) { bv = ov; bj = oj; }
        }
        if ((t & 31) == 0) { wv[t >> 5] = bv; wi[t >> 5] = bj; }
        __syncthreads();
        if (t == 0) {
            float fv = wv[0]; int fj = wi[0];
#pragma unroll
            for (int w = 1; w < 8; w++) {
                if (wv[w] > fv || (wv[w] == fv && wi[w] < fj)) { fv = wv[w]; fj = wi[w]; }
            }
            far_s = fj;
        }
        __syncthreads();
    }
}

// ============================================================================
// Ball query: one warp per proposal
// ============================================================================
__global__ void ball_query_kernel(const float* __restrict__ xyz,
                                  const float* __restrict__ newxyz,
                                  int* __restrict__ ball) {
    int gwarp = (blockIdx.x * blockDim.x + threadIdx.x) >> 5;
    if (gwarp >= NP2) return;
    int lane = threadIdx.x & 31;
    int wl = threadIdx.x >> 5;
    int b = gwarp >> 8;

    __shared__ int slots[8][16];
    if (lane == 0) slots[wl][0] = 0;

    float cx = newxyz[gwarp * 3 + 0];
    float cy = newxyz[gwarp * 3 + 1];
    float cz = newxyz[gwarp * 3 + 2];
    const float* p = xyz + (size_t)b * KPTS * 3;

    int cnt = 0;
    for (int r = 0; r < KPTS / 32 && cnt < NSAMP; r++) {
        int j = r * 32 + lane;
        float dx = cx - p[j * 3 + 0];
        float dy = cy - p[j * 3 + 1];
        float dz = cz - p[j * 3 + 2];
        float d2 = dx * dx + dy * dy + dz * dz;
        bool pred = d2 < 0.09f;
        unsigned m = __ballot_sync(0xffffffffu, pred);
        int pos = cnt + __popc(m & ((1u << lane) - 1u));
        if (pred && pos < NSAMP) slots[wl][pos] = j;
        cnt += __popc(m);
    }
    __syncwarp();
    if (lane < NSAMP) {
        int first = slots[wl][0];
        int v = (lane < cnt) ? slots[wl][lane] : first;
        ball[gwarp * NSAMP + lane] = v;
    }
}

// ============================================================================
// Gathers (channel-major staging)
// ============================================================================
__global__ void gather_xyz_kernel(const float* __restrict__ xyz,
                                  const float* __restrict__ newxyz,
                                  const int* __restrict__ ball,
                                  float* __restrict__ G) {
    int n = blockIdx.x * blockDim.x + threadIdx.x;
    if (n >= NTOT) return;
    int bp = n >> 4;
    int b = bp >> 8;
    int j = ball[n];
    const float* pj = xyz + ((size_t)b * KPTS + j) * 3;
    const float* cen = newxyz + (size_t)bp * 3;
    G[0 * (size_t)NTOT + n] = (pj[0] - cen[0]) / 0.3f;
    G[1 * (size_t)NTOT + n] = (pj[1] - cen[1]) / 0.3f;
    G[2 * (size_t)NTOT + n] = (pj[2] - cen[2]) / 0.3f;
}

__global__ void gather_feat_kernel(const float* __restrict__ feat,
                                   const int* __restrict__ ball,
                                   float* __restrict__ G) {
    int bc = blockIdx.x;          // b * 256 + c
    int b = bc >> 8;
    int c = bc & 255;
    const float* f = feat + ((size_t)b * CFEAT + c) * KPTS;
    const int* bl = ball + (size_t)b * NPROP * NSAMP;
    float* dst = G + (size_t)(3 + c) * NTOT + (size_t)b * NPROP * NSAMP;
    for (int t = threadIdx.x; t < NPROP * NSAMP; t += blockDim.x)
        dst[t] = f[bl[t]];
}

// ============================================================================
// Transpose + split: G[k][NTOT] fp32 -> X0h/X0l [n][288] fp16
// ============================================================================
__global__ void transpose_split_kernel(const float* __restrict__ G,
                                       __half* __restrict__ Xh, __half* __restrict__ Xl) {
    __shared__ float tile[32][33];
    int n0 = blockIdx.x * 32;
    int k0 = blockIdx.y * 32;
    int tx = threadIdx.x, ty = threadIdx.y;   // (32, 8)
#pragma unroll
    for (int i = 0; i < 32; i += 8) {
        int k = k0 + ty + i;
        tile[ty + i][tx] = (k < 259) ? G[(size_t)k * NTOT + n0 + tx] : 0.f;
    }
    __syncthreads();
#pragma unroll
    for (int i = 0; i < 32; i += 8) {
        int n = n0 + ty + i;
        float v = tile[tx][ty + i];
        __half h, l;
        hsplit(v, h, l);
        Xh[(size_t)n * 288 + k0 + tx] = h;
        Xl[(size_t)n * 288 + k0 + tx] = l;
    }
}

// ============================================================================
// Weight split (+padding)
// ============================================================================
__global__ void split_w_kernel(const float* __restrict__ W,
                               __half* __restrict__ Wh, __half* __restrict__ Wl,
                               int rows_valid, int cols_valid, int cols_src,
                               int cols_dst, int total) {
    int idx = blockIdx.x * 256 + threadIdx.x;
    if (idx >= total) return;
    int r = idx / cols_dst, c = idx % cols_dst;
    float v = (r < rows_valid && c < cols_valid) ? W[(size_t)r * cols_src + c] : 0.f;
    __half h, l;
    hsplit(v, h, l);
    Wh[idx] = h;
    Wl[idx] = l;
}

// ============================================================================
// fp16 split-precision tensor-core GEMM (mma.sync.m16n8k16)
//   C[m][ch] = A[m][:KC] . B[ch][:KC]   with A=Ah+Al, B=Bh+Bl
//   MODE 0: BN+ReLU, split fp16 output planes
//   MODE 1: +bias, fp32 output
// CTA tile 128x128, 8 warps of 64x32, K=16 stages, cp.async double buffer.
// ============================================================================
template <int MODE>
__global__ void __launch_bounds__(256, 2)
hgemm_kernel(const __half* __restrict__ Ah, const __half* __restrict__ Al,
             const __half* __restrict__ Bh, const __half* __restrict__ Bl,
             int KC, int ldC,
             __half* __restrict__ Ch, __half* __restrict__ Cl,
             float* __restrict__ Cf,
             const float* __restrict__ gamma, const float* __restrict__ beta,
             const float* __restrict__ mean, const float* __restrict__ var,
             const float* __restrict__ bias) {
    __shared__ __align__(16) uint8_t smem[2][16384];
    const int tid  = threadIdx.x;
    const int lane = tid & 31;
    const int warp = tid >> 5;
    const int wm = warp & 1;        // 2 m-tiles of 64
    const int wn = warp >> 1;       // 4 n-tiles of 32
    const int m0 = blockIdx.x * 128;
    const int n0 = blockIdx.y * 128;

    const uint32_t sb[2] = { s2u(smem[0]), s2u(smem[1]) };

    float acc[4][4][4];
#pragma unroll
    for (int i = 0; i < 4; i++)
#pragma unroll
        for (int j = 0; j < 4; j++)
#pragma unroll
            for (int q = 0; q < 4; q++) acc[i][j][q] = 0.f;

    // per-thread load assignment: plane = tid/64 (Ah,Al,Bh,Bl); 2 rows x 2 chunks
    const int plane = tid >> 6;
    const int idx0 = (tid & 63) * 4;
    const __half* gplane = (plane == 0) ? Ah : (plane == 1) ? Al : (plane == 2) ? Bh : Bl;
    const int rbase = (plane < 2) ? m0 : n0;
    const uint32_t pl_off = plane * 4096;

    const int nst = KC >> 4;

#define LOAD_STAGE(s)                                                          \
    {                                                                          \
        uint32_t base = sb[(s) & 1] + pl_off;                                  \
        int k0 = (s) << 4;                                                     \
        _Pragma("unroll")                                                      \
        for (int t4 = 0; t4 < 4; t4++) {                                       \
            int idx = idx0 + t4;                                               \
            int row = idx >> 1, cc = idx & 1;                                  \
            uint32_t sa = base + row * 32 + (((cc ^ (row >> 2)) & 1) << 4);    \
            cpasync16(sa, gplane + (size_t)(rbase + row) * KC + k0 + cc * 8);  \
        }                                                                      \
        asm volatile("cp.async.commit_group;");                                \
    }

    LOAD_STAGE(0);

    const int lrow = lane & 15, lc = lane >> 4;
    const int br = (lane & 7) + ((lane >> 4) & 1) * 8;
    const int bc = (lane >> 3) & 1;

    for (int s = 0; s < nst; s++) {
        if (s + 1 < nst) {
            LOAD_STAGE(s + 1);
            asm volatile("cp.async.wait_group 1;");
        } else {
            asm volatile("cp.async.wait_group 0;");
        }
        __syncthreads();

        uint32_t base = sb[s & 1];
        uint32_t ah[4][4], al[4][4];
#pragma unroll
        for (int i = 0; i < 4; i++) {
            int r = wm * 64 + i * 16 + lrow;
            uint32_t a = base + r * 32 + (((lc ^ (r >> 2)) & 1) << 4);
            ldsm4(ah[i], a);
            ldsm4(al[i], a + 4096);
        }
#pragma unroll
        for (int jj = 0; jj < 2; jj++) {
            int r = wn * 32 + jj * 16 + br;
            uint32_t boff = base + 8192 + r * 32 + (((bc ^ (r >> 2)) & 1) << 4);
            uint32_t bh4[4], bl4[4];
            ldsm4(bh4, boff);
            ldsm4(bl4, boff + 4096);
#pragma unroll
            for (int j2 = 0; j2 < 2; j2++) {
                const uint32_t* bhf = bh4 + j2 * 2;
                const uint32_t* blf = bl4 + j2 * 2;
#pragma unroll
                for (int i = 0; i < 4; i++) {
                    float* c = acc[i][jj * 2 + j2];
                    mma16816(c, ah[i], bhf);
                    mma16816(c, ah[i], blf);
                    mma16816(c, al[i], bhf);
                }
            }
        }
        __syncthreads();
    }

    // epilogue
    const int colq = (lane & 3) * 2;
    const int rhalf = lane >> 2;
#pragma unroll
    for (int j = 0; j < 4; j++) {
        int ch = n0 + wn * 32 + j * 8 + colq;
        float sc0 = 1.f, sh0 = 0.f, sc1 = 1.f, sh1 = 0.f;
        if (MODE == 0) {
            float s0 = __ldg(gamma + ch) * rsqrtf(__ldg(var + ch) + 1e-5f);
            sc0 = s0; sh0 = __ldg(beta + ch) - __ldg(mean + ch) * s0;
            float s1 = __ldg(gamma + ch + 1) * rsqrtf(__ldg(var + ch + 1) + 1e-5f);
            sc1 = s1; sh1 = __ldg(beta + ch + 1) - __ldg(mean + ch + 1) * s1;
        } else {
            sh0 = (ch < OUTD) ? __ldg(bias + ch) : 0.f;
            sh1 = (ch + 1 < OUTD) ? __ldg(bias + ch + 1) : 0.f;
        }
#pragma unroll
        for (int i = 0; i < 4; i++) {
            int r0 = m0 + wm * 64 + i * 16 + rhalf;
#pragma unroll
            for (int hh = 0; hh < 2; hh++) {
                int r = r0 + hh * 8;
                float v0 = acc[i][j][hh * 2 + 0];
                float v1 = acc[i][j][hh * 2 + 1];
                if (MODE == 0) {
                    v0 = fmaxf(v0 * sc0 + sh0, 0.f);
                    v1 = fmaxf(v1 * sc1 + sh1, 0.f);
                    __half h0, l0, h1, l1;
                    hsplit(v0, h0, l0);
                    hsplit(v1, h1, l1);
                    *(__half2*)(Ch + (size_t)r * ldC + ch) = __halves2half2(h0, h1);
                    *(__half2*)(Cl + (size_t)r * ldC + ch) = __halves2half2(l0, l1);
                } else {
                    Cf[(size_t)r * ldC + ch]     = v0 + sh0;
                    Cf[(size_t)r * ldC + ch + 1] = v1 + sh1;
                }
            }
        }
    }
#undef LOAD_STAGE
}

// ============================================================================
// Maxpool over 16 samples (split planes in, split planes out)
// ============================================================================
__global__ void maxpool_split_kernel(const __half* __restrict__ Xh, const __half* __restrict__ Xl,
                                     __half* __restrict__ Yh, __half* __restrict__ Yl) {
    int bp = blockIdx.x;
    int ch = threadIdx.x;
    const __half* ph = Xh + (size_t)bp * 16 * 256 + ch;
    const __half* pl = Xl + (size_t)bp * 16 * 256 + ch;
    float m = __half2float(ph[0]) + __half2float(pl[0]);
#pragma unroll
    for (int s = 1; s < NSAMP; s++) {
        float v = __half2float(ph[(size_t)s * 256]) + __half2float(pl[(size_t)s * 256]);
        m = fmaxf(m, v);
    }
    __half h, l;
    hsplit(m, h, l);
    Yh[(size_t)bp * 256 + ch] = h;
    Yl[(size_t)bp * 256 + ch] = l;
}

// ============================================================================
// Finalize (net layout [p][128])
// ============================================================================
__global__ void finalize_kernel(const float* __restrict__ net,
                                const float* __restrict__ newxyz,
                                const float* __restrict__ msz,
                                float* __restrict__ out) {
    int n = blockIdx.x * blockDim.x + threadIdx.x;
    if (n >= NP2) return;
#define NET(o) net[(size_t)n * 128 + (o)]

    float obj0 = NET(0), obj1 = NET(1);
    out[OFF_OBJ + n * 2 + 0] = obj0;
    out[OFF_OBJ + n * 2 + 1] = obj1;

    float cx = newxyz[n * 3 + 0] + NET(2);
    float cy = newxyz[n * 3 + 1] + NET(3);
    float cz = newxyz[n * 3 + 2] + NET(4);
    out[OFF_CEN + n * 3 + 0] = cx;
    out[OFF_CEN + n * 3 + 1] = cy;
    out[OFF_CEN + n * 3 + 2] = cz;

    int best = 0;
    float bv = NET(29);
    out[OFF_SS + n * 18 + 0] = bv;
#pragma unroll
    for (int sc = 1; sc < 18; sc++) {
        float v = NET(29 + sc);
        out[OFF_SS + n * 18 + sc] = v;
        if (v > bv) { bv = v; best = sc; }
    }

#pragma unroll
    for (int sc = 0; sc < 18; sc++) {
#pragma unroll
        for (int d = 0; d < 3; d++) {
            float sres = NET(47 + sc * 3 + d) * msz[sc * 3 + d];
            out[OFF_SRES + ((size_t)n * 18 + sc) * 3 + d] = sres;
        }
    }

    float ps[3];
#pragma unroll
    for (int d = 0; d < 3; d++) {
        float m = msz[best * 3 + d];
        ps[d] = NET(47 + best * 3 + d) * m + m;
        out[OFF_PSZ + n * 3 + d] = ps[d];
    }

    float sem[18];
#pragma unroll
    for (int s = 0; s < 18; s++) {
        sem[s] = NET(101 + s);
        out[OFF_SEM + n * 18 + s] = sem[s];
    }

    const float sxA[8] = {1, 1, -1, -1, 1, 1, -1, -1};
    const float syA[8] = {1, 1, 1, 1, -1, -1, -1, -1};
    const float szA[8] = {1, -1, -1, 1, 1, -1, -1, 1};
    float c0 = cx, c1 = cz, c2 = -cy;
#pragma unroll
    for (int k = 0; k < 8; k++) {
        out[OFF_CORN + ((size_t)n * 8 + k) * 3 + 0] = ps[0] * sxA[k] * 0.5f + c0;
        out[OFF_CORN + ((size_t)n * 8 + k) * 3 + 1] = ps[2] * syA[k] * 0.5f + c1;
        out[OFF_CORN + ((size_t)n * 8 + k) * 3 + 2] = ps[1] * szA[k] * 0.5f + c2;
    }

#pragma unroll
    for (int s = 0; s < 18; s++) out[OFF_SLOG + n * 19 + s] = sem[s];
    out[OFF_SLOG + n * 19 + 18] = (obj0 <= obj1) ? 0.0f : 1e10f;

    {
        float m = fmaxf(obj0, obj1);
        float e0 = expf(obj0 - m), e1 = expf(obj1 - m);
        out[OFF_OPROB + n] = e1 / (e0 + e1);
    }
    {
        float m = sem[0];
#pragma unroll
        for (int s = 1; s < 18; s++) m = fmaxf(m, sem[s]);
        float sum = 0.f;
        float e[18];
#pragma unroll
        for (int s = 0; s < 18; s++) { e[s] = expf(sem[s] - m); sum += e[s]; }
        float inv = 1.0f / sum;
#pragma unroll
        for (int s = 0; s < 18; s++) out[OFF_SPROB + n * 18 + s] = e[s] * inv;
    }
#undef NET
}

// ============================================================================
// launch
// ============================================================================
extern "C" void kernel_launch(void* const* d_in, const int* in_sizes, int n_in,
                              void* d_out, int out_size) {
    const float* xyz      = (const float*)d_in[0];
    const float* features = (const float*)d_in[1];
    const float* sa_w1    = (const float*)d_in[2];
    const float* sa_w2    = (const float*)d_in[3];
    const float* sa_w3    = (const float*)d_in[4];
    const float* sa_gamma = (const float*)d_in[5];
    const float* sa_beta  = (const float*)d_in[6];
    const float* sa_mean  = (const float*)d_in[7];
    const float* sa_var   = (const float*)d_in[8];
    const float* p_w1     = (const float*)d_in[9];
    const float* p_w2     = (const float*)d_in[10];
    const float* p_w3     = (const float*)d_in[11];
    const float* p_b3     = (const float*)d_in[12];
    const float* p_gamma  = (const float*)d_in[13];
    const float* p_beta   = (const float*)d_in[14];
    const float* p_mean   = (const float*)d_in[15];
    const float* p_var    = (const float*)d_in[16];
    const float* msz      = (const float*)d_in[17];
    float* out = (float*)d_out;

    float *G, *net, *newxyz;
    int* ball;
    __half *X0h, *X0l, *X1h, *X1l, *X2h, *X2l, *X3h, *X3l;
    __half *Yh, *Yl, *Y1h, *Y1l, *Y2h, *Y2l;
    __half *W1h, *W1l, *W2h, *W2l, *W3h, *W3l, *P1h, *P1l, *P2h, *P2l, *P3h, *P3l;
    cudaGetSymbolAddress((void**)&G,   g_G);
    cudaGetSymbolAddress((void**)&net, g_net);
    cudaGetSymbolAddress((void**)&newxyz, g_newxyz);
    cudaGetSymbolAddress((void**)&ball, g_ball);
    cudaGetSymbolAddress((void**)&X0h, g_X0h); cudaGetSymbolAddress((void**)&X0l, g_X0l);
    cudaGetSymbolAddress((void**)&X1h, g_X1h); cudaGetSymbolAddress((void**)&X1l, g_X1l);
    cudaGetSymbolAddress((void**)&X2h, g_X2h); cudaGetSymbolAddress((void**)&X2l, g_X2l);
    cudaGetSymbolAddress((void**)&X3h, g_X3h); cudaGetSymbolAddress((void**)&X3l, g_X3l);
    cudaGetSymbolAddress((void**)&Yh,  g_Yh);  cudaGetSymbolAddress((void**)&Yl,  g_Yl);
    cudaGetSymbolAddress((void**)&Y1h, g_Y1h); cudaGetSymbolAddress((void**)&Y1l, g_Y1l);
    cudaGetSymbolAddress((void**)&Y2h, g_Y2h); cudaGetSymbolAddress((void**)&Y2l, g_Y2l);
    cudaGetSymbolAddress((void**)&W1h, g_W1h); cudaGetSymbolAddress((void**)&W1l, g_W1l);
    cudaGetSymbolAddress((void**)&W2h, g_W2h); cudaGetSymbolAddress((void**)&W2l, g_W2l);
    cudaGetSymbolAddress((void**)&W3h, g_W3h); cudaGetSymbolAddress((void**)&W3l, g_W3l);
    cudaGetSymbolAddress((void**)&P1h, g_P1h); cudaGetSymbolAddress((void**)&P1l, g_P1l);
    cudaGetSymbolAddress((void**)&P2h, g_P2h); cudaGetSymbolAddress((void**)&P2l, g_P2l);
    cudaGetSymbolAddress((void**)&P3h, g_P3h); cudaGetSymbolAddress((void**)&P3l, g_P3l);

    fps_kernel<<<BATCH, 256>>>(xyz, newxyz);
    ball_query_kernel<<<NP2 * 32 / 256, 256>>>(xyz, newxyz, ball);
    gather_xyz_kernel<<<NTOT / 256, 256>>>(xyz, newxyz, ball, G);
    gather_feat_kernel<<<BATCH * CFEAT, 256>>>(features, ball, G);

    split_w_kernel<<<(256 * 288 + 255) / 256, 256>>>(sa_w1, W1h, W1l, 256, 259, 259, 288, 256 * 288);
    split_w_kernel<<<256, 256>>>(sa_w2, W2h, W2l, 256, 256, 256, 256, 256 * 256);
    split_w_kernel<<<256, 256>>>(sa_w3, W3h, W3l, 256, 256, 256, 256, 256 * 256);
    split_w_kernel<<<256, 256>>>(p_w1, P1h, P1l, 256, 256, 256, 256, 256 * 256);
    split_w_kernel<<<256, 256>>>(p_w2, P2h, P2l, 256, 256, 256, 256, 256 * 256);
    split_w_kernel<<<128, 256>>>(p_w3, P3h, P3l, OUTD, 256, 256, 256, 128 * 256);

    transpose_split_kernel<<<dim3(NTOT / 32, 288 / 32), dim3(32, 8)>>>(G, X0h, X0l);

    dim3 gSA(NTOT / 128, 2);
    hgemm_kernel<0><<<gSA, 256>>>(X0h, X0l, W1h, W1l, 288, 256, X1h, X1l, nullptr,
                                  sa_gamma + 0,   sa_beta + 0,   sa_mean + 0,   sa_var + 0,   nullptr);
    hgemm_kernel<0><<<gSA, 256>>>(X1h, X1l, W2h, W2l, 256, 256, X2h, X2l, nullptr,
                                  sa_gamma + 256, sa_beta + 256, sa_mean + 256, sa_var + 256, nullptr);
    hgemm_kernel<0><<<gSA, 256>>>(X2h, X2l, W3h, W3l, 256, 256, X3h, X3l, nullptr,
                                  sa_gamma + 512, sa_beta + 512, sa_mean + 512, sa_var + 512, nullptr);

    maxpool_split_kernel<<<NP2, 256>>>(X3h, X3l, Yh, Yl);

    dim3 gP(NP2 / 128, 2);
    hgemm_kernel<0><<<gP, 256>>>(Yh, Yl, P1h, P1l, 256, 256, Y1h, Y1l, nullptr,
                                 p_gamma + 0,   p_beta + 0,   p_mean + 0,   p_var + 0,   nullptr);
    hgemm_kernel<0><<<gP, 256>>>(Y1h, Y1l, P2h, P2l, 256, 256, Y2h, Y2l, nullptr,
                                 p_gamma + 256, p_beta + 256, p_mean + 256, p_var + 256, nullptr);
    dim3 gH(NP2 / 128, 1);
    hgemm_kernel<1><<<gH, 256>>>(Y2h, Y2l, P3h, P3l, 256, 128, nullptr, nullptr, net,
                                 nullptr, nullptr, nullptr, nullptr, p_b3);

    finalize_kernel<<<NP2 / 256, 256>>>(net, newxyz, msz, out);
}

// round 10
// speedup vs baseline: 1.9830x; 1.1183x over previous
#include <cuda_runtime.h>
#include <cuda_fp16.h>
#include <cstdint>

#define BATCH 32
#define KPTS 2048
#define CFEAT 256
#define NPROP 256
#define NSAMP 16
#define NTOT (BATCH * NPROP * NSAMP)   // 131072
#define NP2  (BATCH * NPROP)           // 8192
#define OUTD 119

// ---------------- scratch (static device memory) ----------------------------
__device__ float  g_G  [259 * NTOT];                       // channel-major gather staging
__device__ __align__(128) __half g_X0h[(size_t)NTOT * 288];
__device__ __align__(128) __half g_X0l[(size_t)NTOT * 288];
__device__ __align__(128) __half g_X1h[(size_t)NTOT * 256];
__device__ __align__(128) __half g_X1l[(size_t)NTOT * 256];
__device__ __align__(128) __half g_X2h[(size_t)NTOT * 256];
__device__ __align__(128) __half g_X2l[(size_t)NTOT * 256];
__device__ __align__(128) __half g_Yh [NP2 * 256];
__device__ __align__(128) __half g_Yl [NP2 * 256];
__device__ __align__(128) __half g_Y1h[NP2 * 256];
__device__ __align__(128) __half g_Y1l[NP2 * 256];
__device__ __align__(128) __half g_Y2h[NP2 * 256];
__device__ __align__(128) __half g_Y2l[NP2 * 256];
__device__ float  g_net[NP2 * 128];
__device__ __align__(128) __half g_W1h[256 * 288];
__device__ __align__(128) __half g_W1l[256 * 288];
__device__ __align__(128) __half g_W2h[256 * 256];
__device__ __align__(128) __half g_W2l[256 * 256];
__device__ __align__(128) __half g_W3h[256 * 256];
__device__ __align__(128) __half g_W3l[256 * 256];
__device__ __align__(128) __half g_P1h[256 * 256];
__device__ __align__(128) __half g_P1l[256 * 256];
__device__ __align__(128) __half g_P2h[256 * 256];
__device__ __align__(128) __half g_P2l[256 * 256];
__device__ __align__(128) __half g_P3h[128 * 256];
__device__ __align__(128) __half g_P3l[128 * 256];
__device__ float  g_newxyz[NP2 * 3];
__device__ int    g_ball[NP2 * NSAMP];

// ---------------- output offsets (floats) -----------------------------------
#define OFF_OBJ   0
#define OFF_CEN   16384
#define OFF_SS    40960
#define OFF_SRES  188416
#define OFF_PSZ   630784
#define OFF_SEM   655360
#define OFF_CORN  802816
#define OFF_SLOG  999424
#define OFF_OPROB 1155072
#define OFF_SPROB 1163264

// ---------------- helpers ----------------------------------------------------
__device__ __forceinline__ uint32_t s2u(const void* p) {
    uint32_t a;
    asm("{ .reg .u64 t; cvta.to.shared.u64 t, %1; cvt.u32.u64 %0, t; }" : "=r"(a) : "l"(p));
    return a;
}
__device__ __forceinline__ void ldsm4(uint32_t* r, uint32_t a) {
    asm volatile("ldmatrix.sync.aligned.m8n8.x4.shared.b16 {%0,%1,%2,%3}, [%4];"
                 : "=r"(r[0]), "=r"(r[1]), "=r"(r[2]), "=r"(r[3]) : "r"(a));
}
__device__ __forceinline__ void mma16816(float* c, const uint32_t* a, const uint32_t* b) {
    asm volatile(
        "mma.sync.aligned.m16n8k16.row.col.f32.f16.f16.f32 "
        "{%0,%1,%2,%3}, {%4,%5,%6,%7}, {%8,%9}, {%0,%1,%2,%3};"
        : "+f"(c[0]), "+f"(c[1]), "+f"(c[2]), "+f"(c[3])
        : "r"(a[0]), "r"(a[1]), "r"(a[2]), "r"(a[3]), "r"(b[0]), "r"(b[1]));
}
__device__ __forceinline__ void cpasync16(uint32_t sa, const void* g) {
    asm volatile("cp.async.cg.shared.global [%0], [%1], 16;" :: "r"(sa), "l"(g));
}
__device__ __forceinline__ void hsplit(float v, __half& h, __half& l) {
    h = __float2half_rn(v);
    l = __float2half_rn(v - __half2float(h));
}

// ============================================================================
// FPS: one block per batch
// ============================================================================
__global__ void fps_kernel(const float* __restrict__ xyz, float* __restrict__ newxyz) {
    int b = blockIdx.x;
    int t = threadIdx.x;
    __shared__ float sx[KPTS], sy[KPTS], sz[KPTS];
    __shared__ float wv[8];
    __shared__ int   wi[8];
    __shared__ int   far_s;

    const float* p = xyz + (size_t)b * KPTS * 3;
    float px[8], py[8], pz[8], dist[8];
#pragma unroll
    for (int i = 0; i < 8; i++) {
        int j = i * 256 + t;
        px[i] = p[j * 3 + 0];
        py[i] = p[j * 3 + 1];
        pz[i] = p[j * 3 + 2];
        sx[j] = px[i]; sy[j] = py[i]; sz[j] = pz[i];
        dist[i] = 1e10f;
    }
    if (t == 0) far_s = 0;
    __syncthreads();

    for (int it = 0; it < NPROP; it++) {
        int far = far_s;
        if (t == 0) {
            float* o = newxyz + (size_t)(b * NPROP + it) * 3;
            o[0] = sx[far]; o[1] = sy[far]; o[2] = sz[far];
        }
        float cx = sx[far], cy = sy[far], cz = sz[far];
        float bv = -1.0f;
        int   bj = 0x7fffffff;
#pragma unroll
        for (int i = 0; i < 8; i++) {
            float dx = px[i] - cx, dy = py[i] - cy, dz = pz[i] - cz;
            float d = dx * dx + dy * dy + dz * dz;
            dist[i] = fminf(dist[i], d);
            int j = i * 256 + t;
            if (dist[i] > bv || (dist[i] == bv && j < bj)) { bv = dist[i]; bj = j; }
        }
#pragma unroll
        for (int off = 16; off; off >>= 1) {
            float ov = __shfl_down_sync(0xffffffffu, bv, off);
            int   oj = __shfl_down_sync(0xffffffffu, bj, off);
            if (ov > bv || (ov == bv && oj < bj)) { bv = ov; bj = oj; }
        }
        if ((t & 31) == 0) { wv[t >> 5] = bv; wi[t >> 5] = bj; }
        __syncthreads();
        if (t == 0) {
            float fv = wv[0]; int fj = wi[0];
#pragma unroll
            for (int w = 1; w < 8; w++) {
                if (wv[w] > fv || (wv[w] == fv && wi[w] < fj)) { fv = wv[w]; fj = wi[w]; }
            }
            far_s = fj;
        }
        __syncthreads();
    }
}

// ============================================================================
// Ball query: one warp per proposal
// ============================================================================
__global__ void ball_query_kernel(const float* __restrict__ xyz,
                                  const float* __restrict__ newxyz,
                                  int* __restrict__ ball) {
    int gwarp = (blockIdx.x * blockDim.x + threadIdx.x) >> 5;
    if (gwarp >= NP2) return;
    int lane = threadIdx.x & 31;
    int wl = threadIdx.x >> 5;
    int b = gwarp >> 8;

    __shared__ int slots[8][16];
    if (lane == 0) slots[wl][0] = 0;

    float cx = newxyz[gwarp * 3 + 0];
    float cy = newxyz[gwarp * 3 + 1];
    float cz = newxyz[gwarp * 3 + 2];
    const float* p = xyz + (size_t)b * KPTS * 3;

    int cnt = 0;
    for (int r = 0; r < KPTS / 32 && cnt < NSAMP; r++) {
        int j = r * 32 + lane;
        float dx = cx - p[j * 3 + 0];
        float dy = cy - p[j * 3 + 1];
        float dz = cz - p[j * 3 + 2];
        float d2 = dx * dx + dy * dy + dz * dz;
        bool pred = d2 < 0.09f;
        unsigned m = __ballot_sync(0xffffffffu, pred);
        int pos = cnt + __popc(m & ((1u << lane) - 1u));
        if (pred && pos < NSAMP) slots[wl][pos] = j;
        cnt += __popc(m);
    }
    __syncwarp();
    if (lane < NSAMP) {
        int first = slots[wl][0];
        int v = (lane < cnt) ? slots[wl][lane] : first;
        ball[gwarp * NSAMP + lane] = v;
    }
}

// ============================================================================
// Gathers (channel-major staging)
// ============================================================================
__global__ void gather_xyz_kernel(const float* __restrict__ xyz,
                                  const float* __restrict__ newxyz,
                                  const int* __restrict__ ball,
                                  float* __restrict__ G) {
    int n = blockIdx.x * blockDim.x + threadIdx.x;
    if (n >= NTOT) return;
    int bp = n >> 4;
    int b = bp >> 8;
    int j = ball[n];
    const float* pj = xyz + ((size_t)b * KPTS + j) * 3;
    const float* cen = newxyz + (size_t)bp * 3;
    G[0 * (size_t)NTOT + n] = (pj[0] - cen[0]) / 0.3f;
    G[1 * (size_t)NTOT + n] = (pj[1] - cen[1]) / 0.3f;
    G[2 * (size_t)NTOT + n] = (pj[2] - cen[2]) / 0.3f;
}

__global__ void gather_feat_kernel(const float* __restrict__ feat,
                                   const int* __restrict__ ball,
                                   float* __restrict__ G) {
    int bc = blockIdx.x;          // b * 256 + c
    int b = bc >> 8;
    int c = bc & 255;
    const float* f = feat + ((size_t)b * CFEAT + c) * KPTS;
    const int* bl = ball + (size_t)b * NPROP * NSAMP;
    float* dst = G + (size_t)(3 + c) * NTOT + (size_t)b * NPROP * NSAMP;
    for (int t = threadIdx.x; t < NPROP * NSAMP; t += blockDim.x)
        dst[t] = f[bl[t]];
}

// ============================================================================
// Transpose + split: G[k][NTOT] fp32 -> X0h/X0l [n][288] fp16
// ============================================================================
__global__ void transpose_split_kernel(const float* __restrict__ G,
                                       __half* __restrict__ Xh, __half* __restrict__ Xl) {
    __shared__ float tile[32][33];
    int n0 = blockIdx.x * 32;
    int k0 = blockIdx.y * 32;
    int tx = threadIdx.x, ty = threadIdx.y;   // (32, 8)
#pragma unroll
    for (int i = 0; i < 32; i += 8) {
        int k = k0 + ty + i;
        tile[ty + i][tx] = (k < 259) ? G[(size_t)k * NTOT + n0 + tx] : 0.f;
    }
    __syncthreads();
#pragma unroll
    for (int i = 0; i < 32; i += 8) {
        int n = n0 + ty + i;
        float v = tile[tx][ty + i];
        __half h, l;
        hsplit(v, h, l);
        Xh[(size_t)n * 288 + k0 + tx] = h;
        Xl[(size_t)n * 288 + k0 + tx] = l;
    }
}

// ============================================================================
// Weight split (+padding)
// ============================================================================
__global__ void split_w_kernel(const float* __restrict__ W,
                               __half* __restrict__ Wh, __half* __restrict__ Wl,
                               int rows_valid, int cols_valid, int cols_src,
                               int cols_dst, int total) {
    int idx = blockIdx.x * 256 + threadIdx.x;
    if (idx >= total) return;
    int r = idx / cols_dst, c = idx % cols_dst;
    float v = (r < rows_valid && c < cols_valid) ? W[(size_t)r * cols_src + c] : 0.f;
    __half h, l;
    hsplit(v, h, l);
    Wh[idx] = h;
    Wl[idx] = l;
}

// ============================================================================
// Big SA GEMM: CTA 128x256, 8 warps of 64x64, 3-stage cp.async, 1 sync/stage.
//   C[m][ch] = A[m][:KC] . B[ch][:KC], A=Ah+Al, B=Bh+Bl (fp16 split planes)
//   MODE 0: BN+ReLU -> split planes [n][256]
//   MODE 2: BN+ReLU + maxpool over 16 rows -> Y split planes [p][256]
// Stage layout (24576 B): Ah(4K) | Al(4K) | Bh(8K) | Bl(8K)
// ============================================================================
#define STAGE_B 24576

template <int MODE>
__global__ void __launch_bounds__(256, 1)
hgemm256_kernel(const __half* __restrict__ Ah, const __half* __restrict__ Al,
                const __half* __restrict__ Bh, const __half* __restrict__ Bl,
                int KC,
                __half* __restrict__ Ch, __half* __restrict__ Cl,
                const float* __restrict__ gamma, const float* __restrict__ beta,
                const float* __restrict__ mean, const float* __restrict__ var) {
    extern __shared__ __align__(16) uint8_t smem_dyn[];
    const uint32_t sbase = s2u(smem_dyn);
    const int tid  = threadIdx.x;
    const int lane = tid & 31;
    const int warp = tid >> 5;
    const int wm = warp & 1;        // 2 m-tiles of 64
    const int wn = warp >> 1;       // 4 n-tiles of 64
    const int m0 = blockIdx.x * 128;

    float acc[4][8][4];
#pragma unroll
    for (int i = 0; i < 4; i++)
#pragma unroll
        for (int j = 0; j < 8; j++)
#pragma unroll
            for (int q = 0; q < 4; q++) acc[i][j][q] = 0.f;

    const int nst = KC >> 4;

    // cp.async: 1536 x 16B per stage, 6 per thread
#define LOAD_STAGE(s)                                                            \
    {                                                                            \
        uint32_t base = sbase + ((s) % 3) * STAGE_B;                             \
        int k0 = (s) << 4;                                                       \
        _Pragma("unroll")                                                        \
        for (int q = 0; q < 6; q++) {                                            \
            int i = q * 256 + tid;                                               \
            const __half* src;                                                   \
            uint32_t dst;                                                        \
            if (i < 512) {                                                       \
                int pa = i >> 8, r = (i & 255) >> 1, cc = i & 1;                 \
                src = (pa ? Al : Ah) + (size_t)(m0 + r) * KC + k0 + cc * 8;      \
                dst = base + pa * 4096 + r * 32 + (((cc ^ (r >> 2)) & 1) << 4);  \
            } else {                                                             \
                int ib = i - 512;                                                \
                int pb = ib >> 9, r = (ib & 511) >> 1, cc = ib & 1;              \
                src = (pb ? Bl : Bh) + (size_t)r * KC + k0 + cc * 8;             \
                dst = base + 8192 + pb * 8192 + r * 32 +                         \
                      (((cc ^ (r >> 2)) & 1) << 4);                              \
            }                                                                    \
            cpasync16(dst, src);                                                 \
        }                                                                        \
        asm volatile("cp.async.commit_group;");                                  \
    }

    LOAD_STAGE(0);
    LOAD_STAGE(1);

    const int lrow = lane & 15, lc = lane >> 4;
    const int br = (lane & 7) + ((lane >> 4) & 1) * 8;
    const int bc = (lane >> 3) & 1;

    for (int s = 0; s < nst; s++) {
        if (s + 1 < nst) asm volatile("cp.async.wait_group 1;");
        else             asm volatile("cp.async.wait_group 0;");
        __syncthreads();
        if (s + 2 < nst) LOAD_STAGE(s + 2);

        uint32_t base = sbase + (s % 3) * STAGE_B;
        uint32_t baseB = base + 8192;

        uint32_t ah[4][4];
#pragma unroll
        for (int i = 0; i < 4; i++) {
            int r = wm * 64 + i * 16 + lrow;
            ldsm4(ah[i], base + r * 32 + (((lc ^ (r >> 2)) & 1) << 4));
        }
        uint32_t bh[4][4];
#pragma unroll
        for (int jj = 0; jj < 4; jj++) {
            int r = wn * 64 + jj * 16 + br;
            ldsm4(bh[jj], baseB + r * 32 + (((bc ^ (r >> 2)) & 1) << 4));
        }
        // main: Ah . Bh
#pragma unroll
        for (int jj = 0; jj < 4; jj++)
#pragma unroll
            for (int j2 = 0; j2 < 2; j2++)
#pragma unroll
                for (int i = 0; i < 4; i++)
                    mma16816(acc[i][jj * 2 + j2], ah[i], bh[jj] + j2 * 2);

        // corr 1: Ah . Bl
        {
            uint32_t bl4[4][4];
#pragma unroll
            for (int jj = 0; jj < 4; jj++) {
                int r = wn * 64 + jj * 16 + br;
                ldsm4(bl4[jj], baseB + 8192 + r * 32 + (((bc ^ (r >> 2)) & 1) << 4));
            }
#pragma unroll
            for (int jj = 0; jj < 4; jj++)
#pragma unroll
                for (int j2 = 0; j2 < 2; j2++)
#pragma unroll
                    for (int i = 0; i < 4; i++)
                        mma16816(acc[i][jj * 2 + j2], ah[i], bl4[jj] + j2 * 2);
        }
        // corr 2: Al . Bh
        {
            uint32_t al4[4][4];
#pragma unroll
            for (int i = 0; i < 4; i++) {
                int r = wm * 64 + i * 16 + lrow;
                ldsm4(al4[i], base + 4096 + r * 32 + (((lc ^ (r >> 2)) & 1) << 4));
            }
#pragma unroll
            for (int jj = 0; jj < 4; jj++)
#pragma unroll
                for (int j2 = 0; j2 < 2; j2++)
#pragma unroll
                    for (int i = 0; i < 4; i++)
                        mma16816(acc[i][jj * 2 + j2], al4[i], bh[jj] + j2 * 2);
        }
    }

    // ---- epilogue ----
    const int colq = (lane & 3) * 2;
    const int rhalf = lane >> 2;
#pragma unroll
    for (int j = 0; j < 8; j++) {
        int ch = wn * 64 + j * 8 + colq;
        float s0 = __ldg(gamma + ch) * rsqrtf(__ldg(var + ch) + 1e-5f);
        float sh0 = __ldg(beta + ch) - __ldg(mean + ch) * s0;
        float s1 = __ldg(gamma + ch + 1) * rsqrtf(__ldg(var + ch + 1) + 1e-5f);
        float sh1 = __ldg(beta + ch + 1) - __ldg(mean + ch + 1) * s1;
#pragma unroll
        for (int i = 0; i < 4; i++) {
            if (MODE == 0) {
                int r0 = m0 + wm * 64 + i * 16 + rhalf;
#pragma unroll
                for (int hh = 0; hh < 2; hh++) {
                    int r = r0 + hh * 8;
                    float v0 = fmaxf(acc[i][j][hh * 2 + 0] * s0 + sh0, 0.f);
                    float v1 = fmaxf(acc[i][j][hh * 2 + 1] * s1 + sh1, 0.f);
                    __half h0, l0, h1, l1;
                    hsplit(v0, h0, l0);
                    hsplit(v1, h1, l1);
                    *(__half2*)(Ch + (size_t)r * 256 + ch) = __halves2half2(h0, h1);
                    *(__half2*)(Cl + (size_t)r * 256 + ch) = __halves2half2(l0, l1);
                }
            } else {
                // fused 16-row maxpool: frag i covers one whole proposal
                float m0v = fmaxf(fmaxf(acc[i][j][0], acc[i][j][2]) * s0 + sh0, 0.f);
                float m1v = fmaxf(fmaxf(acc[i][j][1], acc[i][j][3]) * s1 + sh1, 0.f);
                // reduce over the 8 row-groups (lane bits 2..4)
#pragma unroll
                for (int off = 4; off <= 16; off <<= 1) {
                    m0v = fmaxf(m0v, __shfl_xor_sync(0xffffffffu, m0v, off));
                    m1v = fmaxf(m1v, __shfl_xor_sync(0xffffffffu, m1v, off));
                }
                if (rhalf == 0) {
                    int p = (m0 + wm * 64 + i * 16) >> 4;
                    __half h0, l0, h1, l1;
                    hsplit(m0v, h0, l0);
                    hsplit(m1v, h1, l1);
                    *(__half2*)(Ch + (size_t)p * 256 + ch) = __halves2half2(h0, h1);
                    *(__half2*)(Cl + (size_t)p * 256 + ch) = __halves2half2(l0, l1);
                }
            }
        }
    }
#undef LOAD_STAGE
}

// ============================================================================
// Small GEMM for proposal head (R8 kernel, known-good)
//   MODE 0: BN+ReLU split planes;  MODE 1: +bias, fp32 out
// ============================================================================
template <int MODE>
__global__ void __launch_bounds__(256, 2)
hgemm_kernel(const __half* __restrict__ Ah, const __half* __restrict__ Al,
             const __half* __restrict__ Bh, const __half* __restrict__ Bl,
             int KC, int ldC,
             __half* __restrict__ Ch, __half* __restrict__ Cl,
             float* __restrict__ Cf,
             const float* __restrict__ gamma, const float* __restrict__ beta,
             const float* __restrict__ mean, const float* __restrict__ var,
             const float* __restrict__ bias) {
    __shared__ __align__(16) uint8_t smem[2][16384];
    const int tid  = threadIdx.x;
    const int lane = tid & 31;
    const int warp = tid >> 5;
    const int wm = warp & 1;
    const int wn = warp >> 1;
    const int m0 = blockIdx.x * 128;
    const int n0 = blockIdx.y * 128;

    const uint32_t sb[2] = { s2u(smem[0]), s2u(smem[1]) };

    float acc[4][4][4];
#pragma unroll
    for (int i = 0; i < 4; i++)
#pragma unroll
        for (int j = 0; j < 4; j++)
#pragma unroll
            for (int q = 0; q < 4; q++) acc[i][j][q] = 0.f;

    const int plane = tid >> 6;
    const int idx0 = (tid & 63) * 4;
    const __half* gplane = (plane == 0) ? Ah : (plane == 1) ? Al : (plane == 2) ? Bh : Bl;
    const int rbase = (plane < 2) ? m0 : n0;
    const uint32_t pl_off = plane * 4096;

    const int nst = KC >> 4;

#define LOAD_STAGE(s)                                                          \
    {                                                                          \
        uint32_t base = sb[(s) & 1] + pl_off;                                  \
        int k0 = (s) << 4;                                                     \
        _Pragma("unroll")                                                      \
        for (int t4 = 0; t4 < 4; t4++) {                                       \
            int idx = idx0 + t4;                                               \
            int row = idx >> 1, cc = idx & 1;                                  \
            uint32_t sa = base + row * 32 + (((cc ^ (row >> 2)) & 1) << 4);    \
            cpasync16(sa, gplane + (size_t)(rbase + row) * KC + k0 + cc * 8);  \
        }                                                                      \
        asm volatile("cp.async.commit_group;");                                \
    }

    LOAD_STAGE(0);

    const int lrow = lane & 15, lc = lane >> 4;
    const int br = (lane & 7) + ((lane >> 4) & 1) * 8;
    const int bc = (lane >> 3) & 1;

    for (int s = 0; s < nst; s++) {
        if (s + 1 < nst) {
            LOAD_STAGE(s + 1);
            asm volatile("cp.async.wait_group 1;");
        } else {
            asm volatile("cp.async.wait_group 0;");
        }
        __syncthreads();

        uint32_t base = sb[s & 1];
        uint32_t ah[4][4], al[4][4];
#pragma unroll
        for (int i = 0; i < 4; i++) {
            int r = wm * 64 + i * 16 + lrow;
            uint32_t a = base + r * 32 + (((lc ^ (r >> 2)) & 1) << 4);
            ldsm4(ah[i], a);
            ldsm4(al[i], a + 4096);
        }
#pragma unroll
        for (int jj = 0; jj < 2; jj++) {
            int r = wn * 32 + jj * 16 + br;
            uint32_t boff = base + 8192 + r * 32 + (((bc ^ (r >> 2)) & 1) << 4);
            uint32_t bh4[4], bl4[4];
            ldsm4(bh4, boff);
            ldsm4(bl4, boff + 4096);
#pragma unroll
            for (int j2 = 0; j2 < 2; j2++) {
                const uint32_t* bhf = bh4 + j2 * 2;
                const uint32_t* blf = bl4 + j2 * 2;
#pragma unroll
                for (int i = 0; i < 4; i++) {
                    float* c = acc[i][jj * 2 + j2];
                    mma16816(c, ah[i], bhf);
                    mma16816(c, ah[i], blf);
                    mma16816(c, al[i], bhf);
                }
            }
        }
        __syncthreads();
    }

    const int colq = (lane & 3) * 2;
    const int rhalf = lane >> 2;
#pragma unroll
    for (int j = 0; j < 4; j++) {
        int ch = n0 + wn * 32 + j * 8 + colq;
        float sc0 = 1.f, sh0 = 0.f, sc1 = 1.f, sh1 = 0.f;
        if (MODE == 0) {
            float s0 = __ldg(gamma + ch) * rsqrtf(__ldg(var + ch) + 1e-5f);
            sc0 = s0; sh0 = __ldg(beta + ch) - __ldg(mean + ch) * s0;
            float s1 = __ldg(gamma + ch + 1) * rsqrtf(__ldg(var + ch + 1) + 1e-5f);
            sc1 = s1; sh1 = __ldg(beta + ch + 1) - __ldg(mean + ch + 1) * s1;
        } else {
            sh0 = (ch < OUTD) ? __ldg(bias + ch) : 0.f;
            sh1 = (ch + 1 < OUTD) ? __ldg(bias + ch + 1) : 0.f;
        }
#pragma unroll
        for (int i = 0; i < 4; i++) {
            int r0 = m0 + wm * 64 + i * 16 + rhalf;
#pragma unroll
            for (int hh = 0; hh < 2; hh++) {
                int r = r0 + hh * 8;
                float v0 = acc[i][j][hh * 2 + 0];
                float v1 = acc[i][j][hh * 2 + 1];
                if (MODE == 0) {
                    v0 = fmaxf(v0 * sc0 + sh0, 0.f);
                    v1 = fmaxf(v1 * sc1 + sh1, 0.f);
                    __half h0, l0, h1, l1;
                    hsplit(v0, h0, l0);
                    hsplit(v1, h1, l1);
                    *(__half2*)(Ch + (size_t)r * ldC + ch) = __halves2half2(h0, h1);
                    *(__half2*)(Cl + (size_t)r * ldC + ch) = __halves2half2(l0, l1);
                } else {
                    Cf[(size_t)r * ldC + ch]     = v0 + sh0;
                    Cf[(size_t)r * ldC + ch + 1] = v1 + sh1;
                }
            }
        }
    }
#undef LOAD_STAGE
}

// ============================================================================
// Finalize (net layout [p][128])
// ============================================================================
__global__ void finalize_kernel(const float* __restrict__ net,
                                const float* __restrict__ newxyz,
                                const float* __restrict__ msz,
                                float* __restrict__ out) {
    int n = blockIdx.x * blockDim.x + threadIdx.x;
    if (n >= NP2) return;
#define NET(o) net[(size_t)n * 128 + (o)]

    float obj0 = NET(0), obj1 = NET(1);
    out[OFF_OBJ + n * 2 + 0] = obj0;
    out[OFF_OBJ + n * 2 + 1] = obj1;

    float cx = newxyz[n * 3 + 0] + NET(2);
    float cy = newxyz[n * 3 + 1] + NET(3);
    float cz = newxyz[n * 3 + 2] + NET(4);
    out[OFF_CEN + n * 3 + 0] = cx;
    out[OFF_CEN + n * 3 + 1] = cy;
    out[OFF_CEN + n * 3 + 2] = cz;

    int best = 0;
    float bv = NET(29);
    out[OFF_SS + n * 18 + 0] = bv;
#pragma unroll
    for (int sc = 1; sc < 18; sc++) {
        float v = NET(29 + sc);
        out[OFF_SS + n * 18 + sc] = v;
        if (v > bv) { bv = v; best = sc; }
    }

#pragma unroll
    for (int sc = 0; sc < 18; sc++) {
#pragma unroll
        for (int d = 0; d < 3; d++) {
            float sres = NET(47 + sc * 3 + d) * msz[sc * 3 + d];
            out[OFF_SRES + ((size_t)n * 18 + sc) * 3 + d] = sres;
        }
    }

    float ps[3];
#pragma unroll
    for (int d = 0; d < 3; d++) {
        float m = msz[best * 3 + d];
        ps[d] = NET(47 + best * 3 + d) * m + m;
        out[OFF_PSZ + n * 3 + d] = ps[d];
    }

    float sem[18];
#pragma unroll
    for (int s = 0; s < 18; s++) {
        sem[s] = NET(101 + s);
        out[OFF_SEM + n * 18 + s] = sem[s];
    }

    const float sxA[8] = {1, 1, -1, -1, 1, 1, -1, -1};
    const float syA[8] = {1, 1, 1, 1, -1, -1, -1, -1};
    const float szA[8] = {1, -1, -1, 1, 1, -1, -1, 1};
    float c0 = cx, c1 = cz, c2 = -cy;
#pragma unroll
    for (int k = 0; k < 8; k++) {
        out[OFF_CORN + ((size_t)n * 8 + k) * 3 + 0] = ps[0] * sxA[k] * 0.5f + c0;
        out[OFF_CORN + ((size_t)n * 8 + k) * 3 + 1] = ps[2] * syA[k] * 0.5f + c1;
        out[OFF_CORN + ((size_t)n * 8 + k) * 3 + 2] = ps[1] * szA[k] * 0.5f + c2;
    }

#pragma unroll
    for (int s = 0; s < 18; s++) out[OFF_SLOG + n * 19 + s] = sem[s];
    out[OFF_SLOG + n * 19 + 18] = (obj0 <= obj1) ? 0.0f : 1e10f;

    {
        float m = fmaxf(obj0, obj1);
        float e0 = expf(obj0 - m), e1 = expf(obj1 - m);
        out[OFF_OPROB + n] = e1 / (e0 + e1);
    }
    {
        float m = sem[0];
#pragma unroll
        for (int s = 1; s < 18; s++) m = fmaxf(m, sem[s]);
        float sum = 0.f;
        float e[18];
#pragma unroll
        for (int s = 0; s < 18; s++) { e[s] = expf(sem[s] - m); sum += e[s]; }
        float inv = 1.0f / sum;
#pragma unroll
        for (int s = 0; s < 18; s++) out[OFF_SPROB + n * 18 + s] = e[s] * inv;
    }
#undef NET
}

// ============================================================================
// launch
// ============================================================================
extern "C" void kernel_launch(void* const* d_in, const int* in_sizes, int n_in,
                              void* d_out, int out_size) {
    const float* xyz      = (const float*)d_in[0];
    const float* features = (const float*)d_in[1];
    const float* sa_w1    = (const float*)d_in[2];
    const float* sa_w2    = (const float*)d_in[3];
    const float* sa_w3    = (const float*)d_in[4];
    const float* sa_gamma = (const float*)d_in[5];
    const float* sa_beta  = (const float*)d_in[6];
    const float* sa_mean  = (const float*)d_in[7];
    const float* sa_var   = (const float*)d_in[8];
    const float* p_w1     = (const float*)d_in[9];
    const float* p_w2     = (const float*)d_in[10];
    const float* p_w3     = (const float*)d_in[11];
    const float* p_b3     = (const float*)d_in[12];
    const float* p_gamma  = (const float*)d_in[13];
    const float* p_beta   = (const float*)d_in[14];
    const float* p_mean   = (const float*)d_in[15];
    const float* p_var    = (const float*)d_in[16];
    const float* msz      = (const float*)d_in[17];
    float* out = (float*)d_out;

    float *G, *net, *newxyz;
    int* ball;
    __half *X0h, *X0l, *X1h, *X1l, *X2h, *X2l;
    __half *Yh, *Yl, *Y1h, *Y1l, *Y2h, *Y2l;
    __half *W1h, *W1l, *W2h, *W2l, *W3h, *W3l, *P1h, *P1l, *P2h, *P2l, *P3h, *P3l;
    cudaGetSymbolAddress((void**)&G,   g_G);
    cudaGetSymbolAddress((void**)&net, g_net);
    cudaGetSymbolAddress((void**)&newxyz, g_newxyz);
    cudaGetSymbolAddress((void**)&ball, g_ball);
    cudaGetSymbolAddress((void**)&X0h, g_X0h); cudaGetSymbolAddress((void**)&X0l, g_X0l);
    cudaGetSymbolAddress((void**)&X1h, g_X1h); cudaGetSymbolAddress((void**)&X1l, g_X1l);
    cudaGetSymbolAddress((void**)&X2h, g_X2h); cudaGetSymbolAddress((void**)&X2l, g_X2l);
    cudaGetSymbolAddress((void**)&Yh,  g_Yh);  cudaGetSymbolAddress((void**)&Yl,  g_Yl);
    cudaGetSymbolAddress((void**)&Y1h, g_Y1h); cudaGetSymbolAddress((void**)&Y1l, g_Y1l);
    cudaGetSymbolAddress((void**)&Y2h, g_Y2h); cudaGetSymbolAddress((void**)&Y2l, g_Y2l);
    cudaGetSymbolAddress((void**)&W1h, g_W1h); cudaGetSymbolAddress((void**)&W1l, g_W1l);
    cudaGetSymbolAddress((void**)&W2h, g_W2h); cudaGetSymbolAddress((void**)&W2l, g_W2l);
    cudaGetSymbolAddress((void**)&W3h, g_W3h); cudaGetSymbolAddress((void**)&W3l, g_W3l);
    cudaGetSymbolAddress((void**)&P1h, g_P1h); cudaGetSymbolAddress((void**)&P1l, g_P1l);
    cudaGetSymbolAddress((void**)&P2h, g_P2h); cudaGetSymbolAddress((void**)&P2l, g_P2l);
    cudaGetSymbolAddress((void**)&P3h, g_P3h); cudaGetSymbolAddress((void**)&P3l, g_P3l);

    const int DYN = 3 * STAGE_B;   // 73728
    cudaFuncSetAttribute(hgemm256_kernel<0>, cudaFuncAttributeMaxDynamicSharedMemorySize, DYN);
    cudaFuncSetAttribute(hgemm256_kernel<2>, cudaFuncAttributeMaxDynamicSharedMemorySize, DYN);

    fps_kernel<<<BATCH, 256>>>(xyz, newxyz);
    ball_query_kernel<<<NP2 * 32 / 256, 256>>>(xyz, newxyz, ball);
    gather_xyz_kernel<<<NTOT / 256, 256>>>(xyz, newxyz, ball, G);
    gather_feat_kernel<<<BATCH * CFEAT, 256>>>(features, ball, G);

    split_w_kernel<<<(256 * 288 + 255) / 256, 256>>>(sa_w1, W1h, W1l, 256, 259, 259, 288, 256 * 288);
    split_w_kernel<<<256, 256>>>(sa_w2, W2h, W2l, 256, 256, 256, 256, 256 * 256);
    split_w_kernel<<<256, 256>>>(sa_w3, W3h, W3l, 256, 256, 256, 256, 256 * 256);
    split_w_kernel<<<256, 256>>>(p_w1, P1h, P1l, 256, 256, 256, 256, 256 * 256);
    split_w_kernel<<<256, 256>>>(p_w2, P2h, P2l, 256, 256, 256, 256, 256 * 256);
    split_w_kernel<<<128, 256>>>(p_w3, P3h, P3l, OUTD, 256, 256, 256, 128 * 256);

    transpose_split_kernel<<<dim3(NTOT / 32, 288 / 32), dim3(32, 8)>>>(G, X0h, X0l);

    hgemm256_kernel<0><<<NTOT / 128, 256, DYN>>>(X0h, X0l, W1h, W1l, 288, X1h, X1l,
        sa_gamma + 0,   sa_beta + 0,   sa_mean + 0,   sa_var + 0);
    hgemm256_kernel<0><<<NTOT / 128, 256, DYN>>>(X1h, X1l, W2h, W2l, 256, X2h, X2l,
        sa_gamma + 256, sa_beta + 256, sa_mean + 256, sa_var + 256);
    hgemm256_kernel<2><<<NTOT / 128, 256, DYN>>>(X2h, X2l, W3h, W3l, 256, Yh, Yl,
        sa_gamma + 512, sa_beta + 512, sa_mean + 512, sa_var + 512);

    dim3 gP(NP2 / 128, 2);
    hgemm_kernel<0><<<gP, 256>>>(Yh, Yl, P1h, P1l, 256, 256, Y1h, Y1l, nullptr,
                                 p_gamma + 0,   p_beta + 0,   p_mean + 0,   p_var + 0,   nullptr);
    hgemm_kernel<0><<<gP, 256>>>(Y1h, Y1l, P2h, P2l, 256, 256, Y2h, Y2l, nullptr,
                                 p_gamma + 256, p_beta + 256, p_mean + 256, p_var + 256, nullptr);
    dim3 gH(NP2 / 128, 1);
    hgemm_kernel<1><<<gH, 256>>>(Y2h, Y2l, P3h, P3l, 256, 128, nullptr, nullptr, net,
                                 nullptr, nullptr, nullptr, nullptr, p_b3);

    finalize_kernel<<<NP2 / 256, 256>>>(net, newxyz, msz, out);
}

// round 11
// speedup vs baseline: 2.2796x; 1.1496x over previous
#include <cuda_runtime.h>
#include <cuda_fp16.h>
#include <cstdint>

#define BATCH 32
#define KPTS 2048
#define CFEAT 256
#define NPROP 256
#define NSAMP 16
#define NTOT (BATCH * NPROP * NSAMP)   // 131072
#define NP2  (BATCH * NPROP)           // 8192
#define OUTD 119

// ---------------- scratch (static device memory) ----------------------------
__device__ float  g_G  [259 * NTOT];                       // channel-major gather staging
__device__ __align__(128) __half g_X0h[(size_t)NTOT * 288];
__device__ __align__(128) __half g_X0l[(size_t)NTOT * 288];
__device__ __align__(128) __half g_Yh [NP2 * 256];
__device__ __align__(128) __half g_Yl [NP2 * 256];
__device__ __align__(128) __half g_Y1h[NP2 * 256];
__device__ __align__(128) __half g_Y1l[NP2 * 256];
__device__ __align__(128) __half g_Y2h[NP2 * 256];
__device__ __align__(128) __half g_Y2l[NP2 * 256];
__device__ float  g_net[NP2 * 128];
__device__ __align__(128) __half g_W1h[256 * 288];
__device__ __align__(128) __half g_W1l[256 * 288];
__device__ __align__(128) __half g_W2h[256 * 256];
__device__ __align__(128) __half g_W2l[256 * 256];
__device__ __align__(128) __half g_W3h[256 * 256];
__device__ __align__(128) __half g_W3l[256 * 256];
__device__ __align__(128) __half g_P1h[256 * 256];
__device__ __align__(128) __half g_P1l[256 * 256];
__device__ __align__(128) __half g_P2h[256 * 256];
__device__ __align__(128) __half g_P2l[256 * 256];
__device__ __align__(128) __half g_P3h[128 * 256];
__device__ __align__(128) __half g_P3l[128 * 256];
__device__ float  g_newxyz[NP2 * 3];
__device__ int    g_ball[NP2 * NSAMP];

// ---------------- output offsets (floats) -----------------------------------
#define OFF_OBJ   0
#define OFF_CEN   16384
#define OFF_SS    40960
#define OFF_SRES  188416
#define OFF_PSZ   630784
#define OFF_SEM   655360
#define OFF_CORN  802816
#define OFF_SLOG  999424
#define OFF_OPROB 1155072
#define OFF_SPROB 1163264

// ---------------- helpers ----------------------------------------------------
__device__ __forceinline__ uint32_t s2u(const void* p) {
    uint32_t a;
    asm("{ .reg .u64 t; cvta.to.shared.u64 t, %1; cvt.u32.u64 %0, t; }" : "=r"(a) : "l"(p));
    return a;
}
__device__ __forceinline__ void ldsm4(uint32_t* r, uint32_t a) {
    asm volatile("ldmatrix.sync.aligned.m8n8.x4.shared.b16 {%0,%1,%2,%3}, [%4];"
                 : "=r"(r[0]), "=r"(r[1]), "=r"(r[2]), "=r"(r[3]) : "r"(a));
}
__device__ __forceinline__ void mma16816(float* c, const uint32_t* a, const uint32_t* b) {
    asm volatile(
        "mma.sync.aligned.m16n8k16.row.col.f32.f16.f16.f32 "
        "{%0,%1,%2,%3}, {%4,%5,%6,%7}, {%8,%9}, {%0,%1,%2,%3};"
        : "+f"(c[0]), "+f"(c[1]), "+f"(c[2]), "+f"(c[3])
        : "r"(a[0]), "r"(a[1]), "r"(a[2]), "r"(a[3]), "r"(b[0]), "r"(b[1]));
}
__device__ __forceinline__ void cpasync16(uint32_t sa, const void* g) {
    asm volatile("cp.async.cg.shared.global [%0], [%1], 16;" :: "r"(sa), "l"(g));
}
__device__ __forceinline__ void hsplit(float v, __half& h, __half& l) {
    h = __float2half_rn(v);
    l = __float2half_rn(v - __half2float(h));
}

// ============================================================================
// FPS
// ============================================================================
__global__ void fps_kernel(const float* __restrict__ xyz, float* __restrict__ newxyz) {
    int b = blockIdx.x;
    int t = threadIdx.x;
    __shared__ float sx[KPTS], sy[KPTS], sz[KPTS];
    __shared__ float wv[8];
    __shared__ int   wi[8];
    __shared__ int   far_s;

    const float* p = xyz + (size_t)b * KPTS * 3;
    float px[8], py[8], pz[8], dist[8];
#pragma unroll
    for (int i = 0; i < 8; i++) {
        int j = i * 256 + t;
        px[i] = p[j * 3 + 0];
        py[i] = p[j * 3 + 1];
        pz[i] = p[j * 3 + 2];
        sx[j] = px[i]; sy[j] = py[i]; sz[j] = pz[i];
        dist[i] = 1e10f;
    }
    if (t == 0) far_s = 0;
    __syncthreads();

    for (int it = 0; it < NPROP; it++) {
        int far = far_s;
        if (t == 0) {
            float* o = newxyz + (size_t)(b * NPROP + it) * 3;
            o[0] = sx[far]; o[1] = sy[far]; o[2] = sz[far];
        }
        float cx = sx[far], cy = sy[far], cz = sz[far];
        float bv = -1.0f;
        int   bj = 0x7fffffff;
#pragma unroll
        for (int i = 0; i < 8; i++) {
            float dx = px[i] - cx, dy = py[i] - cy, dz = pz[i] - cz;
            float d = dx * dx + dy * dy + dz * dz;
            dist[i] = fminf(dist[i], d);
            int j = i * 256 + t;
            if (dist[i] > bv || (dist[i] == bv && j < bj)) { bv = dist[i]; bj = j; }
        }
#pragma unroll
        for (int off = 16; off; off >>= 1) {
            float ov = __shfl_down_sync(0xffffffffu, bv, off);
            int   oj = __shfl_down_sync(0xffffffffu, bj, off);
            if (ov > bv || (ov == bv && oj < bj)) { bv = ov; bj = oj; }
        }
        if ((t & 31) == 0) { wv[t >> 5] = bv; wi[t >> 5] = bj; }
        __syncthreads();
        if (t == 0) {
            float fv = wv[0]; int fj = wi[0];
#pragma unroll
            for (int w = 1; w < 8; w++) {
                if (wv[w] > fv || (wv[w] == fv && wi[w] < fj)) { fv = wv[w]; fj = wi[w]; }
            }
            far_s = fj;
        }
        __syncthreads();
    }
}

// ============================================================================
// Ball query
// ============================================================================
__global__ void ball_query_kernel(const float* __restrict__ xyz,
                                  const float* __restrict__ newxyz,
                                  int* __restrict__ ball) {
    int gwarp = (blockIdx.x * blockDim.x + threadIdx.x) >> 5;
    if (gwarp >= NP2) return;
    int lane = threadIdx.x & 31;
    int wl = threadIdx.x >> 5;
    int b = gwarp >> 8;

    __shared__ int slots[8][16];
    if (lane == 0) slots[wl][0] = 0;

    float cx = newxyz[gwarp * 3 + 0];
    float cy = newxyz[gwarp * 3 + 1];
    float cz = newxyz[gwarp * 3 + 2];
    const float* p = xyz + (size_t)b * KPTS * 3;

    int cnt = 0;
    for (int r = 0; r < KPTS / 32 && cnt < NSAMP; r++) {
        int j = r * 32 + lane;
        float dx = cx - p[j * 3 + 0];
        float dy = cy - p[j * 3 + 1];
        float dz = cz - p[j * 3 + 2];
        float d2 = dx * dx + dy * dy + dz * dz;
        bool pred = d2 < 0.09f;
        unsigned m = __ballot_sync(0xffffffffu, pred);
        int pos = cnt + __popc(m & ((1u << lane) - 1u));
        if (pred && pos < NSAMP) slots[wl][pos] = j;
        cnt += __popc(m);
    }
    __syncwarp();
    if (lane < NSAMP) {
        int first = slots[wl][0];
        int v = (lane < cnt) ? slots[wl][lane] : first;
        ball[gwarp * NSAMP + lane] = v;
    }
}

// ============================================================================
// Gathers (channel-major staging)
// ============================================================================
__global__ void gather_xyz_kernel(const float* __restrict__ xyz,
                                  const float* __restrict__ newxyz,
                                  const int* __restrict__ ball,
                                  float* __restrict__ G) {
    int n = blockIdx.x * blockDim.x + threadIdx.x;
    if (n >= NTOT) return;
    int bp = n >> 4;
    int b = bp >> 8;
    int j = ball[n];
    const float* pj = xyz + ((size_t)b * KPTS + j) * 3;
    const float* cen = newxyz + (size_t)bp * 3;
    G[0 * (size_t)NTOT + n] = (pj[0] - cen[0]) / 0.3f;
    G[1 * (size_t)NTOT + n] = (pj[1] - cen[1]) / 0.3f;
    G[2 * (size_t)NTOT + n] = (pj[2] - cen[2]) / 0.3f;
}

__global__ void gather_feat_kernel(const float* __restrict__ feat,
                                   const int* __restrict__ ball,
                                   float* __restrict__ G) {
    int bc = blockIdx.x;          // b * 256 + c
    int b = bc >> 8;
    int c = bc & 255;
    const float* f = feat + ((size_t)b * CFEAT + c) * KPTS;
    const int* bl = ball + (size_t)b * NPROP * NSAMP;
    float* dst = G + (size_t)(3 + c) * NTOT + (size_t)b * NPROP * NSAMP;
    for (int t = threadIdx.x; t < NPROP * NSAMP; t += blockDim.x)
        dst[t] = f[bl[t]];
}

// ============================================================================
// Transpose + split: G[k][NTOT] fp32 -> X0h/X0l [n][288] fp16
// ============================================================================
__global__ void transpose_split_kernel(const float* __restrict__ G,
                                       __half* __restrict__ Xh, __half* __restrict__ Xl) {
    __shared__ float tile[32][33];
    int n0 = blockIdx.x * 32;
    int k0 = blockIdx.y * 32;
    int tx = threadIdx.x, ty = threadIdx.y;   // (32, 8)
#pragma unroll
    for (int i = 0; i < 32; i += 8) {
        int k = k0 + ty + i;
        tile[ty + i][tx] = (k < 259) ? G[(size_t)k * NTOT + n0 + tx] : 0.f;
    }
    __syncthreads();
#pragma unroll
    for (int i = 0; i < 32; i += 8) {
        int n = n0 + ty + i;
        float v = tile[tx][ty + i];
        __half h, l;
        hsplit(v, h, l);
        Xh[(size_t)n * 288 + k0 + tx] = h;
        Xl[(size_t)n * 288 + k0 + tx] = l;
    }
}

// ============================================================================
// Weight split (+padding)
// ============================================================================
__global__ void split_w_kernel(const float* __restrict__ W,
                               __half* __restrict__ Wh, __half* __restrict__ Wl,
                               int rows_valid, int cols_valid, int cols_src,
                               int cols_dst, int total) {
    int idx = blockIdx.x * 256 + threadIdx.x;
    if (idx >= total) return;
    int r = idx / cols_dst, c = idx % cols_dst;
    float v = (r < rows_valid && c < cols_valid) ? W[(size_t)r * cols_src + c] : 0.f;
    __half h, l;
    hsplit(v, h, l);
    Wh[idx] = h;
    Wl[idx] = l;
}

// ============================================================================
// Shared GEMM building blocks (128x256 CTA tile, 8 warps of 64x64)
// ============================================================================
#define ABUF_B   131072    // 16 k-stages x 8192 (hi 4K | lo 4K)
#define STAGE_B  24576     // phase-1 A+B stage
#define BSTAGE_B 16384     // B-only stage

__device__ __forceinline__ void compute_stage(
    float acc[4][8][4], uint32_t aH, uint32_t aL, uint32_t bH, uint32_t bL,
    int wm, int wn, int lane) {
    const int lrow = lane & 15, lc = lane >> 4;
    const int br = (lane & 7) + ((lane >> 4) & 1) * 8;
    const int bc = (lane >> 3) & 1;
    uint32_t ah[4][4];
#pragma unroll
    for (int i = 0; i < 4; i++) {
        int r = wm * 64 + i * 16 + lrow;
        ldsm4(ah[i], aH + r * 32 + (((lc ^ (r >> 2)) & 1) << 4));
    }
    uint32_t bh[4][4];
#pragma unroll
    for (int jj = 0; jj < 4; jj++) {
        int r = wn * 64 + jj * 16 + br;
        ldsm4(bh[jj], bH + r * 32 + (((bc ^ (r >> 2)) & 1) << 4));
    }
#pragma unroll
    for (int jj = 0; jj < 4; jj++)
#pragma unroll
        for (int j2 = 0; j2 < 2; j2++)
#pragma unroll
            for (int i = 0; i < 4; i++)
                mma16816(acc[i][jj * 2 + j2], ah[i], bh[jj] + j2 * 2);
    {
        uint32_t bl4[4][4];
#pragma unroll
        for (int jj = 0; jj < 4; jj++) {
            int r = wn * 64 + jj * 16 + br;
            ldsm4(bl4[jj], bL + r * 32 + (((bc ^ (r >> 2)) & 1) << 4));
        }
#pragma unroll
        for (int jj = 0; jj < 4; jj++)
#pragma unroll
            for (int j2 = 0; j2 < 2; j2++)
#pragma unroll
                for (int i = 0; i < 4; i++)
                    mma16816(acc[i][jj * 2 + j2], ah[i], bl4[jj] + j2 * 2);
    }
    {
        uint32_t al4[4][4];
#pragma unroll
        for (int i = 0; i < 4; i++) {
            int r = wm * 64 + i * 16 + lrow;
            ldsm4(al4[i], aL + r * 32 + (((lc ^ (r >> 2)) & 1) << 4));
        }
#pragma unroll
        for (int jj = 0; jj < 4; jj++)
#pragma unroll
            for (int j2 = 0; j2 < 2; j2++)
#pragma unroll
                for (int i = 0; i < 4; i++)
                    mma16816(acc[i][jj * 2 + j2], al4[i], bh[jj] + j2 * 2);
    }
}

// BN+ReLU epilogue -> SMEM A-buffer (per-stage swizzled fp16 split layout)
__device__ __forceinline__ void epi_to_abuf(
    float acc[4][8][4], uint8_t* smem, int wm, int wn, int lane,
    const float* __restrict__ gamma, const float* __restrict__ beta,
    const float* __restrict__ mean, const float* __restrict__ var) {
    const int colq = (lane & 3) * 2;
    const int rhalf = lane >> 2;
#pragma unroll
    for (int j = 0; j < 8; j++) {
        int ch = wn * 64 + j * 8 + colq;
        float s0 = __ldg(gamma + ch) * rsqrtf(__ldg(var + ch) + 1e-5f);
        float sh0 = __ldg(beta + ch) - __ldg(mean + ch) * s0;
        float s1 = __ldg(gamma + ch + 1) * rsqrtf(__ldg(var + ch + 1) + 1e-5f);
        float sh1 = __ldg(beta + ch + 1) - __ldg(mean + ch + 1) * s1;
        int ks = ch >> 4;
        int cc = (ch >> 3) & 1;
        int off = (ch & 7) * 2;
#pragma unroll
        for (int i = 0; i < 4; i++) {
#pragma unroll
            for (int hh = 0; hh < 2; hh++) {
                int row = wm * 64 + i * 16 + rhalf + hh * 8;
                float v0 = fmaxf(acc[i][j][hh * 2 + 0] * s0 + sh0, 0.f);
                float v1 = fmaxf(acc[i][j][hh * 2 + 1] * s1 + sh1, 0.f);
                __half h0, l0, h1, l1;
                hsplit(v0, h0, l0);
                hsplit(v1, h1, l1);
                uint32_t ad = ks * 8192 + row * 32 + (((cc ^ (row >> 2)) & 1) << 4) + off;
                *(__half2*)(smem + ad)        = __halves2half2(h0, h1);
                *(__half2*)(smem + ad + 4096) = __halves2half2(l0, l1);
            }
        }
    }
}

// ============================================================================
// Fused SA stack: (X0 * W1 -> bn/relu) * W2 -> bn/relu) * W3 -> bn/relu -> maxpool16 -> Y
// One CTA = 128 points. Activations never leave the SM after phase 1.
// SMEM: [Abuf 128K][stage ring 72K] = 200K
// ============================================================================
__global__ void __launch_bounds__(256, 1)
sa_fused_kernel(const __half* __restrict__ X0h, const __half* __restrict__ X0l,
                const __half* __restrict__ W1h, const __half* __restrict__ W1l,
                const __half* __restrict__ W2h, const __half* __restrict__ W2l,
                const __half* __restrict__ W3h, const __half* __restrict__ W3l,
                __half* __restrict__ Yh, __half* __restrict__ Yl,
                const float* __restrict__ gamma, const float* __restrict__ beta,
                const float* __restrict__ mean, const float* __restrict__ var) {
    extern __shared__ __align__(16) uint8_t smem_dyn[];
    const uint32_t sbase = s2u(smem_dyn);
    const uint32_t stg = sbase + ABUF_B;
    const int tid = threadIdx.x, lane = tid & 31, warp = tid >> 5;
    const int wm = warp & 1, wn = warp >> 1;
    const int m0 = blockIdx.x * 128;

    float acc[4][8][4];
#pragma unroll
    for (int i = 0; i < 4; i++)
#pragma unroll
        for (int j = 0; j < 8; j++)
#pragma unroll
            for (int q = 0; q < 4; q++) acc[i][j][q] = 0.f;

    // phase-1 A+B stage load (1536 x 16B, 6/thread), KC = 288
#define LOAD1(s)                                                                 \
    {                                                                            \
        uint32_t base = stg + ((s) % 3) * STAGE_B;                               \
        int k0 = (s) << 4;                                                       \
        _Pragma("unroll")                                                        \
        for (int q = 0; q < 6; q++) {                                            \
            int i = q * 256 + tid;                                               \
            const __half* src;                                                   \
            uint32_t dst;                                                        \
            if (i < 512) {                                                       \
                int pa = i >> 8, r = (i & 255) >> 1, cc = i & 1;                 \
                src = (pa ? X0l : X0h) + (size_t)(m0 + r) * 288 + k0 + cc * 8;   \
                dst = base + pa * 4096 + r * 32 + (((cc ^ (r >> 2)) & 1) << 4);  \
            } else {                                                             \
                int ib = i - 512;                                                \
                int pb = ib >> 9, r = (ib & 511) >> 1, cc = ib & 1;              \
                src = (pb ? W1l : W1h) + (size_t)r * 288 + k0 + cc * 8;          \
                dst = base + 8192 + pb * 8192 + r * 32 +                         \
                      (((cc ^ (r >> 2)) & 1) << 4);                              \
            }                                                                    \
            cpasync16(dst, src);                                                 \
        }                                                                        \
        asm volatile("cp.async.commit_group;");                                  \
    }

    // B-only stage load (1024 x 16B, 4/thread), KC = 256
#define BLOAD(s, WH, WL)                                                         \
    {                                                                            \
        uint32_t base = stg + ((s) % 3) * BSTAGE_B;                              \
        int k0 = (s) << 4;                                                       \
        _Pragma("unroll")                                                        \
        for (int q = 0; q < 4; q++) {                                            \
            int i = q * 256 + tid;                                               \
            int pb = i >> 9, r = (i & 511) >> 1, cc = i & 1;                     \
            const __half* src = (pb ? (WL) : (WH)) + (size_t)r * 256 + k0 + cc * 8; \
            uint32_t dst = base + pb * 8192 + r * 32 +                           \
                           (((cc ^ (r >> 2)) & 1) << 4);                         \
            cpasync16(dst, src);                                                 \
        }                                                                        \
        asm volatile("cp.async.commit_group;");                                  \
    }

    // ---------------- phase 1: X0 (K=288) x W1 ----------------
    LOAD1(0);
    LOAD1(1);
    for (int s = 0; s < 18; s++) {
        if (s + 1 < 18) asm volatile("cp.async.wait_group 1;");
        else            asm volatile("cp.async.wait_group 0;");
        __syncthreads();
        if (s + 2 < 18) LOAD1(s + 2);
        uint32_t st = stg + (s % 3) * STAGE_B;
        compute_stage(acc, st, st + 4096, st + 8192, st + 16384, wm, wn, lane);
    }
    // prefetch W2 while doing epilogue 1
    BLOAD(0, W2h, W2l);
    BLOAD(1, W2h, W2l);
    epi_to_abuf(acc, smem_dyn, wm, wn, lane, gamma, beta, mean, var);
#pragma unroll
    for (int i = 0; i < 4; i++)
#pragma unroll
        for (int j = 0; j < 8; j++)
#pragma unroll
            for (int q = 0; q < 4; q++) acc[i][j][q] = 0.f;

    // ---------------- phase 2: Abuf x W2 ----------------
    for (int s = 0; s < 16; s++) {
        if (s + 1 < 16) asm volatile("cp.async.wait_group 1;");
        else            asm volatile("cp.async.wait_group 0;");
        __syncthreads();
        if (s + 2 < 16) BLOAD(s + 2, W2h, W2l);
        uint32_t ab = sbase + s * 8192;
        uint32_t bb = stg + (s % 3) * BSTAGE_B;
        compute_stage(acc, ab, ab + 4096, bb, bb + 8192, wm, wn, lane);
    }
    __syncthreads();
    BLOAD(0, W3h, W3l);
    BLOAD(1, W3h, W3l);
    epi_to_abuf(acc, smem_dyn, wm, wn, lane, gamma + 256, beta + 256, mean + 256, var + 256);
#pragma unroll
    for (int i = 0; i < 4; i++)
#pragma unroll
        for (int j = 0; j < 8; j++)
#pragma unroll
            for (int q = 0; q < 4; q++) acc[i][j][q] = 0.f;

    // ---------------- phase 3: Abuf x W3 ----------------
    for (int s = 0; s < 16; s++) {
        if (s + 1 < 16) asm volatile("cp.async.wait_group 1;");
        else            asm volatile("cp.async.wait_group 0;");
        __syncthreads();
        if (s + 2 < 16) BLOAD(s + 2, W3h, W3l);
        uint32_t ab = sbase + s * 8192;
        uint32_t bb = stg + (s % 3) * BSTAGE_B;
        compute_stage(acc, ab, ab + 4096, bb, bb + 8192, wm, wn, lane);
    }

    // ---------------- epilogue 3: BN+ReLU + 16-row maxpool -> Y ----------------
    {
        const int colq = (lane & 3) * 2;
        const int rhalf = lane >> 2;
        const float* g3 = gamma + 512;
        const float* b3 = beta + 512;
        const float* mn3 = mean + 512;
        const float* vr3 = var + 512;
#pragma unroll
        for (int j = 0; j < 8; j++) {
            int ch = wn * 64 + j * 8 + colq;
            float s0 = __ldg(g3 + ch) * rsqrtf(__ldg(vr3 + ch) + 1e-5f);
            float sh0 = __ldg(b3 + ch) - __ldg(mn3 + ch) * s0;
            float s1 = __ldg(g3 + ch + 1) * rsqrtf(__ldg(vr3 + ch + 1) + 1e-5f);
            float sh1 = __ldg(b3 + ch + 1) - __ldg(mn3 + ch + 1) * s1;
#pragma unroll
            for (int i = 0; i < 4; i++) {
                float m0v = fmaxf(fmaxf(acc[i][j][0], acc[i][j][2]) * s0 + sh0, 0.f);
                float m1v = fmaxf(fmaxf(acc[i][j][1], acc[i][j][3]) * s1 + sh1, 0.f);
#pragma unroll
                for (int off = 4; off <= 16; off <<= 1) {
                    m0v = fmaxf(m0v, __shfl_xor_sync(0xffffffffu, m0v, off));
                    m1v = fmaxf(m1v, __shfl_xor_sync(0xffffffffu, m1v, off));
                }
                if (rhalf == 0) {
                    int p = (m0 + wm * 64 + i * 16) >> 4;
                    __half h0, l0, h1, l1;
                    hsplit(m0v, h0, l0);
                    hsplit(m1v, h1, l1);
                    *(__half2*)(Yh + (size_t)p * 256 + ch) = __halves2half2(h0, h1);
                    *(__half2*)(Yl + (size_t)p * 256 + ch) = __halves2half2(l0, l1);
                }
            }
        }
    }
#undef LOAD1
#undef BLOAD
}

// ============================================================================
// Small GEMM for proposal head (known-good R8 kernel)
//   MODE 0: BN+ReLU split planes;  MODE 1: +bias, fp32 out
// ============================================================================
template <int MODE>
__global__ void __launch_bounds__(256, 2)
hgemm_kernel(const __half* __restrict__ Ah, const __half* __restrict__ Al,
             const __half* __restrict__ Bh, const __half* __restrict__ Bl,
             int KC, int ldC,
             __half* __restrict__ Ch, __half* __restrict__ Cl,
             float* __restrict__ Cf,
             const float* __restrict__ gamma, const float* __restrict__ beta,
             const float* __restrict__ mean, const float* __restrict__ var,
             const float* __restrict__ bias) {
    __shared__ __align__(16) uint8_t smem[2][16384];
    const int tid  = threadIdx.x;
    const int lane = tid & 31;
    const int warp = tid >> 5;
    const int wm = warp & 1;
    const int wn = warp >> 1;
    const int m0 = blockIdx.x * 128;
    const int n0 = blockIdx.y * 128;

    const uint32_t sb[2] = { s2u(smem[0]), s2u(smem[1]) };

    float acc[4][4][4];
#pragma unroll
    for (int i = 0; i < 4; i++)
#pragma unroll
        for (int j = 0; j < 4; j++)
#pragma unroll
            for (int q = 0; q < 4; q++) acc[i][j][q] = 0.f;

    const int plane = tid >> 6;
    const int idx0 = (tid & 63) * 4;
    const __half* gplane = (plane == 0) ? Ah : (plane == 1) ? Al : (plane == 2) ? Bh : Bl;
    const int rbase = (plane < 2) ? m0 : n0;
    const uint32_t pl_off = plane * 4096;

    const int nst = KC >> 4;

#define LOAD_STAGE(s)                                                          \
    {                                                                          \
        uint32_t base = sb[(s) & 1] + pl_off;                                  \
        int k0 = (s) << 4;                                                     \
        _Pragma("unroll")                                                      \
        for (int t4 = 0; t4 < 4; t4++) {                                       \
            int idx = idx0 + t4;                                               \
            int row = idx >> 1, cc = idx & 1;                                  \
            uint32_t sa = base + row * 32 + (((cc ^ (row >> 2)) & 1) << 4);    \
            cpasync16(sa, gplane + (size_t)(rbase + row) * KC + k0 + cc * 8);  \
        }                                                                      \
        asm volatile("cp.async.commit_group;");                                \
    }

    LOAD_STAGE(0);

    const int lrow = lane & 15, lc = lane >> 4;
    const int br = (lane & 7) + ((lane >> 4) & 1) * 8;
    const int bc = (lane >> 3) & 1;

    for (int s = 0; s < nst; s++) {
        if (s + 1 < nst) {
            LOAD_STAGE(s + 1);
            asm volatile("cp.async.wait_group 1;");
        } else {
            asm volatile("cp.async.wait_group 0;");
        }
        __syncthreads();

        uint32_t base = sb[s & 1];
        uint32_t ah[4][4], al[4][4];
#pragma unroll
        for (int i = 0; i < 4; i++) {
            int r = wm * 64 + i * 16 + lrow;
            uint32_t a = base + r * 32 + (((lc ^ (r >> 2)) & 1) << 4);
            ldsm4(ah[i], a);
            ldsm4(al[i], a + 4096);
        }
#pragma unroll
        for (int jj = 0; jj < 2; jj++) {
            int r = wn * 32 + jj * 16 + br;
            uint32_t boff = base + 8192 + r * 32 + (((bc ^ (r >> 2)) & 1) << 4);
            uint32_t bh4[4], bl4[4];
            ldsm4(bh4, boff);
            ldsm4(bl4, boff + 4096);
#pragma unroll
            for (int j2 = 0; j2 < 2; j2++) {
                const uint32_t* bhf = bh4 + j2 * 2;
                const uint32_t* blf = bl4 + j2 * 2;
#pragma unroll
                for (int i = 0; i < 4; i++) {
                    float* c = acc[i][jj * 2 + j2];
                    mma16816(c, ah[i], bhf);
                    mma16816(c, ah[i], blf);
                    mma16816(c, al[i], bhf);
                }
            }
        }
        __syncthreads();
    }

    const int colq = (lane & 3) * 2;
    const int rhalf = lane >> 2;
#pragma unroll
    for (int j = 0; j < 4; j++) {
        int ch = n0 + wn * 32 + j * 8 + colq;
        float sc0 = 1.f, sh0 = 0.f, sc1 = 1.f, sh1 = 0.f;
        if (MODE == 0) {
            float s0 = __ldg(gamma + ch) * rsqrtf(__ldg(var + ch) + 1e-5f);
            sc0 = s0; sh0 = __ldg(beta + ch) - __ldg(mean + ch) * s0;
            float s1 = __ldg(gamma + ch + 1) * rsqrtf(__ldg(var + ch + 1) + 1e-5f);
            sc1 = s1; sh1 = __ldg(beta + ch + 1) - __ldg(mean + ch + 1) * s1;
        } else {
            sh0 = (ch < OUTD) ? __ldg(bias + ch) : 0.f;
            sh1 = (ch + 1 < OUTD) ? __ldg(bias + ch + 1) : 0.f;
        }
#pragma unroll
        for (int i = 0; i < 4; i++) {
            int r0 = m0 + wm * 64 + i * 16 + rhalf;
#pragma unroll
            for (int hh = 0; hh < 2; hh++) {
                int r = r0 + hh * 8;
                float v0 = acc[i][j][hh * 2 + 0];
                float v1 = acc[i][j][hh * 2 + 1];
                if (MODE == 0) {
                    v0 = fmaxf(v0 * sc0 + sh0, 0.f);
                    v1 = fmaxf(v1 * sc1 + sh1, 0.f);
                    __half h0, l0, h1, l1;
                    hsplit(v0, h0, l0);
                    hsplit(v1, h1, l1);
                    *(__half2*)(Ch + (size_t)r * ldC + ch) = __halves2half2(h0, h1);
                    *(__half2*)(Cl + (size_t)r * ldC + ch) = __halves2half2(l0, l1);
                } else {
                    Cf[(size_t)r * ldC + ch]     = v0 + sh0;
                    Cf[(size_t)r * ldC + ch + 1] = v1 + sh1;
                }
            }
        }
    }
#undef LOAD_STAGE
}

// ============================================================================
// Finalize (net layout [p][128])
// ============================================================================
__global__ void finalize_kernel(const float* __restrict__ net,
                                const float* __restrict__ newxyz,
                                const float* __restrict__ msz,
                                float* __restrict__ out) {
    int n = blockIdx.x * blockDim.x + threadIdx.x;
    if (n >= NP2) return;
#define NET(o) net[(size_t)n * 128 + (o)]

    float obj0 = NET(0), obj1 = NET(1);
    out[OFF_OBJ + n * 2 + 0] = obj0;
    out[OFF_OBJ + n * 2 + 1] = obj1;

    float cx = newxyz[n * 3 + 0] + NET(2);
    float cy = newxyz[n * 3 + 1] + NET(3);
    float cz = newxyz[n * 3 + 2] + NET(4);
    out[OFF_CEN + n * 3 + 0] = cx;
    out[OFF_CEN + n * 3 + 1] = cy;
    out[OFF_CEN + n * 3 + 2] = cz;

    int best = 0;
    float bv = NET(29);
    out[OFF_SS + n * 18 + 0] = bv;
#pragma unroll
    for (int sc = 1; sc < 18; sc++) {
        float v = NET(29 + sc);
        out[OFF_SS + n * 18 + sc] = v;
        if (v > bv) { bv = v; best = sc; }
    }

#pragma unroll
    for (int sc = 0; sc < 18; sc++) {
#pragma unroll
        for (int d = 0; d < 3; d++) {
            float sres = NET(47 + sc * 3 + d) * msz[sc * 3 + d];
            out[OFF_SRES + ((size_t)n * 18 + sc) * 3 + d] = sres;
        }
    }

    float ps[3];
#pragma unroll
    for (int d = 0; d < 3; d++) {
        float m = msz[best * 3 + d];
        ps[d] = NET(47 + best * 3 + d) * m + m;
        out[OFF_PSZ + n * 3 + d] = ps[d];
    }

    float sem[18];
#pragma unroll
    for (int s = 0; s < 18; s++) {
        sem[s] = NET(101 + s);
        out[OFF_SEM + n * 18 + s] = sem[s];
    }

    const float sxA[8] = {1, 1, -1, -1, 1, 1, -1, -1};
    const float syA[8] = {1, 1, 1, 1, -1, -1, -1, -1};
    const float szA[8] = {1, -1, -1, 1, 1, -1, -1, 1};
    float c0 = cx, c1 = cz, c2 = -cy;
#pragma unroll
    for (int k = 0; k < 8; k++) {
        out[OFF_CORN + ((size_t)n * 8 + k) * 3 + 0] = ps[0] * sxA[k] * 0.5f + c0;
        out[OFF_CORN + ((size_t)n * 8 + k) * 3 + 1] = ps[2] * syA[k] * 0.5f + c1;
        out[OFF_CORN + ((size_t)n * 8 + k) * 3 + 2] = ps[1] * szA[k] * 0.5f + c2;
    }

#pragma unroll
    for (int s = 0; s < 18; s++) out[OFF_SLOG + n * 19 + s] = sem[s];
    out[OFF_SLOG + n * 19 + 18] = (obj0 <= obj1) ? 0.0f : 1e10f;

    {
        float m = fmaxf(obj0, obj1);
        float e0 = expf(obj0 - m), e1 = expf(obj1 - m);
        out[OFF_OPROB + n] = e1 / (e0 + e1);
    }
    {
        float m = sem[0];
#pragma unroll
        for (int s = 1; s < 18; s++) m = fmaxf(m, sem[s]);
        float sum = 0.f;
        float e[18];
#pragma unroll
        for (int s = 0; s < 18; s++) { e[s] = expf(sem[s] - m); sum += e[s]; }
        float inv = 1.0f / sum;
#pragma unroll
        for (int s = 0; s < 18; s++) out[OFF_SPROB + n * 18 + s] = e[s] * inv;
    }
#undef NET
}

// ============================================================================
// launch
// ============================================================================
extern "C" void kernel_launch(void* const* d_in, const int* in_sizes, int n_in,
                              void* d_out, int out_size) {
    const float* xyz      = (const float*)d_in[0];
    const float* features = (const float*)d_in[1];
    const float* sa_w1    = (const float*)d_in[2];
    const float* sa_w2    = (const float*)d_in[3];
    const float* sa_w3    = (const float*)d_in[4];
    const float* sa_gamma = (const float*)d_in[5];
    const float* sa_beta  = (const float*)d_in[6];
    const float* sa_mean  = (const float*)d_in[7];
    const float* sa_var   = (const float*)d_in[8];
    const float* p_w1     = (const float*)d_in[9];
    const float* p_w2     = (const float*)d_in[10];
    const float* p_w3     = (const float*)d_in[11];
    const float* p_b3     = (const float*)d_in[12];
    const float* p_gamma  = (const float*)d_in[13];
    const float* p_beta   = (const float*)d_in[14];
    const float* p_mean   = (const float*)d_in[15];
    const float* p_var    = (const float*)d_in[16];
    const float* msz      = (const float*)d_in[17];
    float* out = (float*)d_out;

    float *G, *net, *newxyz;
    int* ball;
    __half *X0h, *X0l;
    __half *Yh, *Yl, *Y1h, *Y1l, *Y2h, *Y2l;
    __half *W1h, *W1l, *W2h, *W2l, *W3h, *W3l, *P1h, *P1l, *P2h, *P2l, *P3h, *P3l;
    cudaGetSymbolAddress((void**)&G,   g_G);
    cudaGetSymbolAddress((void**)&net, g_net);
    cudaGetSymbolAddress((void**)&newxyz, g_newxyz);
    cudaGetSymbolAddress((void**)&ball, g_ball);
    cudaGetSymbolAddress((void**)&X0h, g_X0h); cudaGetSymbolAddress((void**)&X0l, g_X0l);
    cudaGetSymbolAddress((void**)&Yh,  g_Yh);  cudaGetSymbolAddress((void**)&Yl,  g_Yl);
    cudaGetSymbolAddress((void**)&Y1h, g_Y1h); cudaGetSymbolAddress((void**)&Y1l, g_Y1l);
    cudaGetSymbolAddress((void**)&Y2h, g_Y2h); cudaGetSymbolAddress((void**)&Y2l, g_Y2l);
    cudaGetSymbolAddress((void**)&W1h, g_W1h); cudaGetSymbolAddress((void**)&W1l, g_W1l);
    cudaGetSymbolAddress((void**)&W2h, g_W2h); cudaGetSymbolAddress((void**)&W2l, g_W2l);
    cudaGetSymbolAddress((void**)&W3h, g_W3h); cudaGetSymbolAddress((void**)&W3l, g_W3l);
    cudaGetSymbolAddress((void**)&P1h, g_P1h); cudaGetSymbolAddress((void**)&P1l, g_P1l);
    cudaGetSymbolAddress((void**)&P2h, g_P2h); cudaGetSymbolAddress((void**)&P2l, g_P2l);
    cudaGetSymbolAddress((void**)&P3h, g_P3h); cudaGetSymbolAddress((void**)&P3l, g_P3l);

    const int DYN = ABUF_B + 3 * STAGE_B;   // 204800
    cudaFuncSetAttribute(sa_fused_kernel, cudaFuncAttributeMaxDynamicSharedMemorySize, DYN);

    fps_kernel<<<BATCH, 256>>>(xyz, newxyz);
    ball_query_kernel<<<NP2 * 32 / 256, 256>>>(xyz, newxyz, ball);
    gather_xyz_kernel<<<NTOT / 256, 256>>>(xyz, newxyz, ball, G);
    gather_feat_kernel<<<BATCH * CFEAT, 256>>>(features, ball, G);

    split_w_kernel<<<(256 * 288 + 255) / 256, 256>>>(sa_w1, W1h, W1l, 256, 259, 259, 288, 256 * 288);
    split_w_kernel<<<256, 256>>>(sa_w2, W2h, W2l, 256, 256, 256, 256, 256 * 256);
    split_w_kernel<<<256, 256>>>(sa_w3, W3h, W3l, 256, 256, 256, 256, 256 * 256);
    split_w_kernel<<<256, 256>>>(p_w1, P1h, P1l, 256, 256, 256, 256, 256 * 256);
    split_w_kernel<<<256, 256>>>(p_w2, P2h, P2l, 256, 256, 256, 256, 256 * 256);
    split_w_kernel<<<128, 256>>>(p_w3, P3h, P3l, OUTD, 256, 256, 256, 128 * 256);

    transpose_split_kernel<<<dim3(NTOT / 32, 288 / 32), dim3(32, 8)>>>(G, X0h, X0l);

    sa_fused_kernel<<<NTOT / 128, 256, DYN>>>(X0h, X0l, W1h, W1l, W2h, W2l, W3h, W3l,
                                              Yh, Yl, sa_gamma, sa_beta, sa_mean, sa_var);

    dim3 gP(NP2 / 128, 2);
    hgemm_kernel<0><<<gP, 256>>>(Yh, Yl, P1h, P1l, 256, 256, Y1h, Y1l, nullptr,
                                 p_gamma + 0,   p_beta + 0,   p_mean + 0,   p_var + 0,   nullptr);
    hgemm_kernel<0><<<gP, 256>>>(Y1h, Y1l, P2h, P2l, 256, 256, Y2h, Y2l, nullptr,
                                 p_gamma + 256, p_beta + 256, p_mean + 256, p_var + 256, nullptr);
    dim3 gH(NP2 / 128, 1);
    hgemm_kernel<1><<<gH, 256>>>(Y2h, Y2l, P3h, P3l, 256, 128, nullptr, nullptr, net,
                                 nullptr, nullptr, nullptr, nullptr, p_b3);

    finalize_kernel<<<NP2 / 256, 256>>>(net, newxyz, msz, out);
}

// round 15
// speedup vs baseline: 2.4909x; 1.0927x over previous
#include <cuda_runtime.h>
#include <cuda_fp16.h>
#include <cstdint>

#define BATCH 32
#define KPTS 2048
#define CFEAT 256
#define NPROP 256
#define NSAMP 16
#define NTOT (BATCH * NPROP * NSAMP)   // 131072
#define NP2  (BATCH * NPROP)           // 8192
#define OUTD 119

// ---------------- scratch (static device memory) ----------------------------
__device__ __align__(128) __half g_Yh [NP2 * 256];
__device__ __align__(128) __half g_Yl [NP2 * 256];
__device__ float  g_net[NP2 * 128];
__device__ __align__(128) __half g_W1h[256 * 288];
__device__ __align__(128) __half g_W1l[256 * 288];
__device__ __align__(128) __half g_W2h[256 * 256];
__device__ __align__(128) __half g_W2l[256 * 256];
__device__ __align__(128) __half g_W3h[256 * 256];
__device__ __align__(128) __half g_W3l[256 * 256];
__device__ __align__(128) __half g_P1h[256 * 256];
__device__ __align__(128) __half g_P1l[256 * 256];
__device__ __align__(128) __half g_P2h[256 * 256];
__device__ __align__(128) __half g_P2l[256 * 256];
__device__ __align__(128) __half g_P3h[256 * 256];   // rows >= OUTD zero
__device__ __align__(128) __half g_P3l[256 * 256];
__device__ float  g_newxyz[NP2 * 3];
__device__ int    g_ball[NP2 * NSAMP];

// ---------------- output offsets (floats) -----------------------------------
#define OFF_OBJ   0
#define OFF_CEN   16384
#define OFF_SS    40960
#define OFF_SRES  188416
#define OFF_PSZ   630784
#define OFF_SEM   655360
#define OFF_CORN  802816
#define OFF_SLOG  999424
#define OFF_OPROB 1155072
#define OFF_SPROB 1163264

// ---------------- helpers ----------------------------------------------------
__device__ __forceinline__ uint32_t s2u(const void* p) {
    uint32_t a;
    asm("{ .reg .u64 t; cvta.to.shared.u64 t, %1; cvt.u32.u64 %0, t; }" : "=r"(a) : "l"(p));
    return a;
}
__device__ __forceinline__ void ldsm4(uint32_t* r, uint32_t a) {
    asm volatile("ldmatrix.sync.aligned.m8n8.x4.shared.b16 {%0,%1,%2,%3}, [%4];"
                 : "=r"(r[0]), "=r"(r[1]), "=r"(r[2]), "=r"(r[3]) : "r"(a));
}
__device__ __forceinline__ void mma16816(float* c, const uint32_t* a, const uint32_t* b) {
    asm volatile(
        "mma.sync.aligned.m16n8k16.row.col.f32.f16.f16.f32 "
        "{%0,%1,%2,%3}, {%4,%5,%6,%7}, {%8,%9}, {%0,%1,%2,%3};"
        : "+f"(c[0]), "+f"(c[1]), "+f"(c[2]), "+f"(c[3])
        : "r"(a[0]), "r"(a[1]), "r"(a[2]), "r"(a[3]), "r"(b[0]), "r"(b[1]));
}
__device__ __forceinline__ void cpasync16(uint32_t sa, const void* g) {
    asm volatile("cp.async.cg.shared.global [%0], [%1], 16;" :: "r"(sa), "l"(g));
}
__device__ __forceinline__ void hsplit(float v, __half& h, __half& l) {
    h = __float2half_rn(v);
    l = __float2half_rn(v - __half2float(h));
}

// ============================================================================
// split + pad all six weight matrices in one kernel (launch index 0)
// ============================================================================
__global__ void split_all_kernel(const float* __restrict__ sa_w1,
                                 const float* __restrict__ sa_w2,
                                 const float* __restrict__ sa_w3,
                                 const float* __restrict__ p_w1,
                                 const float* __restrict__ p_w2,
                                 const float* __restrict__ p_w3) {
    int idx = blockIdx.x * 256 + threadIdx.x;
    float v;
    __half* Wh;
    __half* Wl;
    int off;
    if (idx < 73728) {                       // W1: 256 x 288 (259 valid cols)
        int r = idx / 288, c = idx % 288;
        v = (c < 259) ? sa_w1[r * 259 + c] : 0.f;
        Wh = g_W1h; Wl = g_W1l; off = idx;
    } else {
        int idx2 = idx - 73728;
        int seg = idx2 >> 16;                // 0..4
        int w = idx2 & 65535;
        int r = w >> 8;
        off = w;
        if (seg == 0)      { v = sa_w2[w]; Wh = g_W2h; Wl = g_W2l; }
        else if (seg == 1) { v = sa_w3[w]; Wh = g_W3h; Wl = g_W3l; }
        else if (seg == 2) { v = p_w1[w];  Wh = g_P1h; Wl = g_P1l; }
        else if (seg == 3) { v = p_w2[w];  Wh = g_P2h; Wl = g_P2l; }
        else               { v = (r < OUTD) ? p_w3[w] : 0.f; Wh = g_P3h; Wl = g_P3l; }
    }
    __half h, l;
    hsplit(v, h, l);
    Wh[off] = h;
    Wl[off] = l;
}

// ============================================================================
// FPS
// ============================================================================
__global__ void fps_kernel(const float* __restrict__ xyz, float* __restrict__ newxyz) {
    int b = blockIdx.x;
    int t = threadIdx.x;
    __shared__ float sx[KPTS], sy[KPTS], sz[KPTS];
    __shared__ float wv[8];
    __shared__ int   wi[8];
    __shared__ int   far_s;

    const float* p = xyz + (size_t)b * KPTS * 3;
    float px[8], py[8], pz[8], dist[8];
#pragma unroll
    for (int i = 0; i < 8; i++) {
        int j = i * 256 + t;
        px[i] = p[j * 3 + 0];
        py[i] = p[j * 3 + 1];
        pz[i] = p[j * 3 + 2];
        sx[j] = px[i]; sy[j] = py[i]; sz[j] = pz[i];
        dist[i] = 1e10f;
    }
    if (t == 0) far_s = 0;
    __syncthreads();

    for (int it = 0; it < NPROP; it++) {
        int far = far_s;
        if (t == 0) {
            float* o = newxyz + (size_t)(b * NPROP + it) * 3;
            o[0] = sx[far]; o[1] = sy[far]; o[2] = sz[far];
        }
        float cx = sx[far], cy = sy[far], cz = sz[far];
        float bv = -1.0f;
        int   bj = 0x7fffffff;
#pragma unroll
        for (int i = 0; i < 8; i++) {
            float dx = px[i] - cx, dy = py[i] - cy, dz = pz[i] - cz;
            float d = dx * dx + dy * dy + dz * dz;
            dist[i] = fminf(dist[i], d);
            int j = i * 256 + t;
            if (dist[i] > bv || (dist[i] == bv && j < bj)) { bv = dist[i]; bj = j; }
        }
#pragma unroll
        for (int off = 16; off; off >>= 1) {
            float ov = __shfl_down_sync(0xffffffffu, bv, off);
            int   oj = __shfl_down_sync(0xffffffffu, bj, off);
            if (ov > bv || (ov == bv && oj < bj)) { bv = ov; bj = oj; }
        }
        if ((t & 31) == 0) { wv[t >> 5] = bv; wi[t >> 5] = bj; }
        __syncthreads();
        if (t == 0) {
            float fv = wv[0]; int fj = wi[0];
#pragma unroll
            for (int w = 1; w < 8; w++) {
                if (wv[w] > fv || (wv[w] == fv && wi[w] < fj)) { fv = wv[w]; fj = wi[w]; }
            }
            far_s = fj;
        }
        __syncthreads();
    }
}

// ============================================================================
// Ball query
// ============================================================================
__global__ void ball_query_kernel(const float* __restrict__ xyz,
                                  const float* __restrict__ newxyz,
                                  int* __restrict__ ball) {
    int gwarp = (blockIdx.x * blockDim.x + threadIdx.x) >> 5;
    if (gwarp >= NP2) return;
    int lane = threadIdx.x & 31;
    int wl = threadIdx.x >> 5;
    int b = gwarp >> 8;

    __shared__ int slots[8][16];
    if (lane == 0) slots[wl][0] = 0;

    float cx = newxyz[gwarp * 3 + 0];
    float cy = newxyz[gwarp * 3 + 1];
    float cz = newxyz[gwarp * 3 + 2];
    const float* p = xyz + (size_t)b * KPTS * 3;

    int cnt = 0;
    for (int r = 0; r < KPTS / 32 && cnt < NSAMP; r++) {
        int j = r * 32 + lane;
        float dx = cx - p[j * 3 + 0];
        float dy = cy - p[j * 3 + 1];
        float dz = cz - p[j * 3 + 2];
        float d2 = dx * dx + dy * dy + dz * dz;
        bool pred = d2 < 0.09f;
        unsigned m = __ballot_sync(0xffffffffu, pred);
        int pos = cnt + __popc(m & ((1u << lane) - 1u));
        if (pred && pos < NSAMP) slots[wl][pos] = j;
        cnt += __popc(m);
    }
    __syncwarp();
    if (lane < NSAMP) {
        int first = slots[wl][0];
        int v = (lane < cnt) ? slots[wl][lane] : first;
        ball[gwarp * NSAMP + lane] = v;
    }
}

// ============================================================================
// Shared GEMM building blocks (128x256 CTA tile, 8 warps of 64x64)
// ============================================================================
#define ABUF_B    131072                 // 16 k-stages x 8192 (hi 4K | lo 4K)
#define BRING_B   49152                  // 3 x 16384 B-only stages
#define OFF_ASTG  (ABUF_B + BRING_B)     // 180224 : 2 x 8192 gathered-A stages
#define OFF_BALLS (OFF_ASTG + 16384)     // 196608 : 128 ints
#define OFF_CENS  (OFF_BALLS + 512)      // 197120 : 24 floats
#define SA_DYN    197248

#define HSTG_B    24576                  // head phase-1 A+B stage
#define HEAD_DYN  (ABUF_B + 3 * HSTG_B)  // 204800

__device__ __forceinline__ void compute_stage(
    float acc[4][8][4], uint32_t aH, uint32_t aL, uint32_t bH, uint32_t bL,
    int wm, int wn, int lane) {
    const int lrow = lane & 15, lc = lane >> 4;
    const int br = (lane & 7) + ((lane >> 4) & 1) * 8;
    const int bc = (lane >> 3) & 1;
    uint32_t ah[4][4];
#pragma unroll
    for (int i = 0; i < 4; i++) {
        int r = wm * 64 + i * 16 + lrow;
        ldsm4(ah[i], aH + r * 32 + (((lc ^ (r >> 2)) & 1) << 4));
    }
    uint32_t bh[4][4];
#pragma unroll
    for (int jj = 0; jj < 4; jj++) {
        int r = wn * 64 + jj * 16 + br;
        ldsm4(bh[jj], bH + r * 32 + (((bc ^ (r >> 2)) & 1) << 4));
    }
#pragma unroll
    for (int jj = 0; jj < 4; jj++)
#pragma unroll
        for (int j2 = 0; j2 < 2; j2++)
#pragma unroll
            for (int i = 0; i < 4; i++)
                mma16816(acc[i][jj * 2 + j2], ah[i], bh[jj] + j2 * 2);
    {
        uint32_t bl4[4][4];
#pragma unroll
        for (int jj = 0; jj < 4; jj++) {
            int r = wn * 64 + jj * 16 + br;
            ldsm4(bl4[jj], bL + r * 32 + (((bc ^ (r >> 2)) & 1) << 4));
        }
#pragma unroll
        for (int jj = 0; jj < 4; jj++)
#pragma unroll
            for (int j2 = 0; j2 < 2; j2++)
#pragma unroll
                for (int i = 0; i < 4; i++)
                    mma16816(acc[i][jj * 2 + j2], ah[i], bl4[jj] + j2 * 2);
    }
    {
        uint32_t al4[4][4];
#pragma unroll
        for (int i = 0; i < 4; i++) {
            int r = wm * 64 + i * 16 + lrow;
            ldsm4(al4[i], aL + r * 32 + (((lc ^ (r >> 2)) & 1) << 4));
        }
#pragma unroll
        for (int jj = 0; jj < 4; jj++)
#pragma unroll
            for (int j2 = 0; j2 < 2; j2++)
#pragma unroll
                for (int i = 0; i < 4; i++)
                    mma16816(acc[i][jj * 2 + j2], al4[i], bh[jj] + j2 * 2);
    }
}

// BN+ReLU epilogue -> SMEM A-buffer (per-stage swizzled fp16 split layout)
__device__ __forceinline__ void epi_to_abuf(
    float acc[4][8][4], uint8_t* smem, int wm, int wn, int lane,
    const float* __restrict__ gamma, const float* __restrict__ beta,
    const float* __restrict__ mean, const float* __restrict__ var) {
    const int colq = (lane & 3) * 2;
    const int rhalf = lane >> 2;
#pragma unroll
    for (int j = 0; j < 8; j++) {
        int ch = wn * 64 + j * 8 + colq;
        float s0 = __ldg(gamma + ch) * rsqrtf(__ldg(var + ch) + 1e-5f);
        float sh0 = __ldg(beta + ch) - __ldg(mean + ch) * s0;
        float s1 = __ldg(gamma + ch + 1) * rsqrtf(__ldg(var + ch + 1) + 1e-5f);
        float sh1 = __ldg(beta + ch + 1) - __ldg(mean + ch + 1) * s1;
        int ks = ch >> 4;
        int cc = (ch >> 3) & 1;
        int off = (ch & 7) * 2;
#pragma unroll
        for (int i = 0; i < 4; i++) {
#pragma unroll
            for (int hh = 0; hh < 2; hh++) {
                int row = wm * 64 + i * 16 + rhalf + hh * 8;
                float v0 = fmaxf(acc[i][j][hh * 2 + 0] * s0 + sh0, 0.f);
                float v1 = fmaxf(acc[i][j][hh * 2 + 1] * s1 + sh1, 0.f);
                __half h0, l0, h1, l1;
                hsplit(v0, h0, l0);
                hsplit(v1, h1, l1);
                uint32_t ad = ks * 8192 + row * 32 + (((cc ^ (row >> 2)) & 1) << 4) + off;
                *(__half2*)(smem + ad)        = __halves2half2(h0, h1);
                *(__half2*)(smem + ad + 4096) = __halves2half2(l0, l1);
            }
        }
    }
}

// B-only stage load (1024 x 16B, 4/thread), weight rows 256, stride STR
#define BLOADW(s, WH, WL, STR)                                                   \
    {                                                                            \
        uint32_t base = sbase + ABUF_B + ((s) % 3) * 16384;                      \
        int k0 = (s) << 4;                                                       \
        _Pragma("unroll")                                                        \
        for (int q = 0; q < 4; q++) {                                            \
            int i = q * 256 + tid;                                               \
            int pb = i >> 9, r = (i & 511) >> 1, cc = i & 1;                     \
            const __half* src = (pb ? (WL) : (WH)) + (size_t)r * (STR) + k0 + cc * 8; \
            uint32_t dst = base + pb * 8192 + r * 32 +                           \
                           (((cc ^ (r >> 2)) & 1) << 4);                         \
            cpasync16(dst, src);                                                 \
        }                                                                        \
        asm volatile("cp.async.commit_group;");                                  \
    }

// ============================================================================
// Fused SA stack with IN-KERNEL GATHER:
//   phase1 gathers (ball, xyz, features) -> swizzled fp16-split A stages,
//   x W1 -> bn/relu -> Abuf; x W2 -> bn/relu -> Abuf; x W3 -> bn/relu ->
//   maxpool16 -> Y planes.  One CTA = 128 points.
// ============================================================================
__global__ void __launch_bounds__(256, 1)
sa_fused_kernel(const float* __restrict__ xyz, const float* __restrict__ features,
                const int* __restrict__ ball, const float* __restrict__ newxyz,
                const __half* __restrict__ W1h, const __half* __restrict__ W1l,
                const __half* __restrict__ W2h, const __half* __restrict__ W2l,
                const __half* __restrict__ W3h, const __half* __restrict__ W3l,
                __half* __restrict__ Yh, __half* __restrict__ Yl,
                const float* __restrict__ gamma, const float* __restrict__ beta,
                const float* __restrict__ mean, const float* __restrict__ var) {
    extern __shared__ __align__(16) uint8_t smem_dyn[];
    const uint32_t sbase = s2u(smem_dyn);
    const int tid = threadIdx.x, lane = tid & 31, warp = tid >> 5;
    const int wm = warp & 1, wn = warp >> 1;
    const int m0 = blockIdx.x * 128;
    const int b = m0 >> 12;
    const float* xyz_b = xyz + (size_t)b * KPTS * 3;
    const float* feat_b = features + (size_t)b * CFEAT * KPTS;

    int* sball = (int*)(smem_dyn + OFF_BALLS);
    float* scen = (float*)(smem_dyn + OFF_CENS);
    if (tid < 128) sball[tid] = ball[m0 + tid];
    if (tid < 24)  scen[tid] = newxyz[(size_t)(m0 >> 4) * 3 + tid];
    __syncthreads();

    float acc[4][8][4];
#pragma unroll
    for (int i = 0; i < 4; i++)
#pragma unroll
        for (int j = 0; j < 8; j++)
#pragma unroll
            for (int q = 0; q < 4; q++) acc[i][j][q] = 0.f;

    float2 vals[4];
    auto prefetch = [&](int s) {
#pragma unroll
        for (int u = 0; u < 4; u++) {
            int uidx = u * 256 + tid;
            int chlp = uidx >> 7;        // 0..7 channel pair
            int pt = uidx & 127;
            int ch0 = (s << 4) + chlp * 2;
            int j = sball[pt];
            float v0 = 0.f, v1 = 0.f;
            if (ch0 < 3)        v0 = (xyz_b[j * 3 + ch0] - scen[(pt >> 4) * 3 + ch0]) / 0.3f;
            else if (ch0 < 259) v0 = feat_b[(size_t)(ch0 - 3) * KPTS + j];
            int ch1 = ch0 + 1;
            if (ch1 < 3)        v1 = (xyz_b[j * 3 + ch1] - scen[(pt >> 4) * 3 + ch1]) / 0.3f;
            else if (ch1 < 259) v1 = feat_b[(size_t)(ch1 - 3) * KPTS + j];
            vals[u] = make_float2(v0, v1);
        }
    };
    auto store_vals = [&](int s) {
        uint8_t* astg = smem_dyn + OFF_ASTG + (s & 1) * 8192;
#pragma unroll
        for (int u = 0; u < 4; u++) {
            int uidx = u * 256 + tid;
            int chlp = uidx >> 7;
            int pt = uidx & 127;
            int cc = (chlp >> 2) & 1;
            uint32_t ad = pt * 32 + (((cc ^ (pt >> 2)) & 1) << 4) + (chlp & 3) * 4;
            __half h0, l0, h1, l1;
            hsplit(vals[u].x, h0, l0);
            hsplit(vals[u].y, h1, l1);
            *(__half2*)(astg + ad)        = __halves2half2(h0, h1);
            *(__half2*)(astg + 4096 + ad) = __halves2half2(l0, l1);
        }
    };

    // ---------------- phase 1: gathered X0 (K=288) x W1 ----------------
    prefetch(0);
    BLOADW(0, W1h, W1l, 288);
    BLOADW(1, W1h, W1l, 288);
    for (int s = 0; s < 18; s++) {
        if (s + 1 < 18) asm volatile("cp.async.wait_group 1;");
        else            asm volatile("cp.async.wait_group 0;");
        __syncthreads();                    // Astg[s&1] free, B(s) visible-ready
        store_vals(s);
        if (s + 1 < 18) prefetch(s + 1);
        if (s + 2 < 18) BLOADW(s + 2, W1h, W1l, 288);
        __syncthreads();                    // A stores visible
        uint32_t astg = sbase + OFF_ASTG + (s & 1) * 8192;
        uint32_t bb = sbase + ABUF_B + (s % 3) * 16384;
        compute_stage(acc, astg, astg + 4096, bb, bb + 8192, wm, wn, lane);
    }
    BLOADW(0, W2h, W2l, 256);
    BLOADW(1, W2h, W2l, 256);
    epi_to_abuf(acc, smem_dyn, wm, wn, lane, gamma, beta, mean, var);
#pragma unroll
    for (int i = 0; i < 4; i++)
#pragma unroll
        for (int j = 0; j < 8; j++)
#pragma unroll
            for (int q = 0; q < 4; q++) acc[i][j][q] = 0.f;

    // ---------------- phase 2: Abuf x W2 ----------------
    for (int s = 0; s < 16; s++) {
        if (s + 1 < 16) asm volatile("cp.async.wait_group 1;");
        else            asm volatile("cp.async.wait_group 0;");
        __syncthreads();
        if (s + 2 < 16) BLOADW(s + 2, W2h, W2l, 256);
        uint32_t ab = sbase + s * 8192;
        uint32_t bb = sbase + ABUF_B + (s % 3) * 16384;
        compute_stage(acc, ab, ab + 4096, bb, bb + 8192, wm, wn, lane);
    }
    __syncthreads();
    BLOADW(0, W3h, W3l, 256);
    BLOADW(1, W3h, W3l, 256);
    epi_to_abuf(acc, smem_dyn, wm, wn, lane, gamma + 256, beta + 256, mean + 256, var + 256);
#pragma unroll
    for (int i = 0; i < 4; i++)
#pragma unroll
        for (int j = 0; j < 8; j++)
#pragma unroll
            for (int q = 0; q < 4; q++) acc[i][j][q] = 0.f;

    // ---------------- phase 3: Abuf x W3 ----------------
    for (int s = 0; s < 16; s++) {
        if (s + 1 < 16) asm volatile("cp.async.wait_group 1;");
        else            asm volatile("cp.async.wait_group 0;");
        __syncthreads();
        if (s + 2 < 16) BLOADW(s + 2, W3h, W3l, 256);
        uint32_t ab = sbase + s * 8192;
        uint32_t bb = sbase + ABUF_B + (s % 3) * 16384;
        compute_stage(acc, ab, ab + 4096, bb, bb + 8192, wm, wn, lane);
    }

    // ---------------- epilogue 3: BN+ReLU + 16-row maxpool -> Y ----------------
    {
        const int colq = (lane & 3) * 2;
        const int rhalf = lane >> 2;
        const float* g3 = gamma + 512;
        const float* b3 = beta + 512;
        const float* mn3 = mean + 512;
        const float* vr3 = var + 512;
#pragma unroll
        for (int j = 0; j < 8; j++) {
            int ch = wn * 64 + j * 8 + colq;
            float s0 = __ldg(g3 + ch) * rsqrtf(__ldg(vr3 + ch) + 1e-5f);
            float sh0 = __ldg(b3 + ch) - __ldg(mn3 + ch) * s0;
            float s1 = __ldg(g3 + ch + 1) * rsqrtf(__ldg(vr3 + ch + 1) + 1e-5f);
            float sh1 = __ldg(b3 + ch + 1) - __ldg(mn3 + ch + 1) * s1;
#pragma unroll
            for (int i = 0; i < 4; i++) {
                float m0v = fmaxf(fmaxf(acc[i][j][0], acc[i][j][2]) * s0 + sh0, 0.f);
                float m1v = fmaxf(fmaxf(acc[i][j][1], acc[i][j][3]) * s1 + sh1, 0.f);
#pragma unroll
                for (int off = 4; off <= 16; off <<= 1) {
                    m0v = fmaxf(m0v, __shfl_xor_sync(0xffffffffu, m0v, off));
                    m1v = fmaxf(m1v, __shfl_xor_sync(0xffffffffu, m1v, off));
                }
                if (rhalf == 0) {
                    int p = (m0 + wm * 64 + i * 16) >> 4;
                    __half h0, l0, h1, l1;
                    hsplit(m0v, h0, l0);
                    hsplit(m1v, h1, l1);
                    *(__half2*)(Yh + (size_t)p * 256 + ch) = __halves2half2(h0, h1);
                    *(__half2*)(Yl + (size_t)p * 256 + ch) = __halves2half2(l0, l1);
                }
            }
        }
    }
}

// ============================================================================
// Fused proposal head: Y x P1 -> bn/relu -> x P2 -> bn/relu -> x P3 + bias -> net
// One CTA = 128 proposals (grid 64).
// ============================================================================
__global__ void __launch_bounds__(256, 1)
head_fused_kernel(const __half* __restrict__ Yh, const __half* __restrict__ Yl,
                  const __half* __restrict__ P1h, const __half* __restrict__ P1l,
                  const __half* __restrict__ P2h, const __half* __restrict__ P2l,
                  const __half* __restrict__ P3h, const __half* __restrict__ P3l,
                  float* __restrict__ net,
                  const float* __restrict__ gamma, const float* __restrict__ beta,
                  const float* __restrict__ mean, const float* __restrict__ var,
                  const float* __restrict__ bias) {
    extern __shared__ __align__(16) uint8_t smem_dyn[];
    const uint32_t sbase = s2u(smem_dyn);
    const int tid = threadIdx.x, lane = tid & 31, warp = tid >> 5;
    const int wm = warp & 1, wn = warp >> 1;
    const int m0 = blockIdx.x * 128;

    float acc[4][8][4];
#pragma unroll
    for (int i = 0; i < 4; i++)
#pragma unroll
        for (int j = 0; j < 8; j++)
#pragma unroll
            for (int q = 0; q < 4; q++) acc[i][j][q] = 0.f;

    // phase-1 A(Y)+B(P1) stage load (1536 x 16B, 6/thread), K = 256
#define HLOAD(s)                                                                 \
    {                                                                            \
        uint32_t base = sbase + ABUF_B + ((s) % 3) * HSTG_B;                     \
        int k0 = (s) << 4;                                                       \
        _Pragma("unroll")                                                        \
        for (int q = 0; q < 6; q++) {                                            \
            int i = q * 256 + tid;                                               \
            const __half* src;                                                   \
            uint32_t dst;                                                        \
            if (i < 512) {                                                       \
                int pa = i >> 8, r = (i & 255) >> 1, cc = i & 1;                 \
                src = (pa ? Yl : Yh) + (size_t)(m0 + r) * 256 + k0 + cc * 8;     \
                dst = base + pa * 4096 + r * 32 + (((cc ^ (r >> 2)) & 1) << 4);  \
            } else {                                                             \
                int ib = i - 512;                                                \
                int pb = ib >> 9, r = (ib & 511) >> 1, cc = ib & 1;              \
                src = (pb ? P1l : P1h) + (size_t)r * 256 + k0 + cc * 8;          \
                dst = base + 8192 + pb * 8192 + r * 32 +                         \
                      (((cc ^ (r >> 2)) & 1) << 4);                              \
            }                                                                    \
            cpasync16(dst, src);                                                 \
        }                                                                        \
        asm volatile("cp.async.commit_group;");                                  \
    }

    HLOAD(0);
    HLOAD(1);
    for (int s = 0; s < 16; s++) {
        if (s + 1 < 16) asm volatile("cp.async.wait_group 1;");
        else            asm volatile("cp.async.wait_group 0;");
        __syncthreads();
        if (s + 2 < 16) HLOAD(s + 2);
        uint32_t st = sbase + ABUF_B + (s % 3) * HSTG_B;
        compute_stage(acc, st, st + 4096, st + 8192, st + 16384, wm, wn, lane);
    }
    BLOADW(0, P2h, P2l, 256);
    BLOADW(1, P2h, P2l, 256);
    epi_to_abuf(acc, smem_dyn, wm, wn, lane, gamma, beta, mean, var);
#pragma unroll
    for (int i = 0; i < 4; i++)
#pragma unroll
        for (int j = 0; j < 8; j++)
#pragma unroll
            for (int q = 0; q < 4; q++) acc[i][j][q] = 0.f;

    for (int s = 0; s < 16; s++) {
        if (s + 1 < 16) asm volatile("cp.async.wait_group 1;");
        else            asm volatile("cp.async.wait_group 0;");
        __syncthreads();
        if (s + 2 < 16) BLOADW(s + 2, P2h, P2l, 256);
        uint32_t ab = sbase + s * 8192;
        uint32_t bb = sbase + ABUF_B + (s % 3) * 16384;
        compute_stage(acc, ab, ab + 4096, bb, bb + 8192, wm, wn, lane);
    }
    __syncthreads();
    BLOADW(0, P3h, P3l, 256);
    BLOADW(1, P3h, P3l, 256);
    epi_to_abuf(acc, smem_dyn, wm, wn, lane, gamma + 256, beta + 256, mean + 256, var + 256);
#pragma unroll
    for (int i = 0; i < 4; i++)
#pragma unroll
        for (int j = 0; j < 8; j++)
#pragma unroll
            for (int q = 0; q < 4; q++) acc[i][j][q] = 0.f;

    for (int s = 0; s < 16; s++) {
        if (s + 1 < 16) asm volatile("cp.async.wait_group 1;");
        else            asm volatile("cp.async.wait_group 0;");
        __syncthreads();
        if (s + 2 < 16) BLOADW(s + 2, P3h, P3l, 256);
        uint32_t ab = sbase + s * 8192;
        uint32_t bb = sbase + ABUF_B + (s % 3) * 16384;
        compute_stage(acc, ab, ab + 4096, bb, bb + 8192, wm, wn, lane);
    }

    // epilogue: + bias (ch < OUTD), store fp32 net cols < 128
    {
        const int colq = (lane & 3) * 2;
        const int rhalf = lane >> 2;
#pragma unroll
        for (int j = 0; j < 8; j++) {
            int ch = wn * 64 + j * 8 + colq;
            if (ch >= 128) continue;
            float sh0 = (ch < OUTD) ? __ldg(bias + ch) : 0.f;
            float sh1 = (ch + 1 < OUTD) ? __ldg(bias + ch + 1) : 0.f;
#pragma unroll
            for (int i = 0; i < 4; i++) {
#pragma unroll
                for (int hh = 0; hh < 2; hh++) {
                    int r = m0 + wm * 64 + i * 16 + rhalf + hh * 8;
                    net[(size_t)r * 128 + ch]     = acc[i][j][hh * 2 + 0] + sh0;
                    net[(size_t)r * 128 + ch + 1] = acc[i][j][hh * 2 + 1] + sh1;
                }
            }
        }
    }
#undef HLOAD
}

// ============================================================================
// Finalize (net layout [p][128])
// ============================================================================
__global__ void finalize_kernel(const float* __restrict__ net,
                                const float* __restrict__ newxyz,
                                const float* __restrict__ msz,
                                float* __restrict__ out) {
    int n = blockIdx.x * blockDim.x + threadIdx.x;
    if (n >= NP2) return;
#define NET(o) net[(size_t)n * 128 + (o)]

    float obj0 = NET(0), obj1 = NET(1);
    out[OFF_OBJ + n * 2 + 0] = obj0;
    out[OFF_OBJ + n * 2 + 1] = obj1;

    float cx = newxyz[n * 3 + 0] + NET(2);
    float cy = newxyz[n * 3 + 1] + NET(3);
    float cz = newxyz[n * 3 + 2] + NET(4);
    out[OFF_CEN + n * 3 + 0] = cx;
    out[OFF_CEN + n * 3 + 1] = cy;
    out[OFF_CEN + n * 3 + 2] = cz;

    int best = 0;
    float bv = NET(29);
    out[OFF_SS + n * 18 + 0] = bv;
#pragma unroll
    for (int sc = 1; sc < 18; sc++) {
        float v = NET(29 + sc);
        out[OFF_SS + n * 18 + sc] = v;
        if (v > bv) { bv = v; best = sc; }
    }

#pragma unroll
    for (int sc = 0; sc < 18; sc++) {
#pragma unroll
        for (int d = 0; d < 3; d++) {
            float sres = NET(47 + sc * 3 + d) * msz[sc * 3 + d];
            out[OFF_SRES + ((size_t)n * 18 + sc) * 3 + d] = sres;
        }
    }

    float ps[3];
#pragma unroll
    for (int d = 0; d < 3; d++) {
        float m = msz[best * 3 + d];
        ps[d] = NET(47 + best * 3 + d) * m + m;
        out[OFF_PSZ + n * 3 + d] = ps[d];
    }

    float sem[18];
#pragma unroll
    for (int s = 0; s < 18; s++) {
        sem[s] = NET(101 + s);
        out[OFF_SEM + n * 18 + s] = sem[s];
    }

    const float sxA[8] = {1, 1, -1, -1, 1, 1, -1, -1};
    const float syA[8] = {1, 1, 1, 1, -1, -1, -1, -1};
    const float szA[8] = {1, -1, -1, 1, 1, -1, -1, 1};
    float c0 = cx, c1 = cz, c2 = -cy;
#pragma unroll
    for (int k = 0; k < 8; k++) {
        out[OFF_CORN + ((size_t)n * 8 + k) * 3 + 0] = ps[0] * sxA[k] * 0.5f + c0;
        out[OFF_CORN + ((size_t)n * 8 + k) * 3 + 1] = ps[2] * syA[k] * 0.5f + c1;
        out[OFF_CORN + ((size_t)n * 8 + k) * 3 + 2] = ps[1] * szA[k] * 0.5f + c2;
    }

#pragma unroll
    for (int s = 0; s < 18; s++) out[OFF_SLOG + n * 19 + s] = sem[s];
    out[OFF_SLOG + n * 19 + 18] = (obj0 <= obj1) ? 0.0f : 1e10f;

    {
        float m = fmaxf(obj0, obj1);
        float e0 = expf(obj0 - m), e1 = expf(obj1 - m);
        out[OFF_OPROB + n] = e1 / (e0 + e1);
    }
    {
        float m = sem[0];
#pragma unroll
        for (int s = 1; s < 18; s++) m = fmaxf(m, sem[s]);
        float sum = 0.f;
        float e[18];
#pragma unroll
        for (int s = 0; s < 18; s++) { e[s] = expf(sem[s] - m); sum += e[s]; }
        float inv = 1.0f / sum;
#pragma unroll
        for (int s = 0; s < 18; s++) out[OFF_SPROB + n * 18 + s] = e[s] * inv;
    }
#undef NET
}

// ============================================================================
// launch
// ============================================================================
extern "C" void kernel_launch(void* const* d_in, const int* in_sizes, int n_in,
                              void* d_out, int out_size) {
    const float* xyz      = (const float*)d_in[0];
    const float* features = (const float*)d_in[1];
    const float* sa_w1    = (const float*)d_in[2];
    const float* sa_w2    = (const float*)d_in[3];
    const float* sa_w3    = (const float*)d_in[4];
    const float* sa_gamma = (const float*)d_in[5];
    const float* sa_beta  = (const float*)d_in[6];
    const float* sa_mean  = (const float*)d_in[7];
    const float* sa_var   = (const float*)d_in[8];
    const float* p_w1     = (const float*)d_in[9];
    const float* p_w2     = (const float*)d_in[10];
    const float* p_w3     = (const float*)d_in[11];
    const float* p_b3     = (const float*)d_in[12];
    const float* p_gamma  = (const float*)d_in[13];
    const float* p_beta   = (const float*)d_in[14];
    const float* p_mean   = (const float*)d_in[15];
    const float* p_var    = (const float*)d_in[16];
    const float* msz      = (const float*)d_in[17];
    float* out = (float*)d_out;

    float *net, *newxyz;
    int* ball;
    __half *Yh, *Yl;
    __half *W1h, *W1l, *W2h, *W2l, *W3h, *W3l, *P1h, *P1l, *P2h, *P2l, *P3h, *P3l;
    cudaGetSymbolAddress((void**)&net, g_net);
    cudaGetSymbolAddress((void**)&newxyz, g_newxyz);
    cudaGetSymbolAddress((void**)&ball, g_ball);
    cudaGetSymbolAddress((void**)&Yh,  g_Yh);  cudaGetSymbolAddress((void**)&Yl,  g_Yl);
    cudaGetSymbolAddress((void**)&W1h, g_W1h); cudaGetSymbolAddress((void**)&W1l, g_W1l);
    cudaGetSymbolAddress((void**)&W2h, g_W2h); cudaGetSymbolAddress((void**)&W2l, g_W2l);
    cudaGetSymbolAddress((void**)&W3h, g_W3h); cudaGetSymbolAddress((void**)&W3l, g_W3l);
    cudaGetSymbolAddress((void**)&P1h, g_P1h); cudaGetSymbolAddress((void**)&P1l, g_P1l);
    cudaGetSymbolAddress((void**)&P2h, g_P2h); cudaGetSymbolAddress((void**)&P2l, g_P2l);
    cudaGetSymbolAddress((void**)&P3h, g_P3h); cudaGetSymbolAddress((void**)&P3l, g_P3l);

    cudaFuncSetAttribute(sa_fused_kernel, cudaFuncAttributeMaxDynamicSharedMemorySize, SA_DYN);
    cudaFuncSetAttribute(head_fused_kernel, cudaFuncAttributeMaxDynamicSharedMemorySize, HEAD_DYN);

    split_all_kernel<<<1568, 256>>>(sa_w1, sa_w2, sa_w3, p_w1, p_w2, p_w3);
    fps_kernel<<<BATCH, 256>>>(xyz, newxyz);
    ball_query_kernel<<<NP2 * 32 / 256, 256>>>(xyz, newxyz, ball);

    sa_fused_kernel<<<NTOT / 128, 256, SA_DYN>>>(xyz, features, ball, newxyz,
                                                 W1h, W1l, W2h, W2l, W3h, W3l,
                                                 Yh, Yl, sa_gamma, sa_beta, sa_mean, sa_var);

    head_fused_kernel<<<NP2 / 128, 256, HEAD_DYN>>>(Yh, Yl, P1h, P1l, P2h, P2l, P3h, P3l,
                                                    net, p_gamma, p_beta, p_mean, p_var, p_b3);

    finalize_kernel<<<NP2 / 256, 256>>>(net, newxyz, msz, out);
}

// round 17
// speedup vs baseline: 2.6717x; 1.0726x over previous
#include <cuda_runtime.h>
#include <cuda_fp16.h>
#include <cstdint>

#define BATCH 32
#define KPTS 2048
#define CFEAT 256
#define NPROP 256
#define NSAMP 16
#define NTOT (BATCH * NPROP * NSAMP)   // 131072
#define NP2  (BATCH * NPROP)           // 8192
#define OUTD 119

// ---------------- scratch (static device memory) ----------------------------
__device__ __align__(128) __half g_Yh [NP2 * 256];
__device__ __align__(128) __half g_Yl [NP2 * 256];
__device__ float  g_net[NP2 * 128];
__device__ __align__(128) __half g_W1h[256 * 288];
__device__ __align__(128) __half g_W1l[256 * 288];
__device__ __align__(128) __half g_W2h[256 * 256];
__device__ __align__(128) __half g_W2l[256 * 256];
__device__ __align__(128) __half g_W3h[256 * 256];
__device__ __align__(128) __half g_W3l[256 * 256];
__device__ __align__(128) __half g_P1h[256 * 256];
__device__ __align__(128) __half g_P1l[256 * 256];
__device__ __align__(128) __half g_P2h[256 * 256];
__device__ __align__(128) __half g_P2l[256 * 256];
__device__ __align__(128) __half g_P3h[256 * 256];   // rows >= OUTD zero
__device__ __align__(128) __half g_P3l[256 * 256];
__device__ float  g_newxyz[NP2 * 3];
__device__ int    g_ball[NP2 * NSAMP];

// ---------------- output offsets (floats) -----------------------------------
#define OFF_OBJ   0
#define OFF_CEN   16384
#define OFF_SS    40960
#define OFF_SRES  188416
#define OFF_PSZ   630784
#define OFF_SEM   655360
#define OFF_CORN  802816
#define OFF_SLOG  999424
#define OFF_OPROB 1155072
#define OFF_SPROB 1163264

// ---------------- helpers ----------------------------------------------------
__device__ __forceinline__ uint32_t s2u(const void* p) {
    uint32_t a;
    asm("{ .reg .u64 t; cvta.to.shared.u64 t, %1; cvt.u32.u64 %0, t; }" : "=r"(a) : "l"(p));
    return a;
}
__device__ __forceinline__ void ldsm4(uint32_t* r, uint32_t a) {
    asm volatile("ldmatrix.sync.aligned.m8n8.x4.shared.b16 {%0,%1,%2,%3}, [%4];"
                 : "=r"(r[0]), "=r"(r[1]), "=r"(r[2]), "=r"(r[3]) : "r"(a));
}
__device__ __forceinline__ void mma16816(float* c, const uint32_t* a, const uint32_t* b) {
    asm volatile(
        "mma.sync.aligned.m16n8k16.row.col.f32.f16.f16.f32 "
        "{%0,%1,%2,%3}, {%4,%5,%6,%7}, {%8,%9}, {%0,%1,%2,%3};"
        : "+f"(c[0]), "+f"(c[1]), "+f"(c[2]), "+f"(c[3])
        : "r"(a[0]), "r"(a[1]), "r"(a[2]), "r"(a[3]), "r"(b[0]), "r"(b[1]));
}
__device__ __forceinline__ void cpasync16(uint32_t sa, const void* g) {
    asm volatile("cp.async.cg.shared.global [%0], [%1], 16;" :: "r"(sa), "l"(g));
}
__device__ __forceinline__ void hsplit(float v, __half& h, __half& l) {
    h = __float2half_rn(v);
    l = __float2half_rn(v - __half2float(h));
}

// ============================================================================
// split + pad all six weight matrices in one kernel
// ============================================================================
__global__ void split_all_kernel(const float* __restrict__ sa_w1,
                                 const float* __restrict__ sa_w2,
                                 const float* __restrict__ sa_w3,
                                 const float* __restrict__ p_w1,
                                 const float* __restrict__ p_w2,
                                 const float* __restrict__ p_w3) {
    int idx = blockIdx.x * 256 + threadIdx.x;
    float v;
    __half* Wh;
    __half* Wl;
    int off;
    if (idx < 73728) {                       // W1: 256 x 288 (259 valid cols)
        int r = idx / 288, c = idx % 288;
        v = (c < 259) ? sa_w1[r * 259 + c] : 0.f;
        Wh = g_W1h; Wl = g_W1l; off = idx;
    } else {
        int idx2 = idx - 73728;
        int seg = idx2 >> 16;                // 0..4
        int w = idx2 & 65535;
        int r = w >> 8;
        off = w;
        if (seg == 0)      { v = sa_w2[w]; Wh = g_W2h; Wl = g_W2l; }
        else if (seg == 1) { v = sa_w3[w]; Wh = g_W3h; Wl = g_W3l; }
        else if (seg == 2) { v = p_w1[w];  Wh = g_P1h; Wl = g_P1l; }
        else if (seg == 3) { v = p_w2[w];  Wh = g_P2h; Wl = g_P2l; }
        else               { v = (r < OUTD) ? p_w3[w] : 0.f; Wh = g_P3h; Wl = g_P3l; }
    }
    __half h, l;
    hsplit(v, h, l);
    Wh[off] = h;
    Wl[off] = l;
}

// ============================================================================
// FPS
// ============================================================================
__global__ void fps_kernel(const float* __restrict__ xyz, float* __restrict__ newxyz) {
    int b = blockIdx.x;
    int t = threadIdx.x;
    __shared__ float sx[KPTS], sy[KPTS], sz[KPTS];
    __shared__ float wv[8];
    __shared__ int   wi[8];
    __shared__ int   far_s;

    const float* p = xyz + (size_t)b * KPTS * 3;
    float px[8], py[8], pz[8], dist[8];
#pragma unroll
    for (int i = 0; i < 8; i++) {
        int j = i * 256 + t;
        px[i] = p[j * 3 + 0];
        py[i] = p[j * 3 + 1];
        pz[i] = p[j * 3 + 2];
        sx[j] = px[i]; sy[j] = py[i]; sz[j] = pz[i];
        dist[i] = 1e10f;
    }
    if (t == 0) far_s = 0;
    __syncthreads();

    for (int it = 0; it < NPROP; it++) {
        int far = far_s;
        if (t == 0) {
            float* o = newxyz + (size_t)(b * NPROP + it) * 3;
            o[0] = sx[far]; o[1] = sy[far]; o[2] = sz[far];
        }
        float cx = sx[far], cy = sy[far], cz = sz[far];
        float bv = -1.0f;
        int   bj = 0x7fffffff;
#pragma unroll
        for (int i = 0; i < 8; i++) {
            float dx = px[i] - cx, dy = py[i] - cy, dz = pz[i] - cz;
            float d = dx * dx + dy * dy + dz * dz;
            dist[i] = fminf(dist[i], d);
            int j = i * 256 + t;
            if (dist[i] > bv || (dist[i] == bv && j < bj)) { bv = dist[i]; bj = j; }
        }
#pragma unroll
        for (int off = 16; off; off >>= 1) {
            float ov = __shfl_down_sync(0xffffffffu, bv, off);
            int   oj = __shfl_down_sync(0xffffffffu, bj, off);
            if (ov > bv || (ov == bv && oj < bj)) { bv = ov; bj = oj; }
        }
        if ((t & 31) == 0) { wv[t >> 5] = bv; wi[t >> 5] = bj; }
        __syncthreads();
        if (t == 0) {
            float fv = wv[0]; int fj = wi[0];
#pragma unroll
            for (int w = 1; w < 8; w++) {
                if (wv[w] > fv || (wv[w] == fv && wi[w] < fj)) { fv = wv[w]; fj = wi[w]; }
            }
            far_s = fj;
        }
        __syncthreads();
    }
}

// ============================================================================
// Ball query
// ============================================================================
__global__ void ball_query_kernel(const float* __restrict__ xyz,
                                  const float* __restrict__ newxyz,
                                  int* __restrict__ ball) {
    int gwarp = (blockIdx.x * blockDim.x + threadIdx.x) >> 5;
    if (gwarp >= NP2) return;
    int lane = threadIdx.x & 31;
    int wl = threadIdx.x >> 5;
    int b = gwarp >> 8;

    __shared__ int slots[8][16];
    if (lane == 0) slots[wl][0] = 0;

    float cx = newxyz[gwarp * 3 + 0];
    float cy = newxyz[gwarp * 3 + 1];
    float cz = newxyz[gwarp * 3 + 2];
    const float* p = xyz + (size_t)b * KPTS * 3;

    int cnt = 0;
    for (int r = 0; r < KPTS / 32 && cnt < NSAMP; r++) {
        int j = r * 32 + lane;
        float dx = cx - p[j * 3 + 0];
        float dy = cy - p[j * 3 + 1];
        float dz = cz - p[j * 3 + 2];
        float d2 = dx * dx + dy * dy + dz * dz;
        bool pred = d2 < 0.09f;
        unsigned m = __ballot_sync(0xffffffffu, pred);
        int pos = cnt + __popc(m & ((1u << lane) - 1u));
        if (pred && pos < NSAMP) slots[wl][pos] = j;
        cnt += __popc(m);
    }
    __syncwarp();
    if (lane < NSAMP) {
        int first = slots[wl][0];
        int v = (lane < cnt) ? slots[wl][lane] : first;
        ball[gwarp * NSAMP + lane] = v;
    }
}

// ============================================================================
// Shared GEMM building blocks — 512 threads, 16 warps of 32x64 each,
// CTA tile 128x256.
// ============================================================================
#define NTHREADS 512
#define ABUF_B    131072                 // 16 k-stages x 8192 (hi 4K | lo 4K)
#define BRING_B   49152                  // 3 x 16384 B-only stages
#define OFF_ASTG  (ABUF_B + BRING_B)     // 180224 : 2 x 8192 gathered-A stages
#define OFF_BALLS (OFF_ASTG + 16384)     // 196608 : 128 ints
#define OFF_CENS  (OFF_BALLS + 512)      // 197120 : 24 floats
#define SA_DYN    197248

#define HSTG_B    24576                  // head phase-1 A+B stage
#define HEAD_DYN  (ABUF_B + 3 * HSTG_B)  // 204800

__device__ __forceinline__ void compute_stage(
    float acc[2][8][4], uint32_t aH, uint32_t aL, uint32_t bH, uint32_t bL,
    int wm, int wn, int lane) {
    const int lrow = lane & 15, lc = lane >> 4;
    const int br = (lane & 7) + ((lane >> 4) & 1) * 8;
    const int bc = (lane >> 3) & 1;
    uint32_t ah[2][4];
#pragma unroll
    for (int i = 0; i < 2; i++) {
        int r = wm * 32 + i * 16 + lrow;
        ldsm4(ah[i], aH + r * 32 + (((lc ^ (r >> 2)) & 1) << 4));
    }
    uint32_t bh[4][4];
#pragma unroll
    for (int jj = 0; jj < 4; jj++) {
        int r = wn * 64 + jj * 16 + br;
        ldsm4(bh[jj], bH + r * 32 + (((bc ^ (r >> 2)) & 1) << 4));
    }
#pragma unroll
    for (int jj = 0; jj < 4; jj++)
#pragma unroll
        for (int j2 = 0; j2 < 2; j2++)
#pragma unroll
            for (int i = 0; i < 2; i++)
                mma16816(acc[i][jj * 2 + j2], ah[i], bh[jj] + j2 * 2);
    {
        uint32_t bl4[4][4];
#pragma unroll
        for (int jj = 0; jj < 4; jj++) {
            int r = wn * 64 + jj * 16 + br;
            ldsm4(bl4[jj], bL + r * 32 + (((bc ^ (r >> 2)) & 1) << 4));
        }
#pragma unroll
        for (int jj = 0; jj < 4; jj++)
#pragma unroll
            for (int j2 = 0; j2 < 2; j2++)
#pragma unroll
                for (int i = 0; i < 2; i++)
                    mma16816(acc[i][jj * 2 + j2], ah[i], bl4[jj] + j2 * 2);
    }
    {
        uint32_t al2[2][4];
#pragma unroll
        for (int i = 0; i < 2; i++) {
            int r = wm * 32 + i * 16 + lrow;
            ldsm4(al2[i], aL + r * 32 + (((lc ^ (r >> 2)) & 1) << 4));
        }
#pragma unroll
        for (int jj = 0; jj < 4; jj++)
#pragma unroll
            for (int j2 = 0; j2 < 2; j2++)
#pragma unroll
                for (int i = 0; i < 2; i++)
                    mma16816(acc[i][jj * 2 + j2], al2[i], bh[jj] + j2 * 2);
    }
}

// BN+ReLU epilogue -> SMEM A-buffer (per-stage swizzled fp16 split layout)
__device__ __forceinline__ void epi_to_abuf(
    float acc[2][8][4], uint8_t* smem, int wm, int wn, int lane,
    const float* __restrict__ gamma, const float* __restrict__ beta,
    const float* __restrict__ mean, const float* __restrict__ var) {
    const int colq = (lane & 3) * 2;
    const int rhalf = lane >> 2;
#pragma unroll
    for (int j = 0; j < 8; j++) {
        int ch = wn * 64 + j * 8 + colq;
        float s0 = __ldg(gamma + ch) * rsqrtf(__ldg(var + ch) + 1e-5f);
        float sh0 = __ldg(beta + ch) - __ldg(mean + ch) * s0;
        float s1 = __ldg(gamma + ch + 1) * rsqrtf(__ldg(var + ch + 1) + 1e-5f);
        float sh1 = __ldg(beta + ch + 1) - __ldg(mean + ch + 1) * s1;
        int ks = ch >> 4;
        int cc = (ch >> 3) & 1;
        int off = (ch & 7) * 2;
#pragma unroll
        for (int i = 0; i < 2; i++) {
#pragma unroll
            for (int hh = 0; hh < 2; hh++) {
                int row = wm * 32 + i * 16 + rhalf + hh * 8;
                float v0 = fmaxf(acc[i][j][hh * 2 + 0] * s0 + sh0, 0.f);
                float v1 = fmaxf(acc[i][j][hh * 2 + 1] * s1 + sh1, 0.f);
                __half h0, l0, h1, l1;
                hsplit(v0, h0, l0);
                hsplit(v1, h1, l1);
                uint32_t ad = ks * 8192 + row * 32 + (((cc ^ (row >> 2)) & 1) << 4) + off;
                *(__half2*)(smem + ad)        = __halves2half2(h0, h1);
                *(__half2*)(smem + ad + 4096) = __halves2half2(l0, l1);
            }
        }
    }
}

#define ZERO_ACC()                                                               \
    _Pragma("unroll")                                                            \
    for (int i = 0; i < 2; i++)                                                  \
        _Pragma("unroll")                                                        \
        for (int j = 0; j < 8; j++)                                              \
            _Pragma("unroll")                                                    \
            for (int q = 0; q < 4; q++) acc[i][j][q] = 0.f;

// B-only stage load (1024 x 16B, 2/thread), weight rows 256, stride STR
#define BLOADW(s, WH, WL, STR)                                                   \
    {                                                                            \
        uint32_t base = sbase + ABUF_B + ((s) % 3) * 16384;                      \
        int k0 = (s) << 4;                                                       \
        _Pragma("unroll")                                                        \
        for (int q = 0; q < 2; q++) {                                            \
            int i = q * NTHREADS + tid;                                          \
            int pb = i >> 9, r = (i & 511) >> 1, cc = i & 1;                     \
            const __half* src = (pb ? (WL) : (WH)) + (size_t)r * (STR) + k0 + cc * 8; \
            uint32_t dst = base + pb * 8192 + r * 32 +                           \
                           (((cc ^ (r >> 2)) & 1) << 4);                         \
            cpasync16(dst, src);                                                 \
        }                                                                        \
        asm volatile("cp.async.commit_group;");                                  \
    }

// ============================================================================
// Fused SA stack with in-kernel gather.  One CTA = 128 points, 512 threads.
// ============================================================================
__global__ void __launch_bounds__(NTHREADS, 1)
sa_fused_kernel(const float* __restrict__ xyz, const float* __restrict__ features,
                const int* __restrict__ ball, const float* __restrict__ newxyz,
                const __half* __restrict__ W1h, const __half* __restrict__ W1l,
                const __half* __restrict__ W2h, const __half* __restrict__ W2l,
                const __half* __restrict__ W3h, const __half* __restrict__ W3l,
                __half* __restrict__ Yh, __half* __restrict__ Yl,
                const float* __restrict__ gamma, const float* __restrict__ beta,
                const float* __restrict__ mean, const float* __restrict__ var) {
    extern __shared__ __align__(16) uint8_t smem_dyn[];
    const uint32_t sbase = s2u(smem_dyn);
    const int tid = threadIdx.x, lane = tid & 31, warp = tid >> 5;
    const int wm = warp & 3, wn = warp >> 2;
    const int m0 = blockIdx.x * 128;
    const int b = m0 >> 12;
    const float* xyz_b = xyz + (size_t)b * KPTS * 3;
    const float* feat_b = features + (size_t)b * CFEAT * KPTS;

    int* sball = (int*)(smem_dyn + OFF_BALLS);
    float* scen = (float*)(smem_dyn + OFF_CENS);
    if (tid < 128) sball[tid] = ball[m0 + tid];
    if (tid < 24)  scen[tid] = newxyz[(size_t)(m0 >> 4) * 3 + tid];
    __syncthreads();

    float acc[2][8][4];
    ZERO_ACC();

    float2 vals[2];
    auto prefetch = [&](int s) {
#pragma unroll
        for (int u = 0; u < 2; u++) {
            int uidx = u * NTHREADS + tid;
            int chlp = uidx >> 7;        // 0..7 channel pair
            int pt = uidx & 127;
            int ch0 = (s << 4) + chlp * 2;
            int j = sball[pt];
            float v0 = 0.f, v1 = 0.f;
            if (ch0 < 3)        v0 = (xyz_b[j * 3 + ch0] - scen[(pt >> 4) * 3 + ch0]) / 0.3f;
            else if (ch0 < 259) v0 = feat_b[(size_t)(ch0 - 3) * KPTS + j];
            int ch1 = ch0 + 1;
            if (ch1 < 3)        v1 = (xyz_b[j * 3 + ch1] - scen[(pt >> 4) * 3 + ch1]) / 0.3f;
            else if (ch1 < 259) v1 = feat_b[(size_t)(ch1 - 3) * KPTS + j];
            vals[u] = make_float2(v0, v1);
        }
    };
    auto store_vals = [&](int s) {
        uint8_t* astg = smem_dyn + OFF_ASTG + (s & 1) * 8192;
#pragma unroll
        for (int u = 0; u < 2; u++) {
            int uidx = u * NTHREADS + tid;
            int chlp = uidx >> 7;
            int pt = uidx & 127;
            int cc = (chlp >> 2) & 1;
            uint32_t ad = pt * 32 + (((cc ^ (pt >> 2)) & 1) << 4) + (chlp & 3) * 4;
            __half h0, l0, h1, l1;
            hsplit(vals[u].x, h0, l0);
            hsplit(vals[u].y, h1, l1);
            *(__half2*)(astg + ad)        = __halves2half2(h0, h1);
            *(__half2*)(astg + 4096 + ad) = __halves2half2(l0, l1);
        }
    };

    // ---------------- phase 1: gathered X0 (K=288) x W1 ----------------
    prefetch(0);
    BLOADW(0, W1h, W1l, 288);
    BLOADW(1, W1h, W1l, 288);
    for (int s = 0; s < 18; s++) {
        if (s + 1 < 18) asm volatile("cp.async.wait_group 1;");
        else            asm volatile("cp.async.wait_group 0;");
        __syncthreads();                    // Astg[s&1] free, B(s) ready
        store_vals(s);
        if (s + 1 < 18) prefetch(s + 1);
        if (s + 2 < 18) BLOADW(s + 2, W1h, W1l, 288);
        __syncthreads();                    // A stores visible
        uint32_t astg = sbase + OFF_ASTG + (s & 1) * 8192;
        uint32_t bb = sbase + ABUF_B + (s % 3) * 16384;
        compute_stage(acc, astg, astg + 4096, bb, bb + 8192, wm, wn, lane);
    }
    __syncthreads();                        // ring safe before W2 prefetch
    BLOADW(0, W2h, W2l, 256);
    BLOADW(1, W2h, W2l, 256);
    epi_to_abuf(acc, smem_dyn, wm, wn, lane, gamma, beta, mean, var);
    ZERO_ACC();

    // ---------------- phase 2: Abuf x W2 ----------------
    for (int s = 0; s < 16; s++) {
        if (s + 1 < 16) asm volatile("cp.async.wait_group 1;");
        else            asm volatile("cp.async.wait_group 0;");
        __syncthreads();
        if (s + 2 < 16) BLOADW(s + 2, W2h, W2l, 256);
        uint32_t ab = sbase + s * 8192;
        uint32_t bb = sbase + ABUF_B + (s % 3) * 16384;
        compute_stage(acc, ab, ab + 4096, bb, bb + 8192, wm, wn, lane);
    }
    __syncthreads();
    BLOADW(0, W3h, W3l, 256);
    BLOADW(1, W3h, W3l, 256);
    epi_to_abuf(acc, smem_dyn, wm, wn, lane, gamma + 256, beta + 256, mean + 256, var + 256);
    ZERO_ACC();

    // ---------------- phase 3: Abuf x W3 ----------------
    for (int s = 0; s < 16; s++) {
        if (s + 1 < 16) asm volatile("cp.async.wait_group 1;");
        else            asm volatile("cp.async.wait_group 0;");
        __syncthreads();
        if (s + 2 < 16) BLOADW(s + 2, W3h, W3l, 256);
        uint32_t ab = sbase + s * 8192;
        uint32_t bb = sbase + ABUF_B + (s % 3) * 16384;
        compute_stage(acc, ab, ab + 4096, bb, bb + 8192, wm, wn, lane);
    }

    // ---------------- epilogue 3: BN+ReLU + 16-row maxpool -> Y ----------------
    {
        const int colq = (lane & 3) * 2;
        const int rhalf = lane >> 2;
        const float* g3 = gamma + 512;
        const float* b3 = beta + 512;
        const float* mn3 = mean + 512;
        const float* vr3 = var + 512;
#pragma unroll
        for (int j = 0; j < 8; j++) {
            int ch = wn * 64 + j * 8 + colq;
            float s0 = __ldg(g3 + ch) * rsqrtf(__ldg(vr3 + ch) + 1e-5f);
            float sh0 = __ldg(b3 + ch) - __ldg(mn3 + ch) * s0;
            float s1 = __ldg(g3 + ch + 1) * rsqrtf(__ldg(vr3 + ch + 1) + 1e-5f);
            float sh1 = __ldg(b3 + ch + 1) - __ldg(mn3 + ch + 1) * s1;
#pragma unroll
            for (int i = 0; i < 2; i++) {
                float m0v = fmaxf(fmaxf(acc[i][j][0], acc[i][j][2]) * s0 + sh0, 0.f);
                float m1v = fmaxf(fmaxf(acc[i][j][1], acc[i][j][3]) * s1 + sh1, 0.f);
#pragma unroll
                for (int off = 4; off <= 16; off <<= 1) {
                    m0v = fmaxf(m0v, __shfl_xor_sync(0xffffffffu, m0v, off));
                    m1v = fmaxf(m1v, __shfl_xor_sync(0xffffffffu, m1v, off));
                }
                if (rhalf == 0) {
                    int p = (m0 + wm * 32 + i * 16) >> 4;
                    __half h0, l0, h1, l1;
                    hsplit(m0v, h0, l0);
                    hsplit(m1v, h1, l1);
                    *(__half2*)(Yh + (size_t)p * 256 + ch) = __halves2half2(h0, h1);
                    *(__half2*)(Yl + (size_t)p * 256 + ch) = __halves2half2(l0, l1);
                }
            }
        }
    }
}

// ============================================================================
// Fused proposal head: Y x P1 -> bn/relu -> x P2 -> bn/relu -> x P3 + bias -> net
// One CTA = 128 proposals (grid 64), 512 threads.
// ============================================================================
__global__ void __launch_bounds__(NTHREADS, 1)
head_fused_kernel(const __half* __restrict__ Yh, const __half* __restrict__ Yl,
                  const __half* __restrict__ P1h, const __half* __restrict__ P1l,
                  const __half* __restrict__ P2h, const __half* __restrict__ P2l,
                  const __half* __restrict__ P3h, const __half* __restrict__ P3l,
                  float* __restrict__ net,
                  const float* __restrict__ gamma, const float* __restrict__ beta,
                  const float* __restrict__ mean, const float* __restrict__ var,
                  const float* __restrict__ bias) {
    extern __shared__ __align__(16) uint8_t smem_dyn[];
    const uint32_t sbase = s2u(smem_dyn);
    const int tid = threadIdx.x, lane = tid & 31, warp = tid >> 5;
    const int wm = warp & 3, wn = warp >> 2;
    const int m0 = blockIdx.x * 128;

    float acc[2][8][4];
    ZERO_ACC();

    // phase-1 A(Y)+B(P1) stage load (1536 x 16B, 3/thread), K = 256
#define HLOAD(s)                                                                 \
    {                                                                            \
        uint32_t base = sbase + ABUF_B + ((s) % 3) * HSTG_B;                     \
        int k0 = (s) << 4;                                                       \
        _Pragma("unroll")                                                        \
        for (int q = 0; q < 3; q++) {                                            \
            int i = q * NTHREADS + tid;                                          \
            const __half* src;                                                   \
            uint32_t dst;                                                        \
            if (i < 512) {                                                       \
                int pa = i >> 8, r = (i & 255) >> 1, cc = i & 1;                 \
                src = (pa ? Yl : Yh) + (size_t)(m0 + r) * 256 + k0 + cc * 8;     \
                dst = base + pa * 4096 + r * 32 + (((cc ^ (r >> 2)) & 1) << 4);  \
            } else {                                                             \
                int ib = i - 512;                                                \
                int pb = ib >> 9, r = (ib & 511) >> 1, cc = ib & 1;              \
                src = (pb ? P1l : P1h) + (size_t)r * 256 + k0 + cc * 8;          \
                dst = base + 8192 + pb * 8192 + r * 32 +                         \
                      (((cc ^ (r >> 2)) & 1) << 4);                              \
            }                                                                    \
            cpasync16(dst, src);                                                 \
        }                                                                        \
        asm volatile("cp.async.commit_group;");                                  \
    }

    HLOAD(0);
    HLOAD(1);
    for (int s = 0; s < 16; s++) {
        if (s + 1 < 16) asm volatile("cp.async.wait_group 1;");
        else            asm volatile("cp.async.wait_group 0;");
        __syncthreads();
        if (s + 2 < 16) HLOAD(s + 2);
        uint32_t st = sbase + ABUF_B + (s % 3) * HSTG_B;
        compute_stage(acc, st, st + 4096, st + 8192, st + 16384, wm, wn, lane);
    }
    __syncthreads();      // FIX: HSTG ring stage 0 still being read by late warps;
                          // BLOADW(0,P2) below overwrites the same bytes.
    BLOADW(0, P2h, P2l, 256);
    BLOADW(1, P2h, P2l, 256);
    epi_to_abuf(acc, smem_dyn, wm, wn, lane, gamma, beta, mean, var);
    ZERO_ACC();

    for (int s = 0; s < 16; s++) {
        if (s + 1 < 16) asm volatile("cp.async.wait_group 1;");
        else            asm volatile("cp.async.wait_group 0;");
        __syncthreads();
        if (s + 2 < 16) BLOADW(s + 2, P2h, P2l, 256);
        uint32_t ab = sbase + s * 8192;
        uint32_t bb = sbase + ABUF_B + (s % 3) * 16384;
        compute_stage(acc, ab, ab + 4096, bb, bb + 8192, wm, wn, lane);
    }
    __syncthreads();
    BLOADW(0, P3h, P3l, 256);
    BLOADW(1, P3h, P3l, 256);
    epi_to_abuf(acc, smem_dyn, wm, wn, lane, gamma + 256, beta + 256, mean + 256, var + 256);
    ZERO_ACC();

    for (int s = 0; s < 16; s++) {
        if (s + 1 < 16) asm volatile("cp.async.wait_group 1;");
        else            asm volatile("cp.async.wait_group 0;");
        __syncthreads();
        if (s + 2 < 16) BLOADW(s + 2, P3h, P3l, 256);
        uint32_t ab = sbase + s * 8192;
        uint32_t bb = sbase + ABUF_B + (s % 3) * 16384;
        compute_stage(acc, ab, ab + 4096, bb, bb + 8192, wm, wn, lane);
    }

    // epilogue: + bias (ch < OUTD), store fp32 net cols < 128
    {
        const int colq = (lane & 3) * 2;
        const int rhalf = lane >> 2;
#pragma unroll
        for (int j = 0; j < 8; j++) {
            int ch = wn * 64 + j * 8 + colq;
            if (ch >= 128) continue;
            float sh0 = (ch < OUTD) ? __ldg(bias + ch) : 0.f;
            float sh1 = (ch + 1 < OUTD) ? __ldg(bias + ch + 1) : 0.f;
#pragma unroll
            for (int i = 0; i < 2; i++) {
#pragma unroll
                for (int hh = 0; hh < 2; hh++) {
                    int r = m0 + wm * 32 + i * 16 + rhalf + hh * 8;
                    net[(size_t)r * 128 + ch]     = acc[i][j][hh * 2 + 0] + sh0;
                    net[(size_t)r * 128 + ch + 1] = acc[i][j][hh * 2 + 1] + sh1;
                }
            }
        }
    }
#undef HLOAD
}

// ============================================================================
// Finalize (net layout [p][128])
// ============================================================================
__global__ void finalize_kernel(const float* __restrict__ net,
                                const float* __restrict__ newxyz,
                                const float* __restrict__ msz,
                                float* __restrict__ out) {
    int n = blockIdx.x * blockDim.x + threadIdx.x;
    if (n >= NP2) return;
#define NET(o) net[(size_t)n * 128 + (o)]

    float obj0 = NET(0), obj1 = NET(1);
    out[OFF_OBJ + n * 2 + 0] = obj0;
    out[OFF_OBJ + n * 2 + 1] = obj1;

    float cx = newxyz[n * 3 + 0] + NET(2);
    float cy = newxyz[n * 3 + 1] + NET(3);
    float cz = newxyz[n * 3 + 2] + NET(4);
    out[OFF_CEN + n * 3 + 0] = cx;
    out[OFF_CEN + n * 3 + 1] = cy;
    out[OFF_CEN + n * 3 + 2] = cz;

    int best = 0;
    float bv = NET(29);
    out[OFF_SS + n * 18 + 0] = bv;
#pragma unroll
    for (int sc = 1; sc < 18; sc++) {
        float v = NET(29 + sc);
        out[OFF_SS + n * 18 + sc] = v;
        if (v > bv) { bv = v; best = sc; }
    }

#pragma unroll
    for (int sc = 0; sc < 18; sc++) {
#pragma unroll
        for (int d = 0; d < 3; d++) {
            float sres = NET(47 + sc * 3 + d) * msz[sc * 3 + d];
            out[OFF_SRES + ((size_t)n * 18 + sc) * 3 + d] = sres;
        }
    }

    float ps[3];
#pragma unroll
    for (int d = 0; d < 3; d++) {
        float m = msz[best * 3 + d];
        ps[d] = NET(47 + best * 3 + d) * m + m;
        out[OFF_PSZ + n * 3 + d] = ps[d];
    }

    float sem[18];
#pragma unroll
    for (int s = 0; s < 18; s++) {
        sem[s] = NET(101 + s);
        out[OFF_SEM + n * 18 + s] = sem[s];
    }

    const float sxA[8] = {1, 1, -1, -1, 1, 1, -1, -1};
    const float syA[8] = {1, 1, 1, 1, -1, -1, -1, -1};
    const float szA[8] = {1, -1, -1, 1, 1, -1, -1, 1};
    float c0 = cx, c1 = cz, c2 = -cy;
#pragma unroll
    for (int k = 0; k < 8; k++) {
        out[OFF_CORN + ((size_t)n * 8 + k) * 3 + 0] = ps[0] * sxA[k] * 0.5f + c0;
        out[OFF_CORN + ((size_t)n * 8 + k) * 3 + 1] = ps[2] * syA[k] * 0.5f + c1;
        out[OFF_CORN + ((size_t)n * 8 + k) * 3 + 2] = ps[1] * szA[k] * 0.5f + c2;
    }

#pragma unroll
    for (int s = 0; s < 18; s++) out[OFF_SLOG + n * 19 + s] = sem[s];
    out[OFF_SLOG + n * 19 + 18] = (obj0 <= obj1) ? 0.0f : 1e10f;

    {
        float m = fmaxf(obj0, obj1);
        float e0 = expf(obj0 - m), e1 = expf(obj1 - m);
        out[OFF_OPROB + n] = e1 / (e0 + e1);
    }
    {
        float m = sem[0];
#pragma unroll
        for (int s = 1; s < 18; s++) m = fmaxf(m, sem[s]);
        float sum = 0.f;
        float e[18];
#pragma unroll
        for (int s = 0; s < 18; s++) { e[s] = expf(sem[s] - m); sum += e[s]; }
        float inv = 1.0f / sum;
#pragma unroll
        for (int s = 0; s < 18; s++) out[OFF_SPROB + n * 18 + s] = e[s] * inv;
    }
#undef NET
}

// ============================================================================
// launch
// ============================================================================
extern "C" void kernel_launch(void* const* d_in, const int* in_sizes, int n_in,
                              void* d_out, int out_size) {
    const float* xyz      = (const float*)d_in[0];
    const float* features = (const float*)d_in[1];
    const float* sa_w1    = (const float*)d_in[2];
    const float* sa_w2    = (const float*)d_in[3];
    const float* sa_w3    = (const float*)d_in[4];
    const float* sa_gamma = (const float*)d_in[5];
    const float* sa_beta  = (const float*)d_in[6];
    const float* sa_mean  = (const float*)d_in[7];
    const float* sa_var   = (const float*)d_in[8];
    const float* p_w1     = (const float*)d_in[9];
    const float* p_w2     = (const float*)d_in[10];
    const float* p_w3     = (const float*)d_in[11];
    const float* p_b3     = (const float*)d_in[12];
    const float* p_gamma  = (const float*)d_in[13];
    const float* p_beta   = (const float*)d_in[14];
    const float* p_mean   = (const float*)d_in[15];
    const float* p_var    = (const float*)d_in[16];
    const float* msz      = (const float*)d_in[17];
    float* out = (float*)d_out;

    float *net, *newxyz;
    int* ball;
    __half *Yh, *Yl;
    __half *W1h, *W1l, *W2h, *W2l, *W3h, *W3l, *P1h, *P1l, *P2h, *P2l, *P3h, *P3l;
    cudaGetSymbolAddress((void**)&net, g_net);
    cudaGetSymbolAddress((void**)&newxyz, g_newxyz);
    cudaGetSymbolAddress((void**)&ball, g_ball);
    cudaGetSymbolAddress((void**)&Yh,  g_Yh);  cudaGetSymbolAddress((void**)&Yl,  g_Yl);
    cudaGetSymbolAddress((void**)&W1h, g_W1h); cudaGetSymbolAddress((void**)&W1l, g_W1l);
    cudaGetSymbolAddress((void**)&W2h, g_W2h); cudaGetSymbolAddress((void**)&W2l, g_W2l);
    cudaGetSymbolAddress((void**)&W3h, g_W3h); cudaGetSymbolAddress((void**)&W3l, g_W3l);
    cudaGetSymbolAddress((void**)&P1h, g_P1h); cudaGetSymbolAddress((void**)&P1l, g_P1l);
    cudaGetSymbolAddress((void**)&P2h, g_P2h); cudaGetSymbolAddress((void**)&P2l, g_P2l);
    cudaGetSymbolAddress((void**)&P3h, g_P3h); cudaGetSymbolAddress((void**)&P3l, g_P3l);

    cudaFuncSetAttribute(sa_fused_kernel, cudaFuncAttributeMaxDynamicSharedMemorySize, SA_DYN);
    cudaFuncSetAttribute(head_fused_kernel, cudaFuncAttributeMaxDynamicSharedMemorySize, HEAD_DYN);

    split_all_kernel<<<1568, 256>>>(sa_w1, sa_w2, sa_w3, p_w1, p_w2, p_w3);
    fps_kernel<<<BATCH, 256>>>(xyz, newxyz);
    ball_query_kernel<<<NP2 * 32 / 256, 256>>>(xyz, newxyz, ball);

    sa_fused_kernel<<<NTOT / 128, NTHREADS, SA_DYN>>>(xyz, features, ball, newxyz,
                                                      W1h, W1l, W2h, W2l, W3h, W3l,
                                                      Yh, Yl, sa_gamma, sa_beta, sa_mean, sa_var);

    head_fused_kernel<<<NP2 / 128, NTHREADS, HEAD_DYN>>>(Yh, Yl, P1h, P1l, P2h, P2l, P3h, P3l,
                                                         net, p_gamma, p_beta, p_mean, p_var, p_b3);

    finalize_kernel<<<NP2 / 256, 256>>>(net, newxyz, msz, out);
}